// round 4
// baseline (speedup 1.0000x reference)
#include <cuda_runtime.h>
#include <math.h>

#define NN 132
#define MM 264
#define NPIX (NN*NN)      // 17424
#define NIMG 256          // 4*64
#define NCH  64
#define OUTW 256
#define PIF 3.14159265358979323846f

// ---------------- static scratch (allocation-free) ----------------
__device__ float2 g_F[NPIX];            // DFT matrix F[k][n] = exp(-2pi i k n / N)
__device__ float2 g_R[NCH*NPIX];        // per-channel filter (1-V)/(W2+alpha) / N^2
__device__ float  g_xpad[NIMG*NPIX];    // circularly padded input
__device__ float2 g_T1[NIMG*NPIX];      // F * x
__device__ float2 g_X[NIMG*NPIX];       // (F*x)*F^T, then in-place *R
__device__ float2 g_T2[NIMG*NPIX];      // conj(F)^T * Y
__device__ float  g_z[NIMG*NPIX];       // Re(T2 * conj(F))

// ---------------- DFT matrix ----------------
__global__ void k_buildF() {
    int i = blockIdx.x * blockDim.x + threadIdx.x;
    if (i >= NPIX) return;
    int k = i / NN, n = i % NN;
    int t = (k * n) % NN;                   // exact integer reduction
    float ang = (2.0f * PIF / NN) * (float)t;
    float s, c; sincosf(ang, &s, &c);
    g_F[i] = make_float2(c, -s);
}

// ---------------- per-channel frequency filter ----------------
// R(kappa) = (1 - V)/(W2 + alpha) * (1/N^2)
// V = 1/4 sum_r FB(k_r) U(k_r),  W2 = 1/4 sum_r |FB(k_r)|^2, aliases k_r = kappa + r*N
__global__ void k_buildR(const float* __restrict__ w, const float* __restrict__ bias) {
    int k2 = threadIdx.x;     // 0..131
    int k1 = blockIdx.x;      // 0..131
    int c  = blockIdx.y;      // 0..63
    __shared__ float sw[9];
    if (threadIdx.x < 9) sw[threadIdx.x] = w[c * 9 + threadIdx.x];
    __syncthreads();
    float alpha = 1.0f / (1.0f + expf(9.0f - bias[c])) + 1e-5f;

    float Vr = 0.f, Vi = 0.f, W2 = 0.f;
    #pragma unroll
    for (int r1 = 0; r1 < 2; r1++)
    #pragma unroll
    for (int r2 = 0; r2 < 2; r2++) {
        int kk1 = k1 + r1 * NN;
        int kk2 = k2 + r2 * NN;
        // FB(kk1,kk2) = sum_{u,v} w[u][v] exp(-2pi i (kk1*(u-1)+kk2*(v-1))/M)
        float fr = 0.f, fi = 0.f;
        #pragma unroll
        for (int u = 0; u < 3; u++)
        #pragma unroll
        for (int v = 0; v < 3; v++) {
            int t = kk1 * (u - 1) + kk2 * (v - 1);
            t %= MM; if (t < 0) t += MM;
            float ang = (2.0f * PIF / MM) * (float)t;
            float sn, cs; sincosf(ang, &sn, &cs);
            float wv = sw[u * 3 + v];
            fr += wv * cs;
            fi -= wv * sn;
        }
        // U = (1 + e^{-2pi i kk1/M})(1 + e^{-2pi i kk2/M})
        float a1 = (2.0f * PIF / MM) * (float)kk1;
        float a2 = (2.0f * PIF / MM) * (float)kk2;
        float s1, c1, s2, c2;
        sincosf(a1, &s1, &c1);
        sincosf(a2, &s2, &c2);
        float u1r = 1.f + c1, u1i = -s1;
        float u2r = 1.f + c2, u2i = -s2;
        float Ur = u1r * u2r - u1i * u2i;
        float Ui = u1r * u2i + u1i * u2r;
        Vr += fr * Ur - fi * Ui;
        Vi += fr * Ui + fi * Ur;
        W2 += fr * fr + fi * fi;
    }
    Vr *= 0.25f; Vi *= 0.25f; W2 *= 0.25f;
    float sc = 1.0f / (W2 + alpha) * (1.0f / (float)NPIX);
    g_R[(c * NN + k1) * NN + k2] = make_float2((1.f - Vr) * sc, (-Vi) * sc);
}

// ---------------- circular pad (wrap by 2) ----------------
__global__ void k_pad(const float* __restrict__ x) {
    int i = blockIdx.x * blockDim.x + threadIdx.x;
    if (i >= NIMG * NPIX) return;
    int img = i / NPIX;
    int rem = i - img * NPIX;
    int r = rem / NN, cc = rem % NN;
    int sr = (r + 126) & 127;
    int sc = (cc + 126) & 127;
    g_xpad[i] = x[(img * 128 + sr) * 128 + sc];
}

// ---------------- GEMM 1: T1[k][j] = sum_n F[k][n] * xpad[n][j]  (complex x real) ----------------
__global__ void k_g1() {
    __shared__ float2 As[32][33];
    __shared__ float  Bs[32][33];
    int img = blockIdx.z;
    int rowBase = blockIdx.y * 32, colBase = blockIdx.x * 32;
    int tx = threadIdx.x, ty = threadIdx.y, tid = ty * 16 + tx;
    const float* B = g_xpad + img * NPIX;
    float ar[2][2] = {{0,0},{0,0}}, ai[2][2] = {{0,0},{0,0}};
    for (int k0 = 0; k0 < NN; k0 += 32) {
        #pragma unroll
        for (int l = 0; l < 4; l++) {
            int lin = l * 256 + tid, ml = lin >> 5, kk = lin & 31;
            int r = rowBase + ml, cc = k0 + kk;
            As[ml][kk] = (r < NN && cc < NN) ? g_F[r * NN + cc] : make_float2(0.f, 0.f);
        }
        #pragma unroll
        for (int l = 0; l < 4; l++) {
            int lin = l * 256 + tid, kk = lin >> 5, nl = lin & 31;
            int r = k0 + kk, cc = colBase + nl;
            Bs[kk][nl] = (r < NN && cc < NN) ? B[r * NN + cc] : 0.f;
        }
        __syncthreads();
        #pragma unroll
        for (int kk = 0; kk < 32; kk++) {
            float2 a0 = As[ty][kk], a1 = As[ty + 16][kk];
            float b0 = Bs[kk][tx], b1 = Bs[kk][tx + 16];
            ar[0][0] += a0.x * b0; ai[0][0] += a0.y * b0;
            ar[0][1] += a0.x * b1; ai[0][1] += a0.y * b1;
            ar[1][0] += a1.x * b0; ai[1][0] += a1.y * b0;
            ar[1][1] += a1.x * b1; ai[1][1] += a1.y * b1;
        }
        __syncthreads();
    }
    float2* Cm = g_T1 + img * NPIX;
    #pragma unroll
    for (int i = 0; i < 2; i++) {
        int r = rowBase + ty + i * 16; if (r >= NN) continue;
        #pragma unroll
        for (int j = 0; j < 2; j++) {
            int c = colBase + tx + j * 16; if (c >= NN) continue;
            Cm[r * NN + c] = make_float2(ar[i][j], ai[i][j]);
        }
    }
}

// ---------------- GEMM 2: X[k1][k2] = sum_j T1[k1][j] * F[k2][j]  (A * B^T, complex) ----------------
__global__ void k_g2() {
    __shared__ float2 As[32][33];
    __shared__ float2 Bt[32][33];   // Bt[nl][kk] = F[(colBase+nl)][k0+kk]
    int img = blockIdx.z;
    int rowBase = blockIdx.y * 32, colBase = blockIdx.x * 32;
    int tx = threadIdx.x, ty = threadIdx.y, tid = ty * 16 + tx;
    const float2* A = g_T1 + img * NPIX;
    float ar[2][2] = {{0,0},{0,0}}, ai[2][2] = {{0,0},{0,0}};
    for (int k0 = 0; k0 < NN; k0 += 32) {
        #pragma unroll
        for (int l = 0; l < 4; l++) {
            int lin = l * 256 + tid, ml = lin >> 5, kk = lin & 31;
            int r = rowBase + ml, cc = k0 + kk;
            As[ml][kk] = (r < NN && cc < NN) ? A[r * NN + cc] : make_float2(0.f, 0.f);
        }
        #pragma unroll
        for (int l = 0; l < 4; l++) {
            int lin = l * 256 + tid, nl = lin >> 5, kk = lin & 31;
            int r = colBase + nl, cc = k0 + kk;
            Bt[nl][kk] = (r < NN && cc < NN) ? g_F[r * NN + cc] : make_float2(0.f, 0.f);
        }
        __syncthreads();
        #pragma unroll
        for (int kk = 0; kk < 32; kk++) {
            float2 a0 = As[ty][kk], a1 = As[ty + 16][kk];
            float2 b0 = Bt[tx][kk], b1 = Bt[tx + 16][kk];
            ar[0][0] += a0.x * b0.x - a0.y * b0.y; ai[0][0] += a0.x * b0.y + a0.y * b0.x;
            ar[0][1] += a0.x * b1.x - a0.y * b1.y; ai[0][1] += a0.x * b1.y + a0.y * b1.x;
            ar[1][0] += a1.x * b0.x - a1.y * b0.y; ai[1][0] += a1.x * b0.y + a1.y * b0.x;
            ar[1][1] += a1.x * b1.x - a1.y * b1.y; ai[1][1] += a1.x * b1.y + a1.y * b1.x;
        }
        __syncthreads();
    }
    float2* Cm = g_X + img * NPIX;
    #pragma unroll
    for (int i = 0; i < 2; i++) {
        int r = rowBase + ty + i * 16; if (r >= NN) continue;
        #pragma unroll
        for (int j = 0; j < 2; j++) {
            int c = colBase + tx + j * 16; if (c >= NN) continue;
            Cm[r * NN + c] = make_float2(ar[i][j], ai[i][j]);
        }
    }
}

// ---------------- pointwise Y = X .* R(channel), in place ----------------
__global__ void k_mulR() {
    int i = blockIdx.x * blockDim.x + threadIdx.x;
    if (i >= NIMG * NPIX) return;
    int img = i / NPIX;
    int pix = i - img * NPIX;
    int c = img & 63;
    float2 x = g_X[i];
    float2 r = g_R[c * NPIX + pix];
    g_X[i] = make_float2(x.x * r.x - x.y * r.y, x.x * r.y + x.y * r.x);
}

// ---------------- GEMM 3: T2[m][k2] = sum_k1 conj(F[k1][m]) * Y[k1][k2] ----------------
__global__ void k_g3() {
    __shared__ float2 As[32][33];   // As[ml][kk] = conj(F[(k0+kk)][rowBase+ml])
    __shared__ float2 Bs[32][33];
    int img = blockIdx.z;
    int rowBase = blockIdx.y * 32, colBase = blockIdx.x * 32;
    int tx = threadIdx.x, ty = threadIdx.y, tid = ty * 16 + tx;
    const float2* Y = g_X + img * NPIX;
    float ar[2][2] = {{0,0},{0,0}}, ai[2][2] = {{0,0},{0,0}};
    for (int k0 = 0; k0 < NN; k0 += 32) {
        #pragma unroll
        for (int l = 0; l < 4; l++) {
            int lin = l * 256 + tid, kk = lin >> 5, ml = lin & 31;
            int r = k0 + kk, cc = rowBase + ml;
            float2 f = (r < NN && cc < NN) ? g_F[r * NN + cc] : make_float2(0.f, 0.f);
            As[ml][kk] = make_float2(f.x, -f.y);
        }
        #pragma unroll
        for (int l = 0; l < 4; l++) {
            int lin = l * 256 + tid, kk = lin >> 5, nl = lin & 31;
            int r = k0 + kk, cc = colBase + nl;
            Bs[kk][nl] = (r < NN && cc < NN) ? Y[r * NN + cc] : make_float2(0.f, 0.f);
        }
        __syncthreads();
        #pragma unroll
        for (int kk = 0; kk < 32; kk++) {
            float2 a0 = As[ty][kk], a1 = As[ty + 16][kk];
            float2 b0 = Bs[kk][tx], b1 = Bs[kk][tx + 16];
            ar[0][0] += a0.x * b0.x - a0.y * b0.y; ai[0][0] += a0.x * b0.y + a0.y * b0.x;
            ar[0][1] += a0.x * b1.x - a0.y * b1.y; ai[0][1] += a0.x * b1.y + a0.y * b1.x;
            ar[1][0] += a1.x * b0.x - a1.y * b0.y; ai[1][0] += a1.x * b0.y + a1.y * b0.x;
            ar[1][1] += a1.x * b1.x - a1.y * b1.y; ai[1][1] += a1.x * b1.y + a1.y * b1.x;
        }
        __syncthreads();
    }
    float2* Cm = g_T2 + img * NPIX;
    #pragma unroll
    for (int i = 0; i < 2; i++) {
        int r = rowBase + ty + i * 16; if (r >= NN) continue;
        #pragma unroll
        for (int j = 0; j < 2; j++) {
            int c = colBase + tx + j * 16; if (c >= NN) continue;
            Cm[r * NN + c] = make_float2(ar[i][j], ai[i][j]);
        }
    }
}

// ---------------- GEMM 4: z[m1][m2] = Re( sum_k2 T2[m1][k2] * conj(F[k2][m2]) ) ----------------
__global__ void k_g4() {
    __shared__ float2 As[32][33];
    __shared__ float2 Bs[32][33];
    int img = blockIdx.z;
    int rowBase = blockIdx.y * 32, colBase = blockIdx.x * 32;
    int tx = threadIdx.x, ty = threadIdx.y, tid = ty * 16 + tx;
    const float2* A = g_T2 + img * NPIX;
    float acc[2][2] = {{0,0},{0,0}};
    for (int k0 = 0; k0 < NN; k0 += 32) {
        #pragma unroll
        for (int l = 0; l < 4; l++) {
            int lin = l * 256 + tid, ml = lin >> 5, kk = lin & 31;
            int r = rowBase + ml, cc = k0 + kk;
            As[ml][kk] = (r < NN && cc < NN) ? A[r * NN + cc] : make_float2(0.f, 0.f);
        }
        #pragma unroll
        for (int l = 0; l < 4; l++) {
            int lin = l * 256 + tid, kk = lin >> 5, nl = lin & 31;
            int r = k0 + kk, cc = colBase + nl;
            Bs[kk][nl] = (r < NN && cc < NN) ? g_F[r * NN + cc] : make_float2(0.f, 0.f);
        }
        __syncthreads();
        #pragma unroll
        for (int kk = 0; kk < 32; kk++) {
            float2 a0 = As[ty][kk], a1 = As[ty + 16][kk];
            float2 b0 = Bs[kk][tx], b1 = Bs[kk][tx + 16];
            // Re(a * conj(b)) = a.x*b.x + a.y*b.y
            acc[0][0] += a0.x * b0.x + a0.y * b0.y;
            acc[0][1] += a0.x * b1.x + a0.y * b1.y;
            acc[1][0] += a1.x * b0.x + a1.y * b0.y;
            acc[1][1] += a1.x * b1.x + a1.y * b1.y;
        }
        __syncthreads();
    }
    float* Cm = g_z + img * NPIX;
    #pragma unroll
    for (int i = 0; i < 2; i++) {
        int r = rowBase + ty + i * 16; if (r >= NN) continue;
        #pragma unroll
        for (int j = 0; j < 2; j++) {
            int c = colBase + tx + j * 16; if (c >= NN) continue;
            Cm[r * NN + c] = acc[i][j];
        }
    }
}

// ---------------- final: nearest-up + 3x3 polyphase gather + crop + exact GELU ----------------
__global__ void k_final(const float* __restrict__ wt, float* __restrict__ out) {
    int i = blockIdx.x * blockDim.x + threadIdx.x;   // over 4*64*256*256
    int q = i & 255;
    int p = (i >> 8) & 255;
    int img = i >> 16;
    int c = img & 63;
    int n1 = p + 4, n2 = q + 4;          // crop offset = PAD*s = 4
    int m1 = n1 >> 1, m2 = n2 >> 1;      // in [2,130] -> no wraparound needed
    int a1 = n1 & 1, a2 = n2 & 1;
    const float* z = g_z + img * NPIX;
    const float* w = wt + c * 9;
    float z00 = z[m1 * NN + m2];
    float acc;
    if (a1 == 0) {
        if (a2 == 0) acc = w[4] * z00;
        else         acc = w[3] * z00 + w[5] * z[m1 * NN + m2 + 1];
    } else {
        if (a2 == 0) acc = w[1] * z00 + w[7] * z[(m1 + 1) * NN + m2];
        else         acc = w[0] * z00 + w[2] * z[m1 * NN + m2 + 1]
                         + w[6] * z[(m1 + 1) * NN + m2] + w[8] * z[(m1 + 1) * NN + m2 + 1];
    }
    float v = g_xpad[img * NPIX + m1 * NN + m2] + acc;
    out[i] = 0.5f * v * (1.0f + erff(v * 0.70710678118654752f));
}

// ---------------- launch ----------------
extern "C" void kernel_launch(void* const* d_in, const int* in_sizes, int n_in,
                              void* d_out, int out_size) {
    const float* x    = (const float*)d_in[0];   // (4,64,128,128)
    const float* w    = (const float*)d_in[1];   // (1,64,3,3)
    const float* bias = (const float*)d_in[2];   // (1,64,1,1)
    float* out = (float*)d_out;                  // (4,64,256,256)

    k_buildF<<<(NPIX + 255) / 256, 256>>>();
    k_buildR<<<dim3(NN, NCH), NN>>>(w, bias);
    k_pad<<<(NIMG * NPIX + 255) / 256, 256>>>(x);

    dim3 blk(16, 16);
    dim3 grd((NN + 31) / 32, (NN + 31) / 32, NIMG);
    k_g1<<<grd, blk>>>();
    k_g2<<<grd, blk>>>();
    k_mulR<<<(NIMG * NPIX + 255) / 256, 256>>>();
    k_g3<<<grd, blk>>>();
    k_g4<<<grd, blk>>>();

    k_final<<<(4 * 64 * 256 * 256) / 256, 256>>>(w, out);
}

// round 5
// speedup vs baseline: 1.4521x; 1.4521x over previous
#include <cuda_runtime.h>
#include <math.h>

#define NN 132
#define MM 264
#define NPIX (NN*NN)      // 17424
#define NIMG 256          // 4*64
#define NCH  64
#define NH   67           // rows 0..66 (Hermitian half, N even)
#define KG4  134          // 67 complex = 134 floats
#define PIF 3.14159265358979323846f

// ---------------- static scratch (allocation-free) ----------------
__device__ float2 g_F[NPIX];            // F[k][n] = exp(-2pi i k n / N)
__device__ float2 g_E[NPIX];            // E[t][m]: t<=66 -> e^{+2pi i t m/N}; t>66 -> e^{-2pi i (132-t) m/N}
__device__ float  g_G4B[KG4*NN];        // real IDFT-over-k2 matrix with Hermitian doubling
__device__ float2 g_R[NCH*NPIX];        // per-channel filter (1-V)/(W2+alpha) / N^2
__device__ float  g_xpad[NIMG*NPIX];    // circularly padded input
__device__ float2 g_T1[NIMG*NPIX];      // F * x  (rows 0..66 valid)
__device__ float2 g_X[NIMG*NPIX];       // stacked Ys: rows 0..66 = Y, rows 67..131 = mirrored conj
__device__ float2 g_T2[NIMG*NPIX];      // T2 packed [132][67] complex
__device__ float  g_z[NIMG*NPIX];       // real spatial result

// ---------------- DFT matrix ----------------
__global__ void k_buildF() {
    int i = blockIdx.x * blockDim.x + threadIdx.x;
    if (i >= NPIX) return;
    int k = i / NN, n = i % NN;
    int t = (k * n) % NN;
    float ang = (2.0f * PIF / NN) * (float)t;
    float s, c; sincosf(ang, &s, &c);
    g_F[i] = make_float2(c, -s);
}

// ---------------- g3 phase matrix: E[t][m] ----------------
// original sum over k1=0..131 of conj(F[k1][m]) Y[k1][k2]:
//   t<=66: term = e^{+2pi i t m/N} * Y[t][k2]
//   t>=67: with j=132-t, conj(F[t][m]) = F[j][m] = e^{-2pi i j m/N}, operand = Ys[t] (mirrored row)
__global__ void k_buildE() {
    int i = blockIdx.x * blockDim.x + threadIdx.x;
    if (i >= NPIX) return;
    int t = i / NN, m = i % NN;
    int j = (t <= 66) ? t : (NN - t);
    int tm = (j * m) % NN;
    float ang = (2.0f * PIF / NN) * (float)tm;
    float s, c; sincosf(ang, &s, &c);
    g_E[i] = make_float2(c, (t <= 66) ? s : -s);
}

// ---------------- g4 real matrix: z[m1][m2] = sum_t A[m1][t] * G4B[t][m2] ----------------
// A = T2 row-major viewed as floats (interleaved re,im), K = 134.
// z = sum_{k2=0}^{66} g[k2] * ( T2r*cos(2pi k2 m2/N) - T2i*sin(2pi k2 m2/N) ),
// g=1 for k2 in {0,66}, else 2.
__global__ void k_buildG4B() {
    int i = blockIdx.x * blockDim.x + threadIdx.x;
    if (i >= KG4 * NN) return;
    int t = i / NN, m2 = i % NN;
    int k2 = t >> 1;
    float g = (k2 == 0 || k2 == 66) ? 1.0f : 2.0f;
    int tm = (k2 * m2) % NN;
    float ang = (2.0f * PIF / NN) * (float)tm;
    float s, c; sincosf(ang, &s, &c);
    g_G4B[i] = (t & 1) ? (-g * s) : (g * c);
}

// ---------------- per-channel frequency filter ----------------
__global__ void k_buildR(const float* __restrict__ w, const float* __restrict__ bias) {
    int k2 = threadIdx.x;     // 0..131
    int k1 = blockIdx.x;      // 0..131
    int c  = blockIdx.y;      // 0..63
    __shared__ float sw[9];
    if (threadIdx.x < 9) sw[threadIdx.x] = w[c * 9 + threadIdx.x];
    __syncthreads();
    float alpha = 1.0f / (1.0f + expf(9.0f - bias[c])) + 1e-5f;

    float Vr = 0.f, Vi = 0.f, W2 = 0.f;
    #pragma unroll
    for (int r1 = 0; r1 < 2; r1++)
    #pragma unroll
    for (int r2 = 0; r2 < 2; r2++) {
        int kk1 = k1 + r1 * NN;
        int kk2 = k2 + r2 * NN;
        float fr = 0.f, fi = 0.f;
        #pragma unroll
        for (int u = 0; u < 3; u++)
        #pragma unroll
        for (int v = 0; v < 3; v++) {
            int t = kk1 * (u - 1) + kk2 * (v - 1);
            t %= MM; if (t < 0) t += MM;
            float ang = (2.0f * PIF / MM) * (float)t;
            float sn, cs; sincosf(ang, &sn, &cs);
            float wv = sw[u * 3 + v];
            fr += wv * cs;
            fi -= wv * sn;
        }
        float a1 = (2.0f * PIF / MM) * (float)kk1;
        float a2 = (2.0f * PIF / MM) * (float)kk2;
        float s1, c1, s2, c2;
        sincosf(a1, &s1, &c1);
        sincosf(a2, &s2, &c2);
        float u1r = 1.f + c1, u1i = -s1;
        float u2r = 1.f + c2, u2i = -s2;
        float Ur = u1r * u2r - u1i * u2i;
        float Ui = u1r * u2i + u1i * u2r;
        Vr += fr * Ur - fi * Ui;
        Vi += fr * Ui + fi * Ur;
        W2 += fr * fr + fi * fi;
    }
    Vr *= 0.25f; Vi *= 0.25f; W2 *= 0.25f;
    float sc = 1.0f / (W2 + alpha) * (1.0f / (float)NPIX);
    g_R[(c * NN + k1) * NN + k2] = make_float2((1.f - Vr) * sc, (-Vi) * sc);
}

// ---------------- circular pad (wrap by 2) ----------------
__global__ void k_pad(const float* __restrict__ x) {
    int i = blockIdx.x * blockDim.x + threadIdx.x;
    if (i >= NIMG * NPIX) return;
    int img = i / NPIX;
    int rem = i - img * NPIX;
    int r = rem / NN, cc = rem % NN;
    int sr = (r + 126) & 127;
    int sc = (cc + 126) & 127;
    g_xpad[i] = x[(img * 128 + sr) * 128 + sc];
}

// ---------------- GEMM 1: T1[k][j] = sum_n F[k][n] * xpad[n][j], k = 0..66 only ----------------
__global__ void k_g1() {
    __shared__ float2 As[32][33];
    __shared__ float  Bs[32][33];
    int img = blockIdx.z;
    int rowBase = blockIdx.y * 32, colBase = blockIdx.x * 32;
    int tx = threadIdx.x, ty = threadIdx.y, tid = ty * 16 + tx;
    const float* B = g_xpad + img * NPIX;
    float ar[2][2] = {{0,0},{0,0}}, ai[2][2] = {{0,0},{0,0}};
    for (int k0 = 0; k0 < NN; k0 += 32) {
        #pragma unroll
        for (int l = 0; l < 4; l++) {
            int lin = l * 256 + tid, ml = lin >> 5, kk = lin & 31;
            int r = rowBase + ml, cc = k0 + kk;
            As[ml][kk] = (r < NH && cc < NN) ? g_F[r * NN + cc] : make_float2(0.f, 0.f);
        }
        #pragma unroll
        for (int l = 0; l < 4; l++) {
            int lin = l * 256 + tid, kk = lin >> 5, nl = lin & 31;
            int r = k0 + kk, cc = colBase + nl;
            Bs[kk][nl] = (r < NN && cc < NN) ? B[r * NN + cc] : 0.f;
        }
        __syncthreads();
        #pragma unroll
        for (int kk = 0; kk < 32; kk++) {
            float2 a0 = As[ty][kk], a1 = As[ty + 16][kk];
            float b0 = Bs[kk][tx], b1 = Bs[kk][tx + 16];
            ar[0][0] += a0.x * b0; ai[0][0] += a0.y * b0;
            ar[0][1] += a0.x * b1; ai[0][1] += a0.y * b1;
            ar[1][0] += a1.x * b0; ai[1][0] += a1.y * b0;
            ar[1][1] += a1.x * b1; ai[1][1] += a1.y * b1;
        }
        __syncthreads();
    }
    float2* Cm = g_T1 + img * NPIX;
    #pragma unroll
    for (int i = 0; i < 2; i++) {
        int r = rowBase + ty + i * 16; if (r >= NH) continue;
        #pragma unroll
        for (int j = 0; j < 2; j++) {
            int c = colBase + tx + j * 16; if (c >= NN) continue;
            Cm[r * NN + c] = make_float2(ar[i][j], ai[i][j]);
        }
    }
}

// ---------------- GEMM 2: X[k1][k2] = sum_j T1[k1][j] * F[k2][j], k1 = 0..66 ----------------
// Fused epilogue: Y = X .* R(channel); store stacked Ys with Hermitian mirror rows:
//   Ys[k1][k2] = Y ; for k1 in 1..65: Ys[132-k1][(132-k2)%132] = conj(Y)
__global__ void k_g2() {
    __shared__ float2 As[32][33];
    __shared__ float2 Bt[32][33];
    int img = blockIdx.z;
    int rowBase = blockIdx.y * 32, colBase = blockIdx.x * 32;
    int tx = threadIdx.x, ty = threadIdx.y, tid = ty * 16 + tx;
    const float2* A = g_T1 + img * NPIX;
    float ar[2][2] = {{0,0},{0,0}}, ai[2][2] = {{0,0},{0,0}};
    for (int k0 = 0; k0 < NN; k0 += 32) {
        #pragma unroll
        for (int l = 0; l < 4; l++) {
            int lin = l * 256 + tid, ml = lin >> 5, kk = lin & 31;
            int r = rowBase + ml, cc = k0 + kk;
            As[ml][kk] = (r < NH && cc < NN) ? A[r * NN + cc] : make_float2(0.f, 0.f);
        }
        #pragma unroll
        for (int l = 0; l < 4; l++) {
            int lin = l * 256 + tid, nl = lin >> 5, kk = lin & 31;
            int r = colBase + nl, cc = k0 + kk;
            Bt[nl][kk] = (r < NN && cc < NN) ? g_F[r * NN + cc] : make_float2(0.f, 0.f);
        }
        __syncthreads();
        #pragma unroll
        for (int kk = 0; kk < 32; kk++) {
            float2 a0 = As[ty][kk], a1 = As[ty + 16][kk];
            float2 b0 = Bt[tx][kk], b1 = Bt[tx + 16][kk];
            ar[0][0] += a0.x * b0.x - a0.y * b0.y; ai[0][0] += a0.x * b0.y + a0.y * b0.x;
            ar[0][1] += a0.x * b1.x - a0.y * b1.y; ai[0][1] += a0.x * b1.y + a0.y * b1.x;
            ar[1][0] += a1.x * b0.x - a1.y * b0.y; ai[1][0] += a1.x * b0.y + a1.y * b0.x;
            ar[1][1] += a1.x * b1.x - a1.y * b1.y; ai[1][1] += a1.x * b1.y + a1.y * b1.x;
        }
        __syncthreads();
    }
    int ch = img & 63;
    const float2* Rc = g_R + ch * NPIX;
    float2* Ys = g_X + img * NPIX;
    #pragma unroll
    for (int i = 0; i < 2; i++) {
        int r = rowBase + ty + i * 16; if (r >= NH) continue;
        #pragma unroll
        for (int j = 0; j < 2; j++) {
            int c = colBase + tx + j * 16; if (c >= NN) continue;
            float2 rr = Rc[r * NN + c];
            float yr = ar[i][j] * rr.x - ai[i][j] * rr.y;
            float yi = ar[i][j] * rr.y + ai[i][j] * rr.x;
            Ys[r * NN + c] = make_float2(yr, yi);
            if (r >= 1 && r <= 65) {
                int mc = (NN - c) % NN;
                Ys[(NN - r) * NN + mc] = make_float2(yr, -yi);
            }
        }
    }
}

// ---------------- GEMM 3: T2[m][k2] = sum_t E[t][m] * Ys[t][k2], k2 = 0..66 ----------------
// Output packed: g_T2[img][m*67 + k2]
__global__ void k_g3() {
    __shared__ float2 As[32][33];   // As[ml][kk] = E[(k0+kk)][rowBase+ml]
    __shared__ float2 Bs[32][33];
    int img = blockIdx.z;
    int rowBase = blockIdx.y * 32, colBase = blockIdx.x * 32;
    int tx = threadIdx.x, ty = threadIdx.y, tid = ty * 16 + tx;
    const float2* Y = g_X + img * NPIX;
    float ar[2][2] = {{0,0},{0,0}}, ai[2][2] = {{0,0},{0,0}};
    for (int k0 = 0; k0 < NN; k0 += 32) {
        #pragma unroll
        for (int l = 0; l < 4; l++) {
            int lin = l * 256 + tid, kk = lin >> 5, ml = lin & 31;
            int r = k0 + kk, cc = rowBase + ml;
            As[ml][kk] = (r < NN && cc < NN) ? g_E[r * NN + cc] : make_float2(0.f, 0.f);
        }
        #pragma unroll
        for (int l = 0; l < 4; l++) {
            int lin = l * 256 + tid, kk = lin >> 5, nl = lin & 31;
            int r = k0 + kk, cc = colBase + nl;
            Bs[kk][nl] = (r < NN && cc < NN) ? Y[r * NN + cc] : make_float2(0.f, 0.f);
        }
        __syncthreads();
        #pragma unroll
        for (int kk = 0; kk < 32; kk++) {
            float2 a0 = As[ty][kk], a1 = As[ty + 16][kk];
            float2 b0 = Bs[kk][tx], b1 = Bs[kk][tx + 16];
            ar[0][0] += a0.x * b0.x - a0.y * b0.y; ai[0][0] += a0.x * b0.y + a0.y * b0.x;
            ar[0][1] += a0.x * b1.x - a0.y * b1.y; ai[0][1] += a0.x * b1.y + a0.y * b1.x;
            ar[1][0] += a1.x * b0.x - a1.y * b0.y; ai[1][0] += a1.x * b0.y + a1.y * b0.x;
            ar[1][1] += a1.x * b1.x - a1.y * b1.y; ai[1][1] += a1.x * b1.y + a1.y * b1.x;
        }
        __syncthreads();
    }
    float2* Cm = g_T2 + img * NPIX;
    #pragma unroll
    for (int i = 0; i < 2; i++) {
        int r = rowBase + ty + i * 16; if (r >= NN) continue;
        #pragma unroll
        for (int j = 0; j < 2; j++) {
            int c = colBase + tx + j * 16; if (c >= NH) continue;
            Cm[r * NH + c] = make_float2(ar[i][j], ai[i][j]);
        }
    }
}

// ---------------- GEMM 4 (real): z[m1][m2] = sum_{t<134} T2f[m1][t] * G4B[t][m2] ----------------
__global__ void k_g4() {
    __shared__ float As[32][33];
    __shared__ float Bs[32][33];
    int img = blockIdx.z;
    int rowBase = blockIdx.y * 32, colBase = blockIdx.x * 32;
    int tx = threadIdx.x, ty = threadIdx.y, tid = ty * 16 + tx;
    const float* A = (const float*)(g_T2 + img * NPIX);  // [132][134] floats
    float acc[2][2] = {{0,0},{0,0}};
    for (int k0 = 0; k0 < KG4; k0 += 32) {
        #pragma unroll
        for (int l = 0; l < 4; l++) {
            int lin = l * 256 + tid, ml = lin >> 5, kk = lin & 31;
            int r = rowBase + ml, cc = k0 + kk;
            As[ml][kk] = (r < NN && cc < KG4) ? A[r * KG4 + cc] : 0.f;
        }
        #pragma unroll
        for (int l = 0; l < 4; l++) {
            int lin = l * 256 + tid, kk = lin >> 5, nl = lin & 31;
            int r = k0 + kk, cc = colBase + nl;
            Bs[kk][nl] = (r < KG4 && cc < NN) ? g_G4B[r * NN + cc] : 0.f;
        }
        __syncthreads();
        #pragma unroll
        for (int kk = 0; kk < 32; kk++) {
            float a0 = As[ty][kk], a1 = As[ty + 16][kk];
            float b0 = Bs[kk][tx], b1 = Bs[kk][tx + 16];
            acc[0][0] += a0 * b0;
            acc[0][1] += a0 * b1;
            acc[1][0] += a1 * b0;
            acc[1][1] += a1 * b1;
        }
        __syncthreads();
    }
    float* Cm = g_z + img * NPIX;
    #pragma unroll
    for (int i = 0; i < 2; i++) {
        int r = rowBase + ty + i * 16; if (r >= NN) continue;
        #pragma unroll
        for (int j = 0; j < 2; j++) {
            int c = colBase + tx + j * 16; if (c >= NN) continue;
            Cm[r * NN + c] = acc[i][j];
        }
    }
}

// ---------------- final: nearest-up + 3x3 polyphase gather + crop + exact GELU ----------------
__global__ void k_final(const float* __restrict__ wt, float* __restrict__ out) {
    int i = blockIdx.x * blockDim.x + threadIdx.x;
    int q = i & 255;
    int p = (i >> 8) & 255;
    int img = i >> 16;
    int c = img & 63;
    int n1 = p + 4, n2 = q + 4;
    int m1 = n1 >> 1, m2 = n2 >> 1;
    int a1 = n1 & 1, a2 = n2 & 1;
    const float* z = g_z + img * NPIX;
    const float* w = wt + c * 9;
    float z00 = z[m1 * NN + m2];
    float acc;
    if (a1 == 0) {
        if (a2 == 0) acc = w[4] * z00;
        else         acc = w[3] * z00 + w[5] * z[m1 * NN + m2 + 1];
    } else {
        if (a2 == 0) acc = w[1] * z00 + w[7] * z[(m1 + 1) * NN + m2];
        else         acc = w[0] * z00 + w[2] * z[m1 * NN + m2 + 1]
                         + w[6] * z[(m1 + 1) * NN + m2] + w[8] * z[(m1 + 1) * NN + m2 + 1];
    }
    float v = g_xpad[img * NPIX + m1 * NN + m2] + acc;
    out[i] = 0.5f * v * (1.0f + erff(v * 0.70710678118654752f));
}

// ---------------- launch ----------------
extern "C" void kernel_launch(void* const* d_in, const int* in_sizes, int n_in,
                              void* d_out, int out_size) {
    const float* x    = (const float*)d_in[0];   // (4,64,128,128)
    const float* w    = (const float*)d_in[1];   // (1,64,3,3)
    const float* bias = (const float*)d_in[2];   // (1,64,1,1)
    float* out = (float*)d_out;                  // (4,64,256,256)

    k_buildF<<<(NPIX + 255) / 256, 256>>>();
    k_buildE<<<(NPIX + 255) / 256, 256>>>();
    k_buildG4B<<<(KG4 * NN + 255) / 256, 256>>>();
    k_buildR<<<dim3(NN, NCH), NN>>>(w, bias);
    k_pad<<<(NIMG * NPIX + 255) / 256, 256>>>(x);

    dim3 blk(16, 16);
    // g1: rows 0..66 (3 tiles), cols 132 (5 tiles)
    k_g1<<<dim3(5, 3, NIMG), blk>>>();
    // g2: rows 0..66 (3 tiles), cols 132 (5 tiles); fused R + Hermitian mirror store
    k_g2<<<dim3(5, 3, NIMG), blk>>>();
    // g3: rows m 132 (5 tiles), cols k2 0..66 (3 tiles)
    k_g3<<<dim3(3, 5, NIMG), blk>>>();
    // g4: real GEMM, 132x132 out (5x5), K=134
    k_g4<<<dim3(5, 5, NIMG), blk>>>();

    k_final<<<(4 * 64 * 256 * 256) / 256, 256>>>(w, out);
}

// round 6
// speedup vs baseline: 1.5449x; 1.0639x over previous
#include <cuda_runtime.h>
#include <math.h>

#define NN 132
#define MM 264
#define NPIX (NN*NN)      // 17424
#define NIMG 256          // 4*64
#define NCH  64
#define NH   67           // rows 0..66 (Hermitian half)
#define KG4  134          // 67 complex = 134 floats
#define PIF 3.14159265358979323846f

// ---------------- static scratch (allocation-free) ----------------
__device__ float2 g_F[NPIX];            // F[k][n] = exp(-2pi i k n / N)
__device__ float2 g_E[NPIX];            // g3 phase matrix
__device__ float  g_G4B[KG4*NN];        // real IDFT-over-k2 matrix w/ Hermitian doubling
__device__ float2 g_R[NCH*NPIX];        // per-channel filter
__device__ float2 g_E1[MM*3];           // E1[kk][u] = exp(-2pi i kk (u-1)/264)
__device__ float2 g_U1[MM];             // 1 + exp(-2pi i kk/264)
__device__ float2 g_WB[NCH*MM*3];       // WB[c][kk][u] = sum_v w[c][u][v] E1[kk][v]
__device__ float2 g_T1[NIMG*NPIX];      // F * x (rows 0..66 valid)
__device__ float2 g_X[NIMG*NPIX];       // stacked Ys (Hermitian-mirrored full)
__device__ float2 g_T2[NIMG*NPIX];      // T2 packed [132][67] complex
__device__ float  g_z[NIMG*NPIX];       // real spatial result

// ---------------- DFT matrix ----------------
__global__ void k_buildF() {
    int i = blockIdx.x * blockDim.x + threadIdx.x;
    if (i >= NPIX) return;
    int k = i / NN, n = i % NN;
    int t = (k * n) % NN;
    float ang = (2.0f * PIF / NN) * (float)t;
    float s, c; sincosf(ang, &s, &c);
    g_F[i] = make_float2(c, -s);
}

// ---------------- g3 phase matrix ----------------
__global__ void k_buildE() {
    int i = blockIdx.x * blockDim.x + threadIdx.x;
    if (i >= NPIX) return;
    int t = i / NN, m = i % NN;
    int j = (t <= 66) ? t : (NN - t);
    int tm = (j * m) % NN;
    float ang = (2.0f * PIF / NN) * (float)tm;
    float s, c; sincosf(ang, &s, &c);
    g_E[i] = make_float2(c, (t <= 66) ? s : -s);
}

// ---------------- g4 real matrix ----------------
__global__ void k_buildG4B() {
    int i = blockIdx.x * blockDim.x + threadIdx.x;
    if (i >= KG4 * NN) return;
    int t = i / NN, m2 = i % NN;
    int k2 = t >> 1;
    float g = (k2 == 0 || k2 == 66) ? 1.0f : 2.0f;
    int tm = (k2 * m2) % NN;
    float ang = (2.0f * PIF / NN) * (float)tm;
    float s, c; sincosf(ang, &s, &c);
    g_G4B[i] = (t & 1) ? (-g * s) : (g * c);
}

// ---------------- twiddle tables for buildR ----------------
__global__ void k_buildTw() {
    int kk = blockIdx.x * blockDim.x + threadIdx.x;
    if (kk >= MM) return;
    #pragma unroll
    for (int u = 0; u < 3; u++) {
        int t = kk * (u - 1);
        t %= MM; if (t < 0) t += MM;
        float ang = (2.0f * PIF / MM) * (float)t;
        float s, c; sincosf(ang, &s, &c);
        g_E1[kk * 3 + u] = make_float2(c, -s);
    }
    float ang = (2.0f * PIF / MM) * (float)kk;
    float s, c; sincosf(ang, &s, &c);
    g_U1[kk] = make_float2(1.f + c, -s);
}

__global__ void k_buildWB(const float* __restrict__ w) {
    int kk = blockIdx.x * blockDim.x + threadIdx.x;
    int c = blockIdx.y;
    if (kk >= MM) return;
    float2 e0 = g_E1[kk * 3 + 0], e1 = g_E1[kk * 3 + 1], e2 = g_E1[kk * 3 + 2];
    #pragma unroll
    for (int u = 0; u < 3; u++) {
        float w0 = w[c * 9 + u * 3 + 0];
        float w1 = w[c * 9 + u * 3 + 1];
        float w2 = w[c * 9 + u * 3 + 2];
        g_WB[(c * MM + kk) * 3 + u] =
            make_float2(w0 * e0.x + w1 * e1.x + w2 * e2.x,
                        w0 * e0.y + w1 * e1.y + w2 * e2.y);
    }
}

// ---------------- per-channel frequency filter (table-driven, no sincos) ----------------
__global__ void k_buildR(const float* __restrict__ bias) {
    int k2 = threadIdx.x;     // 0..131
    int k1 = blockIdx.x;      // 0..131
    int c  = blockIdx.y;      // 0..63
    float alpha = 1.0f / (1.0f + expf(9.0f - bias[c])) + 1e-5f;

    float Vr = 0.f, Vi = 0.f, W2 = 0.f;
    #pragma unroll
    for (int r1 = 0; r1 < 2; r1++)
    #pragma unroll
    for (int r2 = 0; r2 < 2; r2++) {
        int kk1 = k1 + r1 * NN;
        int kk2 = k2 + r2 * NN;
        float fr = 0.f, fi = 0.f;
        #pragma unroll
        for (int u = 0; u < 3; u++) {
            float2 e = g_E1[kk1 * 3 + u];
            float2 b = g_WB[(c * MM + kk2) * 3 + u];
            fr += e.x * b.x - e.y * b.y;
            fi += e.x * b.y + e.y * b.x;
        }
        float2 u1 = g_U1[kk1], u2 = g_U1[kk2];
        float Ur = u1.x * u2.x - u1.y * u2.y;
        float Ui = u1.x * u2.y + u1.y * u2.x;
        Vr += fr * Ur - fi * Ui;
        Vi += fr * Ui + fi * Ur;
        W2 += fr * fr + fi * fi;
    }
    Vr *= 0.25f; Vi *= 0.25f; W2 *= 0.25f;
    float sc = 1.0f / (W2 + alpha) * (1.0f / (float)NPIX);
    g_R[(c * NN + k1) * NN + k2] = make_float2((1.f - Vr) * sc, (-Vi) * sc);
}

// ---------------- GEMM 1: T1[k][j] = sum_n F[k][n] * xwrap[n][j], k = 0..66 ----------------
// blockDim (8,16); 32x32 tile; 2x4 microtile; B loaded from x with circular wrap
__global__ void k_g1(const float* __restrict__ x) {
    __shared__ float2 As[32][33];
    __shared__ float  Bs[32][36];
    int img = blockIdx.z;
    int rowBase = blockIdx.y * 32, colBase = blockIdx.x * 32;
    int tx = threadIdx.x, ty = threadIdx.y, tid = ty * 8 + tx;
    const float* xb = x + img * 16384;
    float ar[2][4] = {{0}}, ai[2][4] = {{0}};
    for (int k0 = 0; k0 < NN; k0 += 32) {
        #pragma unroll
        for (int l = 0; l < 8; l++) {
            int lin = l * 128 + tid, ml = lin >> 5, kk = lin & 31;
            int r = rowBase + ml, cc = k0 + kk;
            As[ml][kk] = (r < NH && cc < NN) ? g_F[r * NN + cc] : make_float2(0.f, 0.f);
        }
        #pragma unroll
        for (int l = 0; l < 8; l++) {
            int lin = l * 128 + tid, kk = lin >> 5, nl = lin & 31;
            int r = k0 + kk, cc = colBase + nl;
            Bs[kk][nl] = (r < NN && cc < NN)
                ? xb[(((r + 126) & 127) << 7) + ((cc + 126) & 127)] : 0.f;
        }
        __syncthreads();
        #pragma unroll
        for (int kk = 0; kk < 32; kk++) {
            float2 a0 = As[ty][kk], a1 = As[ty + 16][kk];
            float4 b = *(const float4*)&Bs[kk][tx * 4];
            float bj[4] = {b.x, b.y, b.z, b.w};
            #pragma unroll
            for (int j = 0; j < 4; j++) {
                ar[0][j] += a0.x * bj[j]; ai[0][j] += a0.y * bj[j];
                ar[1][j] += a1.x * bj[j]; ai[1][j] += a1.y * bj[j];
            }
        }
        __syncthreads();
    }
    float2* Cm = g_T1 + img * NPIX;
    #pragma unroll
    for (int i = 0; i < 2; i++) {
        int r = rowBase + ty + i * 16; if (r >= NH) continue;
        #pragma unroll
        for (int j = 0; j < 4; j++) {
            int c = colBase + tx * 4 + j; if (c >= NN) continue;
            Cm[r * NN + c] = make_float2(ar[i][j], ai[i][j]);
        }
    }
}

// ---------------- GEMM 2: X = T1 * F^T (k1=0..66); fused *R + Hermitian mirror store ----------------
__global__ void k_g2() {
    __shared__ float2 As[32][33];
    __shared__ float2 Bs[32][36];   // Bs[kk][nl] = F[(colBase+nl)][k0+kk]
    int img = blockIdx.z;
    int rowBase = blockIdx.y * 32, colBase = blockIdx.x * 32;
    int tx = threadIdx.x, ty = threadIdx.y, tid = ty * 8 + tx;
    const float2* A = g_T1 + img * NPIX;
    float ar[2][4] = {{0}}, ai[2][4] = {{0}};
    for (int k0 = 0; k0 < NN; k0 += 32) {
        #pragma unroll
        for (int l = 0; l < 8; l++) {
            int lin = l * 128 + tid, ml = lin >> 5, kk = lin & 31;
            int r = rowBase + ml, cc = k0 + kk;
            As[ml][kk] = (r < NH && cc < NN) ? A[r * NN + cc] : make_float2(0.f, 0.f);
        }
        #pragma unroll
        for (int l = 0; l < 8; l++) {
            int lin = l * 128 + tid, nl = lin >> 5, kk = lin & 31;
            int r = colBase + nl, cc = k0 + kk;
            Bs[kk][nl] = (r < NN && cc < NN) ? g_F[r * NN + cc] : make_float2(0.f, 0.f);
        }
        __syncthreads();
        #pragma unroll
        for (int kk = 0; kk < 32; kk++) {
            float2 a0 = As[ty][kk], a1 = As[ty + 16][kk];
            float4 p = *(const float4*)&Bs[kk][tx * 4];
            float4 q = *(const float4*)&Bs[kk][tx * 4 + 2];
            float2 b[4] = {{p.x, p.y}, {p.z, p.w}, {q.x, q.y}, {q.z, q.w}};
            #pragma unroll
            for (int j = 0; j < 4; j++) {
                ar[0][j] += a0.x * b[j].x - a0.y * b[j].y;
                ai[0][j] += a0.x * b[j].y + a0.y * b[j].x;
                ar[1][j] += a1.x * b[j].x - a1.y * b[j].y;
                ai[1][j] += a1.x * b[j].y + a1.y * b[j].x;
            }
        }
        __syncthreads();
    }
    int ch = img & 63;
    const float2* Rc = g_R + ch * NPIX;
    float2* Ys = g_X + img * NPIX;
    #pragma unroll
    for (int i = 0; i < 2; i++) {
        int r = rowBase + ty + i * 16; if (r >= NH) continue;
        #pragma unroll
        for (int j = 0; j < 4; j++) {
            int c = colBase + tx * 4 + j; if (c >= NN) continue;
            float2 rr = Rc[r * NN + c];
            float yr = ar[i][j] * rr.x - ai[i][j] * rr.y;
            float yi = ar[i][j] * rr.y + ai[i][j] * rr.x;
            Ys[r * NN + c] = make_float2(yr, yi);
            if (r >= 1 && r <= 65) {
                int mc = (NN - c) % NN;
                Ys[(NN - r) * NN + mc] = make_float2(yr, -yi);
            }
        }
    }
}

// ---------------- GEMM 3: T2[m][k2] = sum_t E[t][m] * Ys[t][k2], k2 = 0..66 ----------------
__global__ void k_g3() {
    __shared__ float2 As[32][33];   // As[ml][kk] = E[(k0+kk)][rowBase+ml]
    __shared__ float2 Bs[32][36];
    int img = blockIdx.z;
    int rowBase = blockIdx.y * 32, colBase = blockIdx.x * 32;
    int tx = threadIdx.x, ty = threadIdx.y, tid = ty * 8 + tx;
    const float2* Y = g_X + img * NPIX;
    float ar[2][4] = {{0}}, ai[2][4] = {{0}};
    for (int k0 = 0; k0 < NN; k0 += 32) {
        #pragma unroll
        for (int l = 0; l < 8; l++) {
            int lin = l * 128 + tid, kk = lin >> 5, ml = lin & 31;
            int r = k0 + kk, cc = rowBase + ml;
            As[ml][kk] = (r < NN && cc < NN) ? g_E[r * NN + cc] : make_float2(0.f, 0.f);
        }
        #pragma unroll
        for (int l = 0; l < 8; l++) {
            int lin = l * 128 + tid, kk = lin >> 5, nl = lin & 31;
            int r = k0 + kk, cc = colBase + nl;
            Bs[kk][nl] = (r < NN && cc < NN) ? Y[r * NN + cc] : make_float2(0.f, 0.f);
        }
        __syncthreads();
        #pragma unroll
        for (int kk = 0; kk < 32; kk++) {
            float2 a0 = As[ty][kk], a1 = As[ty + 16][kk];
            float4 p = *(const float4*)&Bs[kk][tx * 4];
            float4 q = *(const float4*)&Bs[kk][tx * 4 + 2];
            float2 b[4] = {{p.x, p.y}, {p.z, p.w}, {q.x, q.y}, {q.z, q.w}};
            #pragma unroll
            for (int j = 0; j < 4; j++) {
                ar[0][j] += a0.x * b[j].x - a0.y * b[j].y;
                ai[0][j] += a0.x * b[j].y + a0.y * b[j].x;
                ar[1][j] += a1.x * b[j].x - a1.y * b[j].y;
                ai[1][j] += a1.x * b[j].y + a1.y * b[j].x;
            }
        }
        __syncthreads();
    }
    float2* Cm = g_T2 + img * NPIX;
    #pragma unroll
    for (int i = 0; i < 2; i++) {
        int r = rowBase + ty + i * 16; if (r >= NN) continue;
        #pragma unroll
        for (int j = 0; j < 4; j++) {
            int c = colBase + tx * 4 + j; if (c >= NH) continue;
            Cm[r * NH + c] = make_float2(ar[i][j], ai[i][j]);
        }
    }
}

// ---------------- GEMM 4 (real): z[m1][m2] = sum_{t<134} T2f[m1][t] * G4B[t][m2] ----------------
__global__ void k_g4() {
    __shared__ float As[32][33];
    __shared__ float Bs[32][36];
    int img = blockIdx.z;
    int rowBase = blockIdx.y * 32, colBase = blockIdx.x * 32;
    int tx = threadIdx.x, ty = threadIdx.y, tid = ty * 8 + tx;
    const float* A = (const float*)(g_T2 + img * NPIX);  // [132][134] floats
    float acc[2][4] = {{0}};
    for (int k0 = 0; k0 < KG4; k0 += 32) {
        #pragma unroll
        for (int l = 0; l < 8; l++) {
            int lin = l * 128 + tid, ml = lin >> 5, kk = lin & 31;
            int r = rowBase + ml, cc = k0 + kk;
            As[ml][kk] = (r < NN && cc < KG4) ? A[r * KG4 + cc] : 0.f;
        }
        #pragma unroll
        for (int l = 0; l < 8; l++) {
            int lin = l * 128 + tid, kk = lin >> 5, nl = lin & 31;
            int r = k0 + kk, cc = colBase + nl;
            Bs[kk][nl] = (r < KG4 && cc < NN) ? g_G4B[r * NN + cc] : 0.f;
        }
        __syncthreads();
        #pragma unroll
        for (int kk = 0; kk < 32; kk++) {
            float a0 = As[ty][kk], a1 = As[ty + 16][kk];
            float4 b = *(const float4*)&Bs[kk][tx * 4];
            float bj[4] = {b.x, b.y, b.z, b.w};
            #pragma unroll
            for (int j = 0; j < 4; j++) {
                acc[0][j] += a0 * bj[j];
                acc[1][j] += a1 * bj[j];
            }
        }
        __syncthreads();
    }
    float* Cm = g_z + img * NPIX;
    #pragma unroll
    for (int i = 0; i < 2; i++) {
        int r = rowBase + ty + i * 16; if (r >= NN) continue;
        #pragma unroll
        for (int j = 0; j < 4; j++) {
            int c = colBase + tx * 4 + j; if (c >= NN) continue;
            Cm[r * NN + c] = acc[i][j];
        }
    }
}

// ---------------- final: nearest-up + 3x3 polyphase gather + crop + exact GELU ----------------
__global__ void k_final(const float* __restrict__ x, const float* __restrict__ wt,
                        float* __restrict__ out) {
    int i = blockIdx.x * blockDim.x + threadIdx.x;
    int q = i & 255;
    int p = (i >> 8) & 255;
    int img = i >> 16;
    int c = img & 63;
    int n1 = p + 4, n2 = q + 4;
    int m1 = n1 >> 1, m2 = n2 >> 1;
    int a1 = n1 & 1, a2 = n2 & 1;
    const float* z = g_z + img * NPIX;
    const float* w = wt + c * 9;
    float z00 = z[m1 * NN + m2];
    float acc;
    if (a1 == 0) {
        if (a2 == 0) acc = w[4] * z00;
        else         acc = w[3] * z00 + w[5] * z[m1 * NN + m2 + 1];
    } else {
        if (a2 == 0) acc = w[1] * z00 + w[7] * z[(m1 + 1) * NN + m2];
        else         acc = w[0] * z00 + w[2] * z[m1 * NN + m2 + 1]
                         + w[6] * z[(m1 + 1) * NN + m2] + w[8] * z[(m1 + 1) * NN + m2 + 1];
    }
    float v = x[(img * 128 + ((m1 + 126) & 127)) * 128 + ((m2 + 126) & 127)] + acc;
    out[i] = 0.5f * v * (1.0f + erff(v * 0.70710678118654752f));
}

// ---------------- launch ----------------
extern "C" void kernel_launch(void* const* d_in, const int* in_sizes, int n_in,
                              void* d_out, int out_size) {
    const float* x    = (const float*)d_in[0];   // (4,64,128,128)
    const float* w    = (const float*)d_in[1];   // (1,64,3,3)
    const float* bias = (const float*)d_in[2];   // (1,64,1,1)
    float* out = (float*)d_out;                  // (4,64,256,256)

    k_buildF<<<(NPIX + 255) / 256, 256>>>();
    k_buildE<<<(NPIX + 255) / 256, 256>>>();
    k_buildG4B<<<(KG4 * NN + 255) / 256, 256>>>();
    k_buildTw<<<(MM + 127) / 128, 128>>>();
    k_buildWB<<<dim3((MM + 127) / 128, NCH), 128>>>(w);
    k_buildR<<<dim3(NN, NCH), NN>>>(bias);

    dim3 blk(8, 16);
    k_g1<<<dim3(5, 3, NIMG), blk>>>(x);   // rows 0..66 (3 tiles) x cols 132 (5 tiles)
    k_g2<<<dim3(5, 3, NIMG), blk>>>();    // fused R + Hermitian mirror
    k_g3<<<dim3(3, 5, NIMG), blk>>>();    // rows m (5) x cols k2 0..66 (3)
    k_g4<<<dim3(5, 5, NIMG), blk>>>();    // real GEMM 132x132, K=134

    k_final<<<(4 * 64 * 256 * 256) / 256, 256>>>(x, w, out);
}

// round 7
// speedup vs baseline: 2.0088x; 1.3003x over previous
#include <cuda_runtime.h>
#include <math.h>

#define NN 132
#define MM 264
#define NPIX (NN*NN)      // 17424
#define NIMG 256          // 4*64
#define NCH  64
#define NH   67           // Hermitian half rows (N even)
#define KT2  136          // planar re/im rows for T2', padded from 134
#define PIF 3.14159265358979323846f

// tile geometry: block (11,17) = 187 threads, microtile 2x4
// M-tile 34 (=2*17), N-tile 44 (=4*11), K-chunk 33 (132=4*33), g4 K-chunk 34 (136=4*34)

// ---------------- static scratch (allocation-free) ----------------
__device__ float2 g_F[NPIX];              // F[k][n] = e^{-2pi i kn/132} (symmetric)
__device__ float2 g_Fi[NPIX];             // Fi[k][n] = e^{+2pi i kn/132} (symmetric)
__device__ float  g_G4A[NN*KT2];          // [m1][t]: t=2k1 -> g cos, t=2k1+1 -> -g sin
__device__ float2 g_R[NCH*NPIX];          // per-channel filter
__device__ float2 g_E1[MM*3];
__device__ float2 g_U1[MM];
__device__ float2 g_WB[NCH*MM*3];
__device__ float2 g_T1[NIMG*NH*NN];       // F*xwrap, rows 0..66
__device__ float2 g_Y[NIMG*NH*NN];        // (T1*F)*R, rows 0..66
__device__ float  g_T2f[NIMG*KT2*NN];     // planar: row 2k1 = re, 2k1+1 = im
__device__ float  g_z[NIMG*NPIX];         // real spatial result

// ---------------- builders ----------------
__global__ void k_buildF() {
    int i = blockIdx.x * blockDim.x + threadIdx.x;
    if (i >= NPIX) return;
    int k = i / NN, n = i % NN;
    int t = (k * n) % NN;
    float ang = (2.0f * PIF / NN) * (float)t;
    float s, c; sincosf(ang, &s, &c);
    g_F[i]  = make_float2(c, -s);
    g_Fi[i] = make_float2(c,  s);
}

__global__ void k_buildG4A() {
    int i = blockIdx.x * blockDim.x + threadIdx.x;
    if (i >= NN * KT2) return;
    int m1 = i / KT2, t = i % KT2;
    int k1 = t >> 1;
    float val = 0.f;
    if (k1 <= 66) {
        float g = (k1 == 0 || k1 == 66) ? 1.0f : 2.0f;
        int tm = (k1 * m1) % NN;
        float ang = (2.0f * PIF / NN) * (float)tm;
        float s, c; sincosf(ang, &s, &c);
        val = (t & 1) ? (-g * s) : (g * c);
    }
    g_G4A[i] = val;
}

__global__ void k_buildTw() {
    int kk = blockIdx.x * blockDim.x + threadIdx.x;
    if (kk >= MM) return;
    #pragma unroll
    for (int u = 0; u < 3; u++) {
        int t = kk * (u - 1);
        t %= MM; if (t < 0) t += MM;
        float ang = (2.0f * PIF / MM) * (float)t;
        float s, c; sincosf(ang, &s, &c);
        g_E1[kk * 3 + u] = make_float2(c, -s);
    }
    float ang = (2.0f * PIF / MM) * (float)kk;
    float s, c; sincosf(ang, &s, &c);
    g_U1[kk] = make_float2(1.f + c, -s);
}

__global__ void k_buildWB(const float* __restrict__ w) {
    int kk = blockIdx.x * blockDim.x + threadIdx.x;
    int c = blockIdx.y;
    if (kk >= MM) return;
    float2 e0 = g_E1[kk * 3 + 0], e1 = g_E1[kk * 3 + 1], e2 = g_E1[kk * 3 + 2];
    #pragma unroll
    for (int u = 0; u < 3; u++) {
        float w0 = w[c * 9 + u * 3 + 0];
        float w1 = w[c * 9 + u * 3 + 1];
        float w2 = w[c * 9 + u * 3 + 2];
        g_WB[(c * MM + kk) * 3 + u] =
            make_float2(w0 * e0.x + w1 * e1.x + w2 * e2.x,
                        w0 * e0.y + w1 * e1.y + w2 * e2.y);
    }
}

__global__ void k_buildR(const float* __restrict__ bias) {
    int k2 = threadIdx.x, k1 = blockIdx.x, c = blockIdx.y;
    float alpha = 1.0f / (1.0f + expf(9.0f - bias[c])) + 1e-5f;
    float Vr = 0.f, Vi = 0.f, W2 = 0.f;
    #pragma unroll
    for (int r1 = 0; r1 < 2; r1++)
    #pragma unroll
    for (int r2 = 0; r2 < 2; r2++) {
        int kk1 = k1 + r1 * NN, kk2 = k2 + r2 * NN;
        float fr = 0.f, fi = 0.f;
        #pragma unroll
        for (int u = 0; u < 3; u++) {
            float2 e = g_E1[kk1 * 3 + u];
            float2 b = g_WB[(c * MM + kk2) * 3 + u];
            fr += e.x * b.x - e.y * b.y;
            fi += e.x * b.y + e.y * b.x;
        }
        float2 u1 = g_U1[kk1], u2 = g_U1[kk2];
        float Ur = u1.x * u2.x - u1.y * u2.y;
        float Ui = u1.x * u2.y + u1.y * u2.x;
        Vr += fr * Ur - fi * Ui;
        Vi += fr * Ui + fi * Ur;
        W2 += fr * fr + fi * fi;
    }
    Vr *= 0.25f; Vi *= 0.25f; W2 *= 0.25f;
    float sc = 1.0f / (W2 + alpha) * (1.0f / (float)NPIX);
    g_R[(c * NN + k1) * NN + k2] = make_float2((1.f - Vr) * sc, (-Vi) * sc);
}

// ---------------- GEMM 1: T1[k][j] = sum_n F[k][n] * xwrap[n][j], k=0..66 ----------------
__global__ void k_g1(const float* __restrict__ x) {
    __shared__ float2 As[34][33];
    __shared__ float  Bs[33][48];
    int img = blockIdx.z;
    int rowBase = blockIdx.y * 34, colBase = blockIdx.x * 44;
    int tx = threadIdx.x, ty = threadIdx.y, tid = ty * 11 + tx;
    const float* xb = x + img * 16384;
    float ar[2][4] = {{0}}, ai[2][4] = {{0}};
    for (int k0 = 0; k0 < NN; k0 += 33) {
        for (int i = tid; i < 34 * 33; i += 187) {
            int ml = i / 33, kk = i - ml * 33;
            int r = rowBase + ml;
            As[ml][kk] = (r < NH) ? g_F[r * NN + k0 + kk] : make_float2(0.f, 0.f);
        }
        for (int i = tid; i < 33 * 44; i += 187) {
            int kk = i / 44, nl = i - kk * 44;
            int r = k0 + kk, cc = colBase + nl;
            Bs[kk][nl] = xb[(((r + 126) & 127) << 7) + ((cc + 126) & 127)];
        }
        __syncthreads();
        #pragma unroll
        for (int kk = 0; kk < 33; kk++) {
            float2 a0 = As[ty][kk], a1 = As[ty + 17][kk];
            float4 b = *(const float4*)&Bs[kk][tx * 4];
            float bj[4] = {b.x, b.y, b.z, b.w};
            #pragma unroll
            for (int j = 0; j < 4; j++) {
                ar[0][j] += a0.x * bj[j]; ai[0][j] += a0.y * bj[j];
                ar[1][j] += a1.x * bj[j]; ai[1][j] += a1.y * bj[j];
            }
        }
        __syncthreads();
    }
    float2* Cm = g_T1 + img * NH * NN;
    #pragma unroll
    for (int i = 0; i < 2; i++) {
        int r = rowBase + ty + i * 17; if (r >= NH) continue;
        float4* p = (float4*)&Cm[r * NN + colBase + tx * 4];
        p[0] = make_float4(ar[i][0], ai[i][0], ar[i][1], ai[i][1]);
        p[1] = make_float4(ar[i][2], ai[i][2], ar[i][3], ai[i][3]);
    }
}

// ---------------- GEMM 2: X[k1][k2] = sum_j T1[k1][j]*F[k2][j]; fused *R ----------------
// F symmetric: F[k2][j] = F[j][k2] -> coalesced B loads
__global__ void k_g2() {
    __shared__ float2 As[34][33];
    __shared__ float2 Bs[33][46];
    int img = blockIdx.z;
    int rowBase = blockIdx.y * 34, colBase = blockIdx.x * 44;
    int tx = threadIdx.x, ty = threadIdx.y, tid = ty * 11 + tx;
    const float2* A = g_T1 + img * NH * NN;
    float ar[2][4] = {{0}}, ai[2][4] = {{0}};
    for (int k0 = 0; k0 < NN; k0 += 33) {
        for (int i = tid; i < 34 * 33; i += 187) {
            int ml = i / 33, kk = i - ml * 33;
            int r = rowBase + ml;
            As[ml][kk] = (r < NH) ? A[r * NN + k0 + kk] : make_float2(0.f, 0.f);
        }
        for (int i = tid; i < 33 * 44; i += 187) {
            int kk = i / 44, nl = i - kk * 44;
            Bs[kk][nl] = g_F[(k0 + kk) * NN + colBase + nl];
        }
        __syncthreads();
        #pragma unroll
        for (int kk = 0; kk < 33; kk++) {
            float2 a0 = As[ty][kk], a1 = As[ty + 17][kk];
            float4 p = *(const float4*)&Bs[kk][tx * 4];
            float4 q = *(const float4*)&Bs[kk][tx * 4 + 2];
            float2 b[4] = {{p.x, p.y}, {p.z, p.w}, {q.x, q.y}, {q.z, q.w}};
            #pragma unroll
            for (int j = 0; j < 4; j++) {
                ar[0][j] += a0.x * b[j].x - a0.y * b[j].y;
                ai[0][j] += a0.x * b[j].y + a0.y * b[j].x;
                ar[1][j] += a1.x * b[j].x - a1.y * b[j].y;
                ai[1][j] += a1.x * b[j].y + a1.y * b[j].x;
            }
        }
        __syncthreads();
    }
    int ch = img & 63;
    const float2* Rc = g_R + ch * NPIX;
    float2* Ys = g_Y + img * NH * NN;
    #pragma unroll
    for (int i = 0; i < 2; i++) {
        int r = rowBase + ty + i * 17; if (r >= NH) continue;
        const float4* rp = (const float4*)&Rc[r * NN + colBase + tx * 4];
        float4 r0 = rp[0], r1 = rp[1];
        float2 rr[4] = {{r0.x, r0.y}, {r0.z, r0.w}, {r1.x, r1.y}, {r1.z, r1.w}};
        float4 o0, o1;
        o0.x = ar[i][0] * rr[0].x - ai[i][0] * rr[0].y;
        o0.y = ar[i][0] * rr[0].y + ai[i][0] * rr[0].x;
        o0.z = ar[i][1] * rr[1].x - ai[i][1] * rr[1].y;
        o0.w = ar[i][1] * rr[1].y + ai[i][1] * rr[1].x;
        o1.x = ar[i][2] * rr[2].x - ai[i][2] * rr[2].y;
        o1.y = ar[i][2] * rr[2].y + ai[i][2] * rr[2].x;
        o1.z = ar[i][3] * rr[3].x - ai[i][3] * rr[3].y;
        o1.w = ar[i][3] * rr[3].y + ai[i][3] * rr[3].x;
        float4* p = (float4*)&Ys[r * NN + colBase + tx * 4];
        p[0] = o0; p[1] = o1;
    }
}

// ---------------- GEMM 3: T2'[k1][m2] = sum_k2 Y[k1][k2] * e^{+2pi i k2 m2/N} ----------------
// planar store: g_T2f row 2k1 = re, 2k1+1 = im; padded row k1=67 stores zeros
__global__ void k_g3() {
    __shared__ float2 As[34][33];
    __shared__ float2 Bs[33][46];
    int img = blockIdx.z;
    int rowBase = blockIdx.y * 34, colBase = blockIdx.x * 44;
    int tx = threadIdx.x, ty = threadIdx.y, tid = ty * 11 + tx;
    const float2* A = g_Y + img * NH * NN;
    float ar[2][4] = {{0}}, ai[2][4] = {{0}};
    for (int k0 = 0; k0 < NN; k0 += 33) {
        for (int i = tid; i < 34 * 33; i += 187) {
            int ml = i / 33, kk = i - ml * 33;
            int r = rowBase + ml;
            As[ml][kk] = (r < NH) ? A[r * NN + k0 + kk] : make_float2(0.f, 0.f);
        }
        for (int i = tid; i < 33 * 44; i += 187) {
            int kk = i / 44, nl = i - kk * 44;
            Bs[kk][nl] = g_Fi[(k0 + kk) * NN + colBase + nl];
        }
        __syncthreads();
        #pragma unroll
        for (int kk = 0; kk < 33; kk++) {
            float2 a0 = As[ty][kk], a1 = As[ty + 17][kk];
            float4 p = *(const float4*)&Bs[kk][tx * 4];
            float4 q = *(const float4*)&Bs[kk][tx * 4 + 2];
            float2 b[4] = {{p.x, p.y}, {p.z, p.w}, {q.x, q.y}, {q.z, q.w}};
            #pragma unroll
            for (int j = 0; j < 4; j++) {
                ar[0][j] += a0.x * b[j].x - a0.y * b[j].y;
                ai[0][j] += a0.x * b[j].y + a0.y * b[j].x;
                ar[1][j] += a1.x * b[j].x - a1.y * b[j].y;
                ai[1][j] += a1.x * b[j].y + a1.y * b[j].x;
            }
        }
        __syncthreads();
    }
    float* Cm = g_T2f + img * KT2 * NN;
    #pragma unroll
    for (int i = 0; i < 2; i++) {
        int k1 = rowBase + ty + i * 17;   // 0..67; row 67 holds zeros (padded A)
        *(float4*)&Cm[(2 * k1) * NN + colBase + tx * 4] =
            make_float4(ar[i][0], ar[i][1], ar[i][2], ar[i][3]);
        *(float4*)&Cm[(2 * k1 + 1) * NN + colBase + tx * 4] =
            make_float4(ai[i][0], ai[i][1], ai[i][2], ai[i][3]);
    }
}

// ---------------- GEMM 4 (real): z[m1][m2] = sum_t G4A[m1][t] * T2f[t][m2], K=136 ----------------
__global__ void k_g4() {
    __shared__ float As[34][34];
    __shared__ float Bs[34][48];
    int img = blockIdx.z;
    int rowBase = blockIdx.y * 34, colBase = blockIdx.x * 44;
    int tx = threadIdx.x, ty = threadIdx.y, tid = ty * 11 + tx;
    const float* B = g_T2f + img * KT2 * NN;
    float acc[2][4] = {{0}};
    for (int k0 = 0; k0 < KT2; k0 += 34) {
        for (int i = tid; i < 34 * 34; i += 187) {
            int ml = i / 34, kk = i - ml * 34;
            int r = rowBase + ml;
            As[ml][kk] = (r < NN) ? g_G4A[r * KT2 + k0 + kk] : 0.f;
        }
        for (int i = tid; i < 34 * 44; i += 187) {
            int kk = i / 44, nl = i - kk * 44;
            Bs[kk][nl] = B[(k0 + kk) * NN + colBase + nl];
        }
        __syncthreads();
        #pragma unroll
        for (int kk = 0; kk < 34; kk++) {
            float a0 = As[ty][kk], a1 = As[ty + 17][kk];
            float4 b = *(const float4*)&Bs[kk][tx * 4];
            float bj[4] = {b.x, b.y, b.z, b.w};
            #pragma unroll
            for (int j = 0; j < 4; j++) {
                acc[0][j] += a0 * bj[j];
                acc[1][j] += a1 * bj[j];
            }
        }
        __syncthreads();
    }
    float* Cm = g_z + img * NPIX;
    #pragma unroll
    for (int i = 0; i < 2; i++) {
        int r = rowBase + ty + i * 17; if (r >= NN) continue;
        *(float4*)&Cm[r * NN + colBase + tx * 4] =
            make_float4(acc[i][0], acc[i][1], acc[i][2], acc[i][3]);
    }
}

// ---------------- final: nearest-up + 3x3 polyphase gather + crop + exact GELU ----------------
__global__ void k_final(const float* __restrict__ x, const float* __restrict__ wt,
                        float* __restrict__ out) {
    int i = blockIdx.x * blockDim.x + threadIdx.x;
    int q = i & 255;
    int p = (i >> 8) & 255;
    int img = i >> 16;
    int c = img & 63;
    int n1 = p + 4, n2 = q + 4;
    int m1 = n1 >> 1, m2 = n2 >> 1;
    int a1 = n1 & 1, a2 = n2 & 1;
    const float* z = g_z + img * NPIX;
    const float* w = wt + c * 9;
    float z00 = z[m1 * NN + m2];
    float acc;
    if (a1 == 0) {
        if (a2 == 0) acc = w[4] * z00;
        else         acc = w[3] * z00 + w[5] * z[m1 * NN + m2 + 1];
    } else {
        if (a2 == 0) acc = w[1] * z00 + w[7] * z[(m1 + 1) * NN + m2];
        else         acc = w[0] * z00 + w[2] * z[m1 * NN + m2 + 1]
                         + w[6] * z[(m1 + 1) * NN + m2] + w[8] * z[(m1 + 1) * NN + m2 + 1];
    }
    float v = x[(img * 128 + ((m1 + 126) & 127)) * 128 + ((m2 + 126) & 127)] + acc;
    out[i] = 0.5f * v * (1.0f + erff(v * 0.70710678118654752f));
}

// ---------------- launch ----------------
extern "C" void kernel_launch(void* const* d_in, const int* in_sizes, int n_in,
                              void* d_out, int out_size) {
    const float* x    = (const float*)d_in[0];   // (4,64,128,128)
    const float* w    = (const float*)d_in[1];   // (1,64,3,3)
    const float* bias = (const float*)d_in[2];   // (1,64,1,1)
    float* out = (float*)d_out;                  // (4,64,256,256)

    k_buildF<<<(NPIX + 255) / 256, 256>>>();
    k_buildG4A<<<(NN * KT2 + 255) / 256, 256>>>();
    k_buildTw<<<(MM + 127) / 128, 128>>>();
    k_buildWB<<<dim3((MM + 127) / 128, NCH), 128>>>(w);
    k_buildR<<<dim3(NN, NCH), NN>>>(bias);

    dim3 blk(11, 17);
    k_g1<<<dim3(3, 2, NIMG), blk>>>(x);   // 67 rows (2x34), 132 cols (3x44)
    k_g2<<<dim3(3, 2, NIMG), blk>>>();    // 67 rows, 132 cols, fused R
    k_g3<<<dim3(3, 2, NIMG), blk>>>();    // 67(+1) rows k1, 132 cols m2, planar store
    k_g4<<<dim3(3, 4, NIMG), blk>>>();    // 132 rows m1 (4x34), 132 cols, K=136 real

    k_final<<<(4 * 64 * 256 * 256) / 256, 256>>>(x, w, out);
}

// round 8
// speedup vs baseline: 2.2259x; 1.1081x over previous
#include <cuda_runtime.h>
#include <math.h>

#define NN 132
#define MM 264
#define NPIX (NN*NN)      // 17424
#define NIMG 256          // 4*64
#define NCH  64
#define NH   67           // Hermitian half rows
#define KT2  136          // planar re/im rows for T2', padded from 134
#define PIF 3.14159265358979323846f

typedef unsigned long long u64;

// ---------------- packed f32x2 helpers ----------------
__device__ __forceinline__ u64 pk(float x, float y) {
    u64 r; asm("mov.b64 %0, {%1,%2};" : "=l"(r) : "f"(x), "f"(y)); return r;
}
__device__ __forceinline__ float2 upk(u64 v) {
    float2 r; asm("mov.b64 {%0,%1}, %2;" : "=f"(r.x), "=f"(r.y) : "l"(v)); return r;
}
#define FMA2(acc, a, b) asm("fma.rn.f32x2 %0, %1, %2, %0;" : "+l"(acc) : "l"(a), "l"(b))

// ---------------- static scratch (allocation-free) ----------------
__device__ float2     g_F[NPIX];          // e^{-2pi i kn/132} (symmetric) — g1 A operand
__device__ ulonglong2 g_Frot[NPIX];       // {(br,bi),(-bi,br)} of g_F       — g2 B operand
__device__ ulonglong2 g_Firot[NPIX];      // same for e^{+2pi i kn/132}      — g3 B operand
__device__ u64        g_G4Apk[KT2*68];    // [t][p] = pk(G4A[2p][t],G4A[2p+1][t]) — g4 A
__device__ float2     g_R[NCH*NPIX];      // per-channel filter
__device__ float2     g_E1[MM*3];
__device__ float2     g_U1[MM];
__device__ float2     g_WB[NCH*MM*3];
__device__ float2     g_T1[NIMG*NH*NN];   // F*xwrap, rows 0..66
__device__ float2     g_Y[NIMG*NH*NN];    // (T1*F)*R, rows 0..66
__device__ float      g_T2f[NIMG*KT2*NN]; // planar: row 2k1 = re, 2k1+1 = im
__device__ float      g_z[NIMG*NPIX];     // real spatial result

// ---------------- builders ----------------
__global__ void k_buildF() {
    int i = blockIdx.x * blockDim.x + threadIdx.x;
    if (i >= NPIX) return;
    int k = i / NN, n = i % NN;
    int t = (k * n) % NN;
    float ang = (2.0f * PIF / NN) * (float)t;
    float s, c; sincosf(ang, &s, &c);
    g_F[i] = make_float2(c, -s);
    ulonglong2 fr; fr.x = pk(c, -s); fr.y = pk(s, c);   // b=(c,-s), rot=(-bi,br)=(s,c)
    g_Frot[i] = fr;
    ulonglong2 fi; fi.x = pk(c, s);  fi.y = pk(-s, c);  // b=(c,s),  rot=(-s,c)
    g_Firot[i] = fi;
}

__device__ __forceinline__ float g4a_val(int m1, int t) {
    if (m1 >= NN) return 0.f;
    int k1 = t >> 1;
    if (k1 > 66) return 0.f;
    float g = (k1 == 0 || k1 == 66) ? 1.0f : 2.0f;
    int tm = (k1 * m1) % NN;
    float ang = (2.0f * PIF / NN) * (float)tm;
    float s, c; sincosf(ang, &s, &c);
    return (t & 1) ? (-g * s) : (g * c);
}

__global__ void k_buildG4A() {
    int i = blockIdx.x * blockDim.x + threadIdx.x;
    if (i >= KT2 * 68) return;
    int t = i / 68, p = i % 68;
    g_G4Apk[i] = pk(g4a_val(2 * p, t), g4a_val(2 * p + 1, t));
}

__global__ void k_buildTw() {
    int kk = blockIdx.x * blockDim.x + threadIdx.x;
    if (kk >= MM) return;
    #pragma unroll
    for (int u = 0; u < 3; u++) {
        int t = kk * (u - 1);
        t %= MM; if (t < 0) t += MM;
        float ang = (2.0f * PIF / MM) * (float)t;
        float s, c; sincosf(ang, &s, &c);
        g_E1[kk * 3 + u] = make_float2(c, -s);
    }
    float ang = (2.0f * PIF / MM) * (float)kk;
    float s, c; sincosf(ang, &s, &c);
    g_U1[kk] = make_float2(1.f + c, -s);
}

__global__ void k_buildWB(const float* __restrict__ w) {
    int kk = blockIdx.x * blockDim.x + threadIdx.x;
    int c = blockIdx.y;
    if (kk >= MM) return;
    float2 e0 = g_E1[kk * 3 + 0], e1 = g_E1[kk * 3 + 1], e2 = g_E1[kk * 3 + 2];
    #pragma unroll
    for (int u = 0; u < 3; u++) {
        float w0 = w[c * 9 + u * 3 + 0];
        float w1 = w[c * 9 + u * 3 + 1];
        float w2 = w[c * 9 + u * 3 + 2];
        g_WB[(c * MM + kk) * 3 + u] =
            make_float2(w0 * e0.x + w1 * e1.x + w2 * e2.x,
                        w0 * e0.y + w1 * e1.y + w2 * e2.y);
    }
}

__global__ void k_buildR(const float* __restrict__ bias) {
    int k2 = threadIdx.x, k1 = blockIdx.x, c = blockIdx.y;
    float alpha = 1.0f / (1.0f + expf(9.0f - bias[c])) + 1e-5f;
    float Vr = 0.f, Vi = 0.f, W2 = 0.f;
    #pragma unroll
    for (int r1 = 0; r1 < 2; r1++)
    #pragma unroll
    for (int r2 = 0; r2 < 2; r2++) {
        int kk1 = k1 + r1 * NN, kk2 = k2 + r2 * NN;
        float fr = 0.f, fi = 0.f;
        #pragma unroll
        for (int u = 0; u < 3; u++) {
            float2 e = g_E1[kk1 * 3 + u];
            float2 b = g_WB[(c * MM + kk2) * 3 + u];
            fr += e.x * b.x - e.y * b.y;
            fi += e.x * b.y + e.y * b.x;
        }
        float2 u1 = g_U1[kk1], u2 = g_U1[kk2];
        float Ur = u1.x * u2.x - u1.y * u2.y;
        float Ui = u1.x * u2.y + u1.y * u2.x;
        Vr += fr * Ur - fi * Ui;
        Vi += fr * Ui + fi * Ur;
        W2 += fr * fr + fi * fi;
    }
    Vr *= 0.25f; Vi *= 0.25f; W2 *= 0.25f;
    float sc = 1.0f / (W2 + alpha) * (1.0f / (float)NPIX);
    g_R[(c * NN + k1) * NN + k2] = make_float2((1.f - Vr) * sc, (-Vi) * sc);
}

// ---------------- GEMM 1: T1[k][j] = sum_n F[k][n]*xwrap[n][j], k=0..66 ----------------
// block (11,17); tile 68 rows x 44 cols; K chunk 33; microtile 4x4
// acc(ar,ai) += (ax,ay) * (b,b)   -> 1 FFMA2 per complex-real MAC
__global__ void k_g1(const float* __restrict__ x) {
    __shared__ u64 As[68][33];     // natural complex F (re,im) packed
    __shared__ u64 Bs[33][44];     // (b,b) duped; slot (j*11 + tx)
    int img = blockIdx.z;
    int colBase = blockIdx.x * 44;
    int tx = threadIdx.x, ty = threadIdx.y, tid = ty * 11 + tx;
    const float* xb = x + img * 16384;
    u64 acc[4][4];
    #pragma unroll
    for (int i = 0; i < 4; i++)
        #pragma unroll
        for (int j = 0; j < 4; j++) acc[i][j] = 0ULL;

    for (int k0 = 0; k0 < NN; k0 += 33) {
        for (int i = tid; i < 68 * 33; i += 187) {
            int r = i / 33, kk = i - r * 33;
            As[r][kk] = (r < NH) ? ((const u64*)g_F)[r * NN + k0 + kk] : 0ULL;
        }
        for (int i = tid; i < 33 * 44; i += 187) {
            int kk = i / 44, nl = i - kk * 44;
            int rr = k0 + kk, cc = colBase + nl;
            float v = xb[(((rr + 126) & 127) << 7) + ((cc + 126) & 127)];
            Bs[kk][(nl & 3) * 11 + (nl >> 2)] = pk(v, v);
        }
        __syncthreads();
        #pragma unroll
        for (int kk = 0; kk < 33; kk++) {
            u64 a[4], b[4];
            #pragma unroll
            for (int i = 0; i < 4; i++) a[i] = As[ty + 17 * i][kk];
            #pragma unroll
            for (int j = 0; j < 4; j++) b[j] = Bs[kk][j * 11 + tx];
            #pragma unroll
            for (int i = 0; i < 4; i++)
                #pragma unroll
                for (int j = 0; j < 4; j++) FMA2(acc[i][j], a[i], b[j]);
        }
        __syncthreads();
    }
    float2* Cm = g_T1 + img * NH * NN;
    #pragma unroll
    for (int i = 0; i < 4; i++) {
        int r = ty + 17 * i; if (r >= NH) continue;
        float2 v0 = upk(acc[i][0]), v1 = upk(acc[i][1]);
        float2 v2 = upk(acc[i][2]), v3 = upk(acc[i][3]);
        float4* p = (float4*)&Cm[r * NN + colBase + tx * 4];
        p[0] = make_float4(v0.x, v0.y, v1.x, v1.y);
        p[1] = make_float4(v2.x, v2.y, v3.x, v3.y);
    }
}

// ---------------- GEMM 2: X[k1][k2] = sum_j T1[k1][j]*F[k2][j]; fused *R ----------------
// acc += (ax,ax)*(br,bi); acc += (ay,ay)*(-bi,br)  -> 2 FFMA2 per complex MAC
__global__ void k_g2() {
    __shared__ ulonglong2 As[68][33];  // {(ax,ax),(ay,ay)}
    __shared__ ulonglong2 Bs[33][44];  // {(br,bi),(-bi,br)}; slot (j*11+tx)
    int img = blockIdx.z;
    int colBase = blockIdx.x * 44;
    int tx = threadIdx.x, ty = threadIdx.y, tid = ty * 11 + tx;
    const float2* A = g_T1 + img * NH * NN;
    u64 acc[4][4];
    #pragma unroll
    for (int i = 0; i < 4; i++)
        #pragma unroll
        for (int j = 0; j < 4; j++) acc[i][j] = 0ULL;

    for (int k0 = 0; k0 < NN; k0 += 33) {
        for (int i = tid; i < 68 * 33; i += 187) {
            int r = i / 33, kk = i - r * 33;
            ulonglong2 av;
            if (r < NH) {
                float2 v = A[r * NN + k0 + kk];
                av.x = pk(v.x, v.x); av.y = pk(v.y, v.y);
            } else { av.x = 0ULL; av.y = 0ULL; }
            As[r][kk] = av;
        }
        for (int i = tid; i < 33 * 44; i += 187) {
            int kk = i / 44, nl = i - kk * 44;
            Bs[kk][(nl & 3) * 11 + (nl >> 2)] = g_Frot[(k0 + kk) * NN + colBase + nl];
        }
        __syncthreads();
        #pragma unroll
        for (int kk = 0; kk < 33; kk++) {
            ulonglong2 a[4], b[4];
            #pragma unroll
            for (int i = 0; i < 4; i++) a[i] = As[ty + 17 * i][kk];
            #pragma unroll
            for (int j = 0; j < 4; j++) b[j] = Bs[kk][j * 11 + tx];
            #pragma unroll
            for (int i = 0; i < 4; i++)
                #pragma unroll
                for (int j = 0; j < 4; j++) {
                    FMA2(acc[i][j], a[i].x, b[j].x);
                    FMA2(acc[i][j], a[i].y, b[j].y);
                }
        }
        __syncthreads();
    }
    int ch = img & 63;
    const float2* Rc = g_R + ch * NPIX;
    float2* Ys = g_Y + img * NH * NN;
    #pragma unroll
    for (int i = 0; i < 4; i++) {
        int r = ty + 17 * i; if (r >= NH) continue;
        const float4* rp = (const float4*)&Rc[r * NN + colBase + tx * 4];
        float4 r0 = rp[0], r1 = rp[1];
        float2 v0 = upk(acc[i][0]), v1 = upk(acc[i][1]);
        float2 v2 = upk(acc[i][2]), v3 = upk(acc[i][3]);
        float4 o0, o1;
        o0.x = v0.x * r0.x - v0.y * r0.y;  o0.y = v0.x * r0.y + v0.y * r0.x;
        o0.z = v1.x * r0.z - v1.y * r0.w;  o0.w = v1.x * r0.w + v1.y * r0.z;
        o1.x = v2.x * r1.x - v2.y * r1.y;  o1.y = v2.x * r1.y + v2.y * r1.x;
        o1.z = v3.x * r1.z - v3.y * r1.w;  o1.w = v3.x * r1.w + v3.y * r1.z;
        float4* p = (float4*)&Ys[r * NN + colBase + tx * 4];
        p[0] = o0; p[1] = o1;
    }
}

// ---------------- GEMM 3: T2'[k1][m2] = sum_k2 Y[k1][k2]*Fi[k2][m2]; planar store ----------------
__global__ void k_g3() {
    __shared__ ulonglong2 As[68][33];
    __shared__ ulonglong2 Bs[33][44];
    int img = blockIdx.z;
    int colBase = blockIdx.x * 44;
    int tx = threadIdx.x, ty = threadIdx.y, tid = ty * 11 + tx;
    const float2* A = g_Y + img * NH * NN;
    u64 acc[4][4];
    #pragma unroll
    for (int i = 0; i < 4; i++)
        #pragma unroll
        for (int j = 0; j < 4; j++) acc[i][j] = 0ULL;

    for (int k0 = 0; k0 < NN; k0 += 33) {
        for (int i = tid; i < 68 * 33; i += 187) {
            int r = i / 33, kk = i - r * 33;
            ulonglong2 av;
            if (r < NH) {
                float2 v = A[r * NN + k0 + kk];
                av.x = pk(v.x, v.x); av.y = pk(v.y, v.y);
            } else { av.x = 0ULL; av.y = 0ULL; }
            As[r][kk] = av;
        }
        for (int i = tid; i < 33 * 44; i += 187) {
            int kk = i / 44, nl = i - kk * 44;
            Bs[kk][(nl & 3) * 11 + (nl >> 2)] = g_Firot[(k0 + kk) * NN + colBase + nl];
        }
        __syncthreads();
        #pragma unroll
        for (int kk = 0; kk < 33; kk++) {
            ulonglong2 a[4], b[4];
            #pragma unroll
            for (int i = 0; i < 4; i++) a[i] = As[ty + 17 * i][kk];
            #pragma unroll
            for (int j = 0; j < 4; j++) b[j] = Bs[kk][j * 11 + tx];
            #pragma unroll
            for (int i = 0; i < 4; i++)
                #pragma unroll
                for (int j = 0; j < 4; j++) {
                    FMA2(acc[i][j], a[i].x, b[j].x);
                    FMA2(acc[i][j], a[i].y, b[j].y);
                }
        }
        __syncthreads();
    }
    float* Cm = g_T2f + img * KT2 * NN;
    #pragma unroll
    for (int i = 0; i < 4; i++) {
        int k1 = ty + 17 * i;   // 0..67; row 67 = zeros (padded A)
        float2 v0 = upk(acc[i][0]), v1 = upk(acc[i][1]);
        float2 v2 = upk(acc[i][2]), v3 = upk(acc[i][3]);
        *(float4*)&Cm[(2 * k1) * NN + colBase + tx * 4] =
            make_float4(v0.x, v1.x, v2.x, v3.x);
        *(float4*)&Cm[(2 * k1 + 1) * NN + colBase + tx * 4] =
            make_float4(v0.y, v1.y, v2.y, v3.y);
    }
}

// ---------------- GEMM 4 (real): z[m1][m2] = sum_t G4A[m1][t]*T2f[t][m2], K=136 ----------------
// row-pair packing: acc(z[2p][c], z[2p+1][c]) += (A[2p][t],A[2p+1][t]) * (b,b)
// block (11,17); tile 136 rows x 44 cols; thread rows 8ty..8ty+7 (p = 4ty+q), cols tx*4..+3
__global__ void k_g4() {
    __shared__ u64 As[34][68];   // pair-packed A; [kk][p]
    __shared__ u64 Bs[34][44];   // (b,b) duped; slot (j*11+tx)
    int img = blockIdx.z;
    int colBase = blockIdx.x * 44;
    int tx = threadIdx.x, ty = threadIdx.y, tid = ty * 11 + tx;
    const float* B = g_T2f + img * KT2 * NN;
    u64 acc[4][4];
    #pragma unroll
    for (int q = 0; q < 4; q++)
        #pragma unroll
        for (int j = 0; j < 4; j++) acc[q][j] = 0ULL;

    for (int k0 = 0; k0 < KT2; k0 += 34) {
        for (int i = tid; i < 34 * 68; i += 187) {
            int kk = i / 68, p = i - kk * 68;
            As[kk][p] = g_G4Apk[(k0 + kk) * 68 + p];
        }
        for (int i = tid; i < 34 * 44; i += 187) {
            int kk = i / 44, nl = i - kk * 44;
            float v = B[(k0 + kk) * NN + colBase + nl];
            Bs[kk][(nl & 3) * 11 + (nl >> 2)] = pk(v, v);
        }
        __syncthreads();
        #pragma unroll
        for (int kk = 0; kk < 34; kk++) {
            u64 a[4], b[4];
            ulonglong2 au = *(const ulonglong2*)&As[kk][ty * 4];
            ulonglong2 av = *(const ulonglong2*)&As[kk][ty * 4 + 2];
            a[0] = au.x; a[1] = au.y; a[2] = av.x; a[3] = av.y;
            #pragma unroll
            for (int j = 0; j < 4; j++) b[j] = Bs[kk][j * 11 + tx];
            #pragma unroll
            for (int q = 0; q < 4; q++)
                #pragma unroll
                for (int j = 0; j < 4; j++) FMA2(acc[q][j], a[q], b[j]);
        }
        __syncthreads();
    }
    float* Cm = g_z + img * NPIX;
    #pragma unroll
    for (int q = 0; q < 4; q++) {
        int p = ty * 4 + q;
        int r0 = 2 * p;
        if (r0 + 1 >= NN) continue;   // rows 132+ are pad
        float2 v0 = upk(acc[q][0]), v1 = upk(acc[q][1]);
        float2 v2 = upk(acc[q][2]), v3 = upk(acc[q][3]);
        *(float4*)&Cm[r0 * NN + colBase + tx * 4] =
            make_float4(v0.x, v1.x, v2.x, v3.x);
        *(float4*)&Cm[(r0 + 1) * NN + colBase + tx * 4] =
            make_float4(v0.y, v1.y, v2.y, v3.y);
    }
}

// ---------------- final: nearest-up + 3x3 polyphase gather + crop + exact GELU ----------------
__global__ void k_final(const float* __restrict__ x, const float* __restrict__ wt,
                        float* __restrict__ out) {
    int i = blockIdx.x * blockDim.x + threadIdx.x;
    int q = i & 255;
    int p = (i >> 8) & 255;
    int img = i >> 16;
    int c = img & 63;
    int n1 = p + 4, n2 = q + 4;
    int m1 = n1 >> 1, m2 = n2 >> 1;
    int a1 = n1 & 1, a2 = n2 & 1;
    const float* z = g_z + img * NPIX;
    const float* w = wt + c * 9;
    float z00 = z[m1 * NN + m2];
    float acc;
    if (a1 == 0) {
        if (a2 == 0) acc = w[4] * z00;
        else         acc = w[3] * z00 + w[5] * z[m1 * NN + m2 + 1];
    } else {
        if (a2 == 0) acc = w[1] * z00 + w[7] * z[(m1 + 1) * NN + m2];
        else         acc = w[0] * z00 + w[2] * z[m1 * NN + m2 + 1]
                         + w[6] * z[(m1 + 1) * NN + m2] + w[8] * z[(m1 + 1) * NN + m2 + 1];
    }
    float v = x[(img * 128 + ((m1 + 126) & 127)) * 128 + ((m2 + 126) & 127)] + acc;
    out[i] = 0.5f * v * (1.0f + erff(v * 0.70710678118654752f));
}

// ---------------- launch ----------------
extern "C" void kernel_launch(void* const* d_in, const int* in_sizes, int n_in,
                              void* d_out, int out_size) {
    const float* x    = (const float*)d_in[0];   // (4,64,128,128)
    const float* w    = (const float*)d_in[1];   // (1,64,3,3)
    const float* bias = (const float*)d_in[2];   // (1,64,1,1)
    float* out = (float*)d_out;                  // (4,64,256,256)

    k_buildF<<<(NPIX + 255) / 256, 256>>>();
    k_buildG4A<<<(KT2 * 68 + 255) / 256, 256>>>();
    k_buildTw<<<(MM + 127) / 128, 128>>>();
    k_buildWB<<<dim3((MM + 127) / 128, NCH), 128>>>(w);
    k_buildR<<<dim3(NN, NCH), NN>>>(bias);

    dim3 blk(11, 17);
    k_g1<<<dim3(3, 1, NIMG), blk>>>(x);   // 68-row tile (covers 67), 3x44 cols
    k_g2<<<dim3(3, 1, NIMG), blk>>>();
    k_g3<<<dim3(3, 1, NIMG), blk>>>();
    k_g4<<<dim3(3, 1, NIMG), blk>>>();    // 136-row tile (covers 132), 3x44 cols

    k_final<<<(4 * 64 * 256 * 256) / 256, 256>>>(x, w, out);
}

// round 9
// speedup vs baseline: 2.5888x; 1.1630x over previous
#include <cuda_runtime.h>
#include <math.h>

#define NN 132
#define MM 264
#define NPIX (NN*NN)
#define NIMG 256
#define NCH  64
#define PIF 3.14159265358979323846f

typedef unsigned long long u64;

__device__ __forceinline__ u64 pk(float x, float y) {
    u64 r; asm("mov.b64 %0, {%1,%2};" : "=l"(r) : "f"(x), "f"(y)); return r;
}
__device__ __forceinline__ float2 upk(u64 v) {
    float2 r; asm("mov.b64 {%0,%1}, %2;" : "=f"(r.x), "=f"(r.y) : "l"(v)); return r;
}
#define FMA2(acc, a, b) asm("fma.rn.f32x2 %0, %1, %2, %0;" : "+l"(acc) : "l"(a), "l"(b))

// ---------------- static scratch ----------------
__device__ ulonglong2 g_CSd[68*68];        // {pk(c,c), pk(s,s)}, c=cos(2pi kn/132); zero at k==67||n==67
__device__ ulonglong2 g_Bd3[68*132];       // [k2][m2]: {pk(c,c), pk(-s,s)}; zero row k2==67
__device__ u64        g_G4[68*68];         // [m1][k1]: pk(g*c, -g*s); g={1 at k1 0,66; 2 else; 0 at 67}
__device__ u64        g_xfP[NIMG*4*68*34]; // folded x, j-pair packed: [img][arr][n][jp]
__device__ ulonglong2 g_P[NIMG*68*68];     // [img][k][j]: {pk(P1,-P3'), pk(-P4',P2)}
__device__ ulonglong2 g_SYDY[NIMG*68*68];  // [img][k1][k2]: {pk(sYr,sYi), pk(dYi,dYr)}
__device__ u64        g_T2pk[NIMG*68*132]; // [img][k1][m2]: pk(T2re,T2im)
__device__ float      g_z[NIMG*NPIX];
__device__ float2     g_R[NCH*NPIX];
__device__ float2     g_E1[MM*3];
__device__ float2     g_U1[MM];
__device__ float2     g_WB[NCH*MM*3];

// ---------------- builders ----------------
__global__ void k_buildCSd() {
    int i = blockIdx.x * blockDim.x + threadIdx.x;
    if (i >= 68 * 68) return;
    int k = i / 68, n = i % 68;
    ulonglong2 v;
    if (k == 67 || n == 67) { v.x = 0ULL; v.y = 0ULL; }
    else {
        int t = (k * n) % NN;
        float ang = (2.0f * PIF / NN) * (float)t;
        float s, c; sincosf(ang, &s, &c);
        v.x = pk(c, c); v.y = pk(s, s);
    }
    g_CSd[i] = v;
}

__global__ void k_buildBd3() {
    int i = blockIdx.x * blockDim.x + threadIdx.x;
    if (i >= 68 * 132) return;
    int k2 = i / 132, m2 = i % 132;
    ulonglong2 v;
    if (k2 == 67) { v.x = 0ULL; v.y = 0ULL; }
    else {
        int t = (k2 * m2) % NN;
        float ang = (2.0f * PIF / NN) * (float)t;
        float s, c; sincosf(ang, &s, &c);
        v.x = pk(c, c); v.y = pk(-s, s);
    }
    g_Bd3[i] = v;
}

__global__ void k_buildG4() {
    int i = blockIdx.x * blockDim.x + threadIdx.x;
    if (i >= 68 * 68) return;
    int m1 = i / 68, k1 = i % 68;
    if (k1 == 67) { g_G4[i] = 0ULL; return; }
    float g = (k1 == 0 || k1 == 66) ? 1.0f : 2.0f;
    int t = (k1 * m1) % NN;
    float ang = (2.0f * PIF / NN) * (float)t;
    float s, c; sincosf(ang, &s, &c);
    g_G4[i] = pk(g * c, -g * s);
}

__global__ void k_buildTw() {
    int kk = blockIdx.x * blockDim.x + threadIdx.x;
    if (kk >= MM) return;
    #pragma unroll
    for (int u = 0; u < 3; u++) {
        int t = kk * (u - 1);
        t %= MM; if (t < 0) t += MM;
        float ang = (2.0f * PIF / MM) * (float)t;
        float s, c; sincosf(ang, &s, &c);
        g_E1[kk * 3 + u] = make_float2(c, -s);
    }
    float ang = (2.0f * PIF / MM) * (float)kk;
    float s, c; sincosf(ang, &s, &c);
    g_U1[kk] = make_float2(1.f + c, -s);
}

__global__ void k_buildWB(const float* __restrict__ w) {
    int kk = blockIdx.x * blockDim.x + threadIdx.x;
    int c = blockIdx.y;
    if (kk >= MM) return;
    float2 e0 = g_E1[kk * 3 + 0], e1 = g_E1[kk * 3 + 1], e2 = g_E1[kk * 3 + 2];
    #pragma unroll
    for (int u = 0; u < 3; u++) {
        float w0 = w[c * 9 + u * 3 + 0];
        float w1 = w[c * 9 + u * 3 + 1];
        float w2 = w[c * 9 + u * 3 + 2];
        g_WB[(c * MM + kk) * 3 + u] =
            make_float2(w0 * e0.x + w1 * e1.x + w2 * e2.x,
                        w0 * e0.y + w1 * e1.y + w2 * e2.y);
    }
}

__global__ void k_buildR(const float* __restrict__ bias) {
    int k2 = threadIdx.x, k1 = blockIdx.x, c = blockIdx.y;   // k1 in [0,67)
    float alpha = 1.0f / (1.0f + expf(9.0f - bias[c])) + 1e-5f;
    float Vr = 0.f, Vi = 0.f, W2 = 0.f;
    #pragma unroll
    for (int r1 = 0; r1 < 2; r1++)
    #pragma unroll
    for (int r2 = 0; r2 < 2; r2++) {
        int kk1 = k1 + r1 * NN, kk2 = k2 + r2 * NN;
        float fr = 0.f, fi = 0.f;
        #pragma unroll
        for (int u = 0; u < 3; u++) {
            float2 e = g_E1[kk1 * 3 + u];
            float2 b = g_WB[(c * MM + kk2) * 3 + u];
            fr += e.x * b.x - e.y * b.y;
            fi += e.x * b.y + e.y * b.x;
        }
        float2 u1 = g_U1[kk1], u2 = g_U1[kk2];
        float Ur = u1.x * u2.x - u1.y * u2.y;
        float Ui = u1.x * u2.y + u1.y * u2.x;
        Vr += fr * Ur - fi * Ui;
        Vi += fr * Ui + fi * Ur;
        W2 += fr * fr + fi * fi;
    }
    Vr *= 0.25f; Vi *= 0.25f; W2 *= 0.25f;
    float sc = 1.0f / (W2 + alpha) * (1.0f / (float)NPIX);
    g_R[(c * NN + k1) * NN + k2] = make_float2((1.f - Vr) * sc, (-Vi) * sc);
}

// ---------------- kA: quadrant fold of input ----------------
__global__ void kA(const float* __restrict__ x) {
    int idx = blockIdx.x * blockDim.x + threadIdx.x;
    if (idx >= NIMG * 68 * 34) return;
    int img = idx / (68 * 34);
    int rem = idx - img * 68 * 34;
    int n = rem / 34, jp = rem % 34;
    const float* xb = x + img * 16384;
    float vals[4][2];
    #pragma unroll
    for (int h = 0; h < 2; h++) {
        int jt = 2 * jp + h;
        float pp = 0.f, pm = 0.f, mp = 0.f, mm = 0.f;
        if (n < 67 && jt < 67) {
            int n2 = (NN - n) % NN, j2 = (NN - jt) % NN;
            bool nsel = (n != 0 && n != 66);
            bool jsel = (jt != 0 && jt != 66);
            #define XW(R,C) xb[((((R)+126)&127)<<7) + (((C)+126)&127)]
            float a  = XW(n, jt);
            float b  = nsel ? XW(n2, jt) : 0.f;
            float cc = jsel ? XW(n, j2) : 0.f;
            float d  = (nsel && jsel) ? XW(n2, j2) : 0.f;
            #undef XW
            pp = a + b + cc + d;
            pm = jsel ? (a + b - cc - d) : 0.f;
            mp = nsel ? (a - b + cc - d) : 0.f;
            mm = (nsel && jsel) ? (a - b - cc + d) : 0.f;
        }
        vals[0][h] = pp; vals[1][h] = pm; vals[2][h] = mp; vals[3][h] = mm;
    }
    #pragma unroll
    for (int a = 0; a < 4; a++)
        g_xfP[((img * 4 + a) * 68 + n) * 34 + jp] = pk(vals[a][0], vals[a][1]);
}

// ---------------- kB: four folded real GEMMs (P1,P2,P3',P4') ----------------
// block (17,17); grid (2, NIMG). rows k=ty+17i (68), jpair = blockIdx.x*17+tx
__global__ void kB() {
    __shared__ ulonglong2 As[68][34];
    __shared__ u64 Bs[4][34][18];
    int img = blockIdx.y;
    int jpBase = blockIdx.x * 17;
    int tx = threadIdx.x, ty = threadIdx.y, tid = ty * 17 + tx;
    u64 acc[4][4];
    #pragma unroll
    for (int a = 0; a < 4; a++)
        #pragma unroll
        for (int i = 0; i < 4; i++) acc[a][i] = 0ULL;

    for (int k0 = 0; k0 < 68; k0 += 34) {
        for (int i = tid; i < 68 * 34; i += 289) {
            int r = i / 34, n = i - r * 34;
            As[r][n] = g_CSd[r * 68 + k0 + n];
        }
        for (int i = tid; i < 4 * 34 * 17; i += 289) {
            int a = i / (34 * 17);
            int rem = i - a * 34 * 17;
            int n = rem / 17, jp = rem % 17;
            Bs[a][n][jp] = g_xfP[((img * 4 + a) * 68 + k0 + n) * 34 + jpBase + jp];
        }
        __syncthreads();
        #pragma unroll
        for (int n = 0; n < 34; n++) {
            ulonglong2 cs[4];
            #pragma unroll
            for (int i = 0; i < 4; i++) cs[i] = As[ty + 17 * i][n];
            u64 b0 = Bs[0][n][tx], b1 = Bs[1][n][tx];
            u64 b2 = Bs[2][n][tx], b3 = Bs[3][n][tx];
            #pragma unroll
            for (int i = 0; i < 4; i++) {
                FMA2(acc[0][i], cs[i].x, b0);
                FMA2(acc[1][i], cs[i].x, b1);
                FMA2(acc[2][i], cs[i].y, b2);
                FMA2(acc[3][i], cs[i].y, b3);
            }
        }
        __syncthreads();
    }
    int j0 = (jpBase + tx) * 2;
    #pragma unroll
    for (int i = 0; i < 4; i++) {
        int k = ty + 17 * i;
        float2 p1 = upk(acc[0][i]), p2 = upk(acc[1][i]);
        float2 p3 = upk(acc[2][i]), p4 = upk(acc[3][i]);
        ulonglong2 v0, v1;
        v0.x = pk(p1.x, -p3.x); v0.y = pk(-p4.x, p2.x);
        v1.x = pk(p1.y, -p3.y); v1.y = pk(-p4.y, p2.y);
        g_P[(img * 68 + k) * 68 + j0]     = v0;
        g_P[(img * 68 + k) * 68 + j0 + 1] = v1;
    }
}

// ---------------- kC: U,V,W,Z GEMMs + R-multiply + k2-fold epilogue ----------------
// block (17,17); grid (2, NIMG). rows k1=ty+17i, cols k2 = colBase + tx*2 + j
__global__ void kC() {
    __shared__ ulonglong2 As[68][17];
    __shared__ ulonglong2 Bs[17][35];
    int img = blockIdx.y;
    int colBase = blockIdx.x * 34;
    int tx = threadIdx.x, ty = threadIdx.y, tid = ty * 17 + tx;
    u64 UW[4][2], VZ[4][2];
    #pragma unroll
    for (int i = 0; i < 4; i++)
        #pragma unroll
        for (int j = 0; j < 2; j++) { UW[i][j] = 0ULL; VZ[i][j] = 0ULL; }

    for (int k0 = 0; k0 < 68; k0 += 17) {
        for (int i = tid; i < 68 * 17; i += 289) {
            int r = i / 17, jj = i - r * 17;
            As[r][jj] = g_P[(img * 68 + r) * 68 + k0 + jj];
        }
        for (int i = tid; i < 17 * 34; i += 289) {
            int jj = i / 34, c = i - jj * 34;
            Bs[jj][c] = g_CSd[(colBase + c) * 68 + k0 + jj];
        }
        __syncthreads();
        #pragma unroll
        for (int jj = 0; jj < 17; jj++) {
            ulonglong2 a[4], bv[2];
            #pragma unroll
            for (int i = 0; i < 4; i++) a[i] = As[ty + 17 * i][jj];
            #pragma unroll
            for (int j = 0; j < 2; j++) bv[j] = Bs[jj][tx * 2 + j];
            #pragma unroll
            for (int i = 0; i < 4; i++)
                #pragma unroll
                for (int j = 0; j < 2; j++) {
                    FMA2(UW[i][j], a[i].x, bv[j].x);
                    FMA2(VZ[i][j], a[i].y, bv[j].y);
                }
        }
        __syncthreads();
    }
    int ch = img & 63;
    #pragma unroll
    for (int i = 0; i < 4; i++) {
        int k1 = ty + 17 * i;
        #pragma unroll
        for (int j = 0; j < 2; j++) {
            int k2 = colBase + tx * 2 + j;
            float2 uw = upk(UW[i][j]), vz = upk(VZ[i][j]);
            float U = uw.x, W = uw.y, V = vz.x, Z = vz.y;
            float Xr = U + V, Xi = W - Z;
            float Xr2 = U - V, Xi2 = W + Z;
            int k2m = (NN - k2) % NN;
            float2 R1 = g_R[ch * NPIX + k1 * NN + k2];
            float2 R2 = g_R[ch * NPIX + k1 * NN + k2m];
            float Yr  = Xr * R1.x - Xi * R1.y;
            float Yi  = Xr * R1.y + Xi * R1.x;
            float Yr2 = Xr2 * R2.x - Xi2 * R2.y;
            float Yi2 = Xr2 * R2.y + Xi2 * R2.x;
            bool dbl = (k2 >= 1 && k2 <= 65);
            float sYr = dbl ? Yr + Yr2 : Yr;
            float sYi = dbl ? Yi + Yi2 : Yi;
            float dYi = dbl ? Yi - Yi2 : 0.f;
            float dYr = dbl ? Yr - Yr2 : 0.f;
            ulonglong2 o;
            o.x = pk(sYr, sYi); o.y = pk(dYi, dYr);
            g_SYDY[(img * 68 + k1) * 68 + k2] = o;
        }
    }
}

// ---------------- kD: T2 = fold-GEMM over k2 (K=68), packed (re,im) ----------------
// block (11,17); grid (3, NIMG). rows k1=ty+17i (68), cols m2 = colBase + tx*4 + j
__global__ void kD() {
    __shared__ ulonglong2 As[68][17];
    __shared__ ulonglong2 Bs[17][45];
    int img = blockIdx.y;
    int colBase = blockIdx.x * 44;
    int tx = threadIdx.x, ty = threadIdx.y, tid = ty * 11 + tx;
    u64 acc[4][4];
    #pragma unroll
    for (int i = 0; i < 4; i++)
        #pragma unroll
        for (int j = 0; j < 4; j++) acc[i][j] = 0ULL;

    for (int k0 = 0; k0 < 68; k0 += 17) {
        for (int i = tid; i < 68 * 17; i += 187) {
            int r = i / 17, jj = i - r * 17;
            As[r][jj] = g_SYDY[(img * 68 + r) * 68 + k0 + jj];
        }
        for (int i = tid; i < 17 * 44; i += 187) {
            int jj = i / 44, c = i - jj * 44;
            Bs[jj][c] = g_Bd3[(k0 + jj) * 132 + colBase + c];
        }
        __syncthreads();
        #pragma unroll
        for (int jj = 0; jj < 17; jj++) {
            ulonglong2 a[4], bv[4];
            #pragma unroll
            for (int i = 0; i < 4; i++) a[i] = As[ty + 17 * i][jj];
            #pragma unroll
            for (int j = 0; j < 4; j++) bv[j] = Bs[jj][tx * 4 + j];
            #pragma unroll
            for (int i = 0; i < 4; i++)
                #pragma unroll
                for (int j = 0; j < 4; j++) {
                    FMA2(acc[i][j], a[i].x, bv[j].x);
                    FMA2(acc[i][j], a[i].y, bv[j].y);
                }
        }
        __syncthreads();
    }
    #pragma unroll
    for (int i = 0; i < 4; i++) {
        int k1 = ty + 17 * i;
        u64* p = &g_T2pk[(img * 68 + k1) * 132 + colBase + tx * 4];
        *(ulonglong2*)&p[0] = make_ulonglong2(acc[i][0], acc[i][1]);
        *(ulonglong2*)&p[2] = make_ulonglong2(acc[i][2], acc[i][3]);
    }
}

// ---------------- kE: (C,S) GEMM over k1 (K=68) + mirror combine ----------------
// block (11,17); grid (3, NIMG). rows m1=ty+17i, cols m2 = colBase + tx*4 + j
__global__ void kE() {
    __shared__ u64 As[68][18];
    __shared__ u64 Bs[17][45];
    int img = blockIdx.y;
    int colBase = blockIdx.x * 44;
    int tx = threadIdx.x, ty = threadIdx.y, tid = ty * 11 + tx;
    u64 acc[4][4];
    #pragma unroll
    for (int i = 0; i < 4; i++)
        #pragma unroll
        for (int j = 0; j < 4; j++) acc[i][j] = 0ULL;

    for (int k0 = 0; k0 < 68; k0 += 17) {
        for (int i = tid; i < 68 * 17; i += 187) {
            int r = i / 17, jj = i - r * 17;
            As[r][jj] = g_G4[r * 68 + k0 + jj];
        }
        for (int i = tid; i < 17 * 44; i += 187) {
            int jj = i / 44, c = i - jj * 44;
            Bs[jj][c] = g_T2pk[(img * 68 + k0 + jj) * 132 + colBase + c];
        }
        __syncthreads();
        #pragma unroll
        for (int jj = 0; jj < 17; jj++) {
            u64 a[4], b[4];
            #pragma unroll
            for (int i = 0; i < 4; i++) a[i] = As[ty + 17 * i][jj];
            #pragma unroll
            for (int j = 0; j < 4; j++) b[j] = Bs[jj][tx * 4 + j];
            #pragma unroll
            for (int i = 0; i < 4; i++)
                #pragma unroll
                for (int j = 0; j < 4; j++) FMA2(acc[i][j], a[i], b[j]);
        }
        __syncthreads();
    }
    float* zb = g_z + img * NPIX;
    #pragma unroll
    for (int i = 0; i < 4; i++) {
        int m1 = ty + 17 * i;
        if (m1 > 66) continue;
        float2 v0 = upk(acc[i][0]), v1 = upk(acc[i][1]);
        float2 v2 = upk(acc[i][2]), v3 = upk(acc[i][3]);
        float4 zp = make_float4(v0.x + v0.y, v1.x + v1.y, v2.x + v2.y, v3.x + v3.y);
        *(float4*)&zb[m1 * NN + colBase + tx * 4] = zp;
        if (m1 >= 1 && m1 <= 65) {
            float4 zm = make_float4(v0.x - v0.y, v1.x - v1.y, v2.x - v2.y, v3.x - v3.y);
            *(float4*)&zb[(NN - m1) * NN + colBase + tx * 4] = zm;
        }
    }
}

// ---------------- final: nearest-up + 3x3 polyphase gather + crop + exact GELU ----------------
__global__ void k_final(const float* __restrict__ x, const float* __restrict__ wt,
                        float* __restrict__ out) {
    int i = blockIdx.x * blockDim.x + threadIdx.x;
    int q = i & 255;
    int p = (i >> 8) & 255;
    int img = i >> 16;
    int c = img & 63;
    int n1 = p + 4, n2 = q + 4;
    int m1 = n1 >> 1, m2 = n2 >> 1;
    int a1 = n1 & 1, a2 = n2 & 1;
    const float* z = g_z + img * NPIX;
    const float* w = wt + c * 9;
    float z00 = z[m1 * NN + m2];
    float acc;
    if (a1 == 0) {
        if (a2 == 0) acc = w[4] * z00;
        else         acc = w[3] * z00 + w[5] * z[m1 * NN + m2 + 1];
    } else {
        if (a2 == 0) acc = w[1] * z00 + w[7] * z[(m1 + 1) * NN + m2];
        else         acc = w[0] * z00 + w[2] * z[m1 * NN + m2 + 1]
                         + w[6] * z[(m1 + 1) * NN + m2] + w[8] * z[(m1 + 1) * NN + m2 + 1];
    }
    float v = x[(img * 128 + ((m1 + 126) & 127)) * 128 + ((m2 + 126) & 127)] + acc;
    out[i] = 0.5f * v * (1.0f + erff(v * 0.70710678118654752f));
}

// ---------------- launch ----------------
extern "C" void kernel_launch(void* const* d_in, const int* in_sizes, int n_in,
                              void* d_out, int out_size) {
    const float* x    = (const float*)d_in[0];   // (4,64,128,128)
    const float* w    = (const float*)d_in[1];   // (1,64,3,3)
    const float* bias = (const float*)d_in[2];   // (1,64,1,1)
    float* out = (float*)d_out;                  // (4,64,256,256)

    k_buildCSd<<<(68 * 68 + 255) / 256, 256>>>();
    k_buildBd3<<<(68 * 132 + 255) / 256, 256>>>();
    k_buildG4<<<(68 * 68 + 255) / 256, 256>>>();
    k_buildTw<<<(MM + 127) / 128, 128>>>();
    k_buildWB<<<dim3((MM + 127) / 128, NCH), 128>>>(w);
    k_buildR<<<dim3(67, NCH), NN>>>(bias);

    kA<<<(NIMG * 68 * 34 + 255) / 256, 256>>>(x);

    dim3 b17(17, 17), b11(11, 17);
    kB<<<dim3(2, NIMG), b17>>>();
    kC<<<dim3(2, NIMG), b17>>>();
    kD<<<dim3(3, NIMG), b11>>>();
    kE<<<dim3(3, NIMG), b11>>>();

    k_final<<<(4 * 64 * 256 * 256) / 256, 256>>>(x, w, out);
}

// round 11
// speedup vs baseline: 2.8462x; 1.0994x over previous
#include <cuda_runtime.h>
#include <math.h>

#define NN 132
#define MM 264
#define NPIX (NN*NN)
#define NIMG 256
#define NCH  64
#define PIF 3.14159265358979323846f

typedef unsigned long long u64;

__device__ __forceinline__ u64 pk(float x, float y) {
    u64 r; asm("mov.b64 %0, {%1,%2};" : "=l"(r) : "f"(x), "f"(y)); return r;
}
__device__ __forceinline__ float2 upk(u64 v) {
    float2 r; asm("mov.b64 {%0,%1}, %2;" : "=f"(r.x), "=f"(r.y) : "l"(v)); return r;
}
#define FMA2(acc, a, b) asm("fma.rn.f32x2 %0, %1, %2, %0;" : "+l"(acc) : "l"(a), "l"(b))

// ---------------- static scratch ----------------
__device__ ulonglong2 g_CSd[68*68];        // {pk(c,c), pk(s,s)}; zero at k==67||n==67
__device__ ulonglong2 g_Bd3[68*132];       // [k2][m2]: {pk(c,c), pk(-s,s)}; zero row k2==67
__device__ u64        g_G4[68*68];         // [m1][k1]: pk(g*c, -g*s); 0 at k1==67
__device__ u64        g_xfP[NIMG*4*68*34]; // folded x, j-pair packed
__device__ ulonglong2 g_P[NIMG*68*68];     // [img][k][j]: {pk(P1,-P3'), pk(-P4',P2)}
__device__ ulonglong2 g_SYDY[NIMG*68*68];  // [img][k1][k2]: {pk(sYr,sYi), pk(dYi,dYr)}
__device__ u64        g_T2pk[NIMG*68*132]; // [img][k1][m2]: pk(T2re,T2im)
__device__ float      g_z[NIMG*NPIX];
__device__ float2     g_R[NCH*NPIX];
__device__ float2     g_E1[MM*3];
__device__ float2     g_U1[MM];
__device__ float2     g_WB[NCH*MM*3];

// ---------------- builders ----------------
__global__ void k_buildCSd() {
    int i = blockIdx.x * blockDim.x + threadIdx.x;
    if (i >= 68 * 68) return;
    int k = i / 68, n = i % 68;
    ulonglong2 v;
    if (k == 67 || n == 67) { v.x = 0ULL; v.y = 0ULL; }
    else {
        int t = (k * n) % NN;
        float ang = (2.0f * PIF / NN) * (float)t;
        float s, c; sincosf(ang, &s, &c);
        v.x = pk(c, c); v.y = pk(s, s);
    }
    g_CSd[i] = v;
}

__global__ void k_buildBd3() {
    int i = blockIdx.x * blockDim.x + threadIdx.x;
    if (i >= 68 * 132) return;
    int k2 = i / 132, m2 = i % 132;
    ulonglong2 v;
    if (k2 == 67) { v.x = 0ULL; v.y = 0ULL; }
    else {
        int t = (k2 * m2) % NN;
        float ang = (2.0f * PIF / NN) * (float)t;
        float s, c; sincosf(ang, &s, &c);
        v.x = pk(c, c); v.y = pk(-s, s);
    }
    g_Bd3[i] = v;
}

__global__ void k_buildG4() {
    int i = blockIdx.x * blockDim.x + threadIdx.x;
    if (i >= 68 * 68) return;
    int m1 = i / 68, k1 = i % 68;
    if (k1 == 67) { g_G4[i] = 0ULL; return; }
    float g = (k1 == 0 || k1 == 66) ? 1.0f : 2.0f;
    int t = (k1 * m1) % NN;
    float ang = (2.0f * PIF / NN) * (float)t;
    float s, c; sincosf(ang, &s, &c);
    g_G4[i] = pk(g * c, -g * s);
}

__global__ void k_buildTw() {
    int kk = blockIdx.x * blockDim.x + threadIdx.x;
    if (kk >= MM) return;
    #pragma unroll
    for (int u = 0; u < 3; u++) {
        int t = kk * (u - 1);
        t %= MM; if (t < 0) t += MM;
        float ang = (2.0f * PIF / MM) * (float)t;
        float s, c; sincosf(ang, &s, &c);
        g_E1[kk * 3 + u] = make_float2(c, -s);
    }
    float ang = (2.0f * PIF / MM) * (float)kk;
    float s, c; sincosf(ang, &s, &c);
    g_U1[kk] = make_float2(1.f + c, -s);
}

__global__ void k_buildWB(const float* __restrict__ w) {
    int kk = blockIdx.x * blockDim.x + threadIdx.x;
    int c = blockIdx.y;
    if (kk >= MM) return;
    float2 e0 = g_E1[kk * 3 + 0], e1 = g_E1[kk * 3 + 1], e2 = g_E1[kk * 3 + 2];
    #pragma unroll
    for (int u = 0; u < 3; u++) {
        float w0 = w[c * 9 + u * 3 + 0];
        float w1 = w[c * 9 + u * 3 + 1];
        float w2 = w[c * 9 + u * 3 + 2];
        g_WB[(c * MM + kk) * 3 + u] =
            make_float2(w0 * e0.x + w1 * e1.x + w2 * e2.x,
                        w0 * e0.y + w1 * e1.y + w2 * e2.y);
    }
}

__global__ void k_buildR(const float* __restrict__ bias) {
    int k2 = threadIdx.x, k1 = blockIdx.x, c = blockIdx.y;
    float alpha = 1.0f / (1.0f + expf(9.0f - bias[c])) + 1e-5f;
    float Vr = 0.f, Vi = 0.f, W2 = 0.f;
    #pragma unroll
    for (int r1 = 0; r1 < 2; r1++)
    #pragma unroll
    for (int r2 = 0; r2 < 2; r2++) {
        int kk1 = k1 + r1 * NN, kk2 = k2 + r2 * NN;
        float fr = 0.f, fi = 0.f;
        #pragma unroll
        for (int u = 0; u < 3; u++) {
            float2 e = g_E1[kk1 * 3 + u];
            float2 b = g_WB[(c * MM + kk2) * 3 + u];
            fr += e.x * b.x - e.y * b.y;
            fi += e.x * b.y + e.y * b.x;
        }
        float2 u1 = g_U1[kk1], u2 = g_U1[kk2];
        float Ur = u1.x * u2.x - u1.y * u2.y;
        float Ui = u1.x * u2.y + u1.y * u2.x;
        Vr += fr * Ur - fi * Ui;
        Vi += fr * Ui + fi * Ur;
        W2 += fr * fr + fi * fi;
    }
    Vr *= 0.25f; Vi *= 0.25f; W2 *= 0.25f;
    float sc = 1.0f / (W2 + alpha) * (1.0f / (float)NPIX);
    g_R[(c * NN + k1) * NN + k2] = make_float2((1.f - Vr) * sc, (-Vi) * sc);
}

// ---------------- kA: quadrant fold of input ----------------
__global__ void kA(const float* __restrict__ x) {
    int idx = blockIdx.x * blockDim.x + threadIdx.x;
    if (idx >= NIMG * 68 * 34) return;
    int img = idx / (68 * 34);
    int rem = idx - img * 68 * 34;
    int n = rem / 34, jp = rem % 34;
    const float* xb = x + img * 16384;
    float vals[4][2];
    #pragma unroll
    for (int h = 0; h < 2; h++) {
        int jt = 2 * jp + h;
        float pp = 0.f, pm = 0.f, mp = 0.f, mm = 0.f;
        if (n < 67 && jt < 67) {
            int n2 = (NN - n) % NN, j2 = (NN - jt) % NN;
            bool nsel = (n != 0 && n != 66);
            bool jsel = (jt != 0 && jt != 66);
            #define XW(R,C) xb[((((R)+126)&127)<<7) + (((C)+126)&127)]
            float a  = XW(n, jt);
            float b  = nsel ? XW(n2, jt) : 0.f;
            float cc = jsel ? XW(n, j2) : 0.f;
            float d  = (nsel && jsel) ? XW(n2, j2) : 0.f;
            #undef XW
            pp = a + b + cc + d;
            pm = jsel ? (a + b - cc - d) : 0.f;
            mp = nsel ? (a - b + cc - d) : 0.f;
            mm = (nsel && jsel) ? (a - b - cc + d) : 0.f;
        }
        vals[0][h] = pp; vals[1][h] = pm; vals[2][h] = mp; vals[3][h] = mm;
    }
    #pragma unroll
    for (int a = 0; a < 4; a++)
        g_xfP[((img * 4 + a) * 68 + n) * 34 + jp] = pk(vals[a][0], vals[a][1]);
}

// ---------------- kB: folded real GEMMs, 2 images per block ----------------
// block (17,17); grid (2, NIMG/2)
__global__ void kB() {
    __shared__ ulonglong2 As[68][34];        // CSd (shared across images)
    __shared__ ulonglong2 Bs[4][34][18];     // img-packed: .x=img0, .y=img1
    int img0 = blockIdx.y * 2;
    int jpBase = blockIdx.x * 17;
    int tx = threadIdx.x, ty = threadIdx.y, tid = ty * 17 + tx;
    u64 acc[2][4][4];
    #pragma unroll
    for (int m = 0; m < 2; m++)
        #pragma unroll
        for (int a = 0; a < 4; a++)
            #pragma unroll
            for (int i = 0; i < 4; i++) acc[m][a][i] = 0ULL;

    const int IMGSTR = 4 * 68 * 34;
    for (int k0 = 0; k0 < 68; k0 += 34) {
        for (int i = tid; i < 68 * 34; i += 289) {
            int r = i / 34, n = i - r * 34;
            As[r][n] = g_CSd[r * 68 + k0 + n];
        }
        for (int i = tid; i < 4 * 34 * 17; i += 289) {
            int a = i / 578;
            int rem = i - a * 578;
            int n = rem / 17, jp = rem % 17;
            int base = (a * 68 + k0 + n) * 34 + jpBase + jp;
            ulonglong2 v;
            v.x = g_xfP[img0 * IMGSTR + base];
            v.y = g_xfP[(img0 + 1) * IMGSTR + base];
            Bs[a][n][jp] = v;
        }
        __syncthreads();
        #pragma unroll
        for (int n = 0; n < 34; n++) {
            ulonglong2 cs[4];
            #pragma unroll
            for (int i = 0; i < 4; i++) cs[i] = As[ty + 17 * i][n];
            ulonglong2 b0 = Bs[0][n][tx], b1 = Bs[1][n][tx];
            ulonglong2 b2 = Bs[2][n][tx], b3 = Bs[3][n][tx];
            #pragma unroll
            for (int i = 0; i < 4; i++) {
                FMA2(acc[0][0][i], cs[i].x, b0.x);
                FMA2(acc[0][1][i], cs[i].x, b1.x);
                FMA2(acc[0][2][i], cs[i].y, b2.x);
                FMA2(acc[0][3][i], cs[i].y, b3.x);
                FMA2(acc[1][0][i], cs[i].x, b0.y);
                FMA2(acc[1][1][i], cs[i].x, b1.y);
                FMA2(acc[1][2][i], cs[i].y, b2.y);
                FMA2(acc[1][3][i], cs[i].y, b3.y);
            }
        }
        __syncthreads();
    }
    int j0 = (jpBase + tx) * 2;
    #pragma unroll
    for (int m = 0; m < 2; m++) {
        int img = img0 + m;
        #pragma unroll
        for (int i = 0; i < 4; i++) {
            int k = ty + 17 * i;
            float2 p1 = upk(acc[m][0][i]), p2 = upk(acc[m][1][i]);
            float2 p3 = upk(acc[m][2][i]), p4 = upk(acc[m][3][i]);
            ulonglong2 v0, v1;
            v0.x = pk(p1.x, -p3.x); v0.y = pk(-p4.x, p2.x);
            v1.x = pk(p1.y, -p3.y); v1.y = pk(-p4.y, p2.y);
            g_P[(img * 68 + k) * 68 + j0]     = v0;
            g_P[(img * 68 + k) * 68 + j0 + 1] = v1;
        }
    }
}

// ---------------- kC: U,V,W,Z GEMMs + R + k2-fold, 2 images per block ----------------
// block (17,17); grid (2, NIMG/2)
__global__ void kC() {
    __shared__ ulonglong2 As[2][68][17];
    __shared__ ulonglong2 Bs[17][35];
    int img0 = blockIdx.y * 2;
    int colBase = blockIdx.x * 34;
    int tx = threadIdx.x, ty = threadIdx.y, tid = ty * 17 + tx;
    u64 UW[2][4][2], VZ[2][4][2];
    #pragma unroll
    for (int m = 0; m < 2; m++)
        #pragma unroll
        for (int i = 0; i < 4; i++)
            #pragma unroll
            for (int j = 0; j < 2; j++) { UW[m][i][j] = 0ULL; VZ[m][i][j] = 0ULL; }

    for (int k0 = 0; k0 < 68; k0 += 17) {
        for (int i = tid; i < 2 * 68 * 17; i += 289) {
            int m = i / 1156;
            int rem = i - m * 1156;
            int r = rem / 17, jj = rem - r * 17;
            As[m][r][jj] = g_P[((img0 + m) * 68 + r) * 68 + k0 + jj];
        }
        for (int i = tid; i < 17 * 34; i += 289) {
            int jj = i / 34, c = i - jj * 34;
            Bs[jj][c] = g_CSd[(colBase + c) * 68 + k0 + jj];
        }
        __syncthreads();
        #pragma unroll
        for (int jj = 0; jj < 17; jj++) {
            ulonglong2 a[2][4], bv[2];
            #pragma unroll
            for (int j = 0; j < 2; j++) bv[j] = Bs[jj][tx * 2 + j];
            #pragma unroll
            for (int m = 0; m < 2; m++)
                #pragma unroll
                for (int i = 0; i < 4; i++) a[m][i] = As[m][ty + 17 * i][jj];
            #pragma unroll
            for (int m = 0; m < 2; m++)
                #pragma unroll
                for (int i = 0; i < 4; i++)
                    #pragma unroll
                    for (int j = 0; j < 2; j++) {
                        FMA2(UW[m][i][j], a[m][i].x, bv[j].x);
                        FMA2(VZ[m][i][j], a[m][i].y, bv[j].y);
                    }
        }
        __syncthreads();
    }
    #pragma unroll
    for (int m = 0; m < 2; m++) {
        int img = img0 + m;
        int ch = img & 63;
        #pragma unroll
        for (int i = 0; i < 4; i++) {
            int k1 = ty + 17 * i;
            #pragma unroll
            for (int j = 0; j < 2; j++) {
                int k2 = colBase + tx * 2 + j;
                float2 uw = upk(UW[m][i][j]), vz = upk(VZ[m][i][j]);
                float U = uw.x, W = uw.y, V = vz.x, Z = vz.y;
                float Xr = U + V, Xi = W - Z;
                float Xr2 = U - V, Xi2 = W + Z;
                int k2m = (NN - k2) % NN;
                float2 R1 = g_R[ch * NPIX + k1 * NN + k2];
                float2 R2 = g_R[ch * NPIX + k1 * NN + k2m];
                float Yr  = Xr * R1.x - Xi * R1.y;
                float Yi  = Xr * R1.y + Xi * R1.x;
                float Yr2 = Xr2 * R2.x - Xi2 * R2.y;
                float Yi2 = Xr2 * R2.y + Xi2 * R2.x;
                bool dbl = (k2 >= 1 && k2 <= 65);
                float sYr = dbl ? Yr + Yr2 : Yr;
                float sYi = dbl ? Yi + Yi2 : Yi;
                float dYi = dbl ? Yi - Yi2 : 0.f;
                float dYr = dbl ? Yr - Yr2 : 0.f;
                ulonglong2 o;
                o.x = pk(sYr, sYi); o.y = pk(dYi, dYr);
                g_SYDY[(img * 68 + k1) * 68 + k2] = o;
            }
        }
    }
}

// ---------------- kD: T2 fold-GEMM over k2, 2 images per block ----------------
// block (11,17); grid (3, NIMG/2)
__global__ void kD() {
    __shared__ ulonglong2 As[2][68][17];
    __shared__ ulonglong2 Bs[17][45];
    int img0 = blockIdx.y * 2;
    int colBase = blockIdx.x * 44;
    int tx = threadIdx.x, ty = threadIdx.y, tid = ty * 11 + tx;
    u64 acc[2][4][4];
    #pragma unroll
    for (int m = 0; m < 2; m++)
        #pragma unroll
        for (int i = 0; i < 4; i++)
            #pragma unroll
            for (int j = 0; j < 4; j++) acc[m][i][j] = 0ULL;

    for (int k0 = 0; k0 < 68; k0 += 17) {
        for (int i = tid; i < 2 * 68 * 17; i += 187) {
            int m = i / 1156;
            int rem = i - m * 1156;
            int r = rem / 17, jj = rem - r * 17;
            As[m][r][jj] = g_SYDY[((img0 + m) * 68 + r) * 68 + k0 + jj];
        }
        for (int i = tid; i < 17 * 44; i += 187) {
            int jj = i / 44, c = i - jj * 44;
            Bs[jj][c] = g_Bd3[(k0 + jj) * 132 + colBase + c];
        }
        __syncthreads();
        #pragma unroll
        for (int jj = 0; jj < 17; jj++) {
            ulonglong2 a[2][4], bv[4];
            #pragma unroll
            for (int j = 0; j < 4; j++) bv[j] = Bs[jj][tx * 4 + j];
            #pragma unroll
            for (int m = 0; m < 2; m++)
                #pragma unroll
                for (int i = 0; i < 4; i++) a[m][i] = As[m][ty + 17 * i][jj];
            #pragma unroll
            for (int m = 0; m < 2; m++)
                #pragma unroll
                for (int i = 0; i < 4; i++)
                    #pragma unroll
                    for (int j = 0; j < 4; j++) {
                        FMA2(acc[m][i][j], a[m][i].x, bv[j].x);
                        FMA2(acc[m][i][j], a[m][i].y, bv[j].y);
                    }
        }
        __syncthreads();
    }
    #pragma unroll
    for (int m = 0; m < 2; m++) {
        int img = img0 + m;
        #pragma unroll
        for (int i = 0; i < 4; i++) {
            int k1 = ty + 17 * i;
            u64* p = &g_T2pk[(img * 68 + k1) * 132 + colBase + tx * 4];
            *(ulonglong2*)&p[0] = make_ulonglong2(acc[m][i][0], acc[m][i][1]);
            *(ulonglong2*)&p[2] = make_ulonglong2(acc[m][i][2], acc[m][i][3]);
        }
    }
}

// ---------------- kE: (C,S) GEMM over k1 + mirror, 2 images per block ----------------
// block (11,17); grid (3, NIMG/2)
__global__ void kE() {
    __shared__ u64 As[68][18];               // G4 (shared across images)
    __shared__ ulonglong2 Bs[17][45];        // img-packed: .x=img0, .y=img1
    int img0 = blockIdx.y * 2;
    int colBase = blockIdx.x * 44;
    int tx = threadIdx.x, ty = threadIdx.y, tid = ty * 11 + tx;
    u64 acc[2][4][4];
    #pragma unroll
    for (int m = 0; m < 2; m++)
        #pragma unroll
        for (int i = 0; i < 4; i++)
            #pragma unroll
            for (int j = 0; j < 4; j++) acc[m][i][j] = 0ULL;

    for (int k0 = 0; k0 < 68; k0 += 17) {
        for (int i = tid; i < 68 * 17; i += 187) {
            int r = i / 17, jj = i - r * 17;
            As[r][jj] = g_G4[r * 68 + k0 + jj];
        }
        for (int i = tid; i < 17 * 44; i += 187) {
            int jj = i / 44, c = i - jj * 44;
            int base = (k0 + jj) * 132 + colBase + c;
            ulonglong2 v;
            v.x = g_T2pk[img0 * 68 * 132 + base];
            v.y = g_T2pk[(img0 + 1) * 68 * 132 + base];
            Bs[jj][c] = v;
        }
        __syncthreads();
        #pragma unroll
        for (int jj = 0; jj < 17; jj++) {
            u64 a[4];
            ulonglong2 b[4];
            #pragma unroll
            for (int i = 0; i < 4; i++) a[i] = As[ty + 17 * i][jj];
            #pragma unroll
            for (int j = 0; j < 4; j++) b[j] = Bs[jj][tx * 4 + j];
            #pragma unroll
            for (int i = 0; i < 4; i++)
                #pragma unroll
                for (int j = 0; j < 4; j++) {
                    FMA2(acc[0][i][j], a[i], b[j].x);
                    FMA2(acc[1][i][j], a[i], b[j].y);
                }
        }
        __syncthreads();
    }
    #pragma unroll
    for (int m = 0; m < 2; m++) {
        float* zb = g_z + (img0 + m) * NPIX;
        #pragma unroll
        for (int i = 0; i < 4; i++) {
            int m1 = ty + 17 * i;
            if (m1 > 66) continue;
            float2 v0 = upk(acc[m][i][0]), v1 = upk(acc[m][i][1]);
            float2 v2 = upk(acc[m][i][2]), v3 = upk(acc[m][i][3]);
            float4 zp = make_float4(v0.x + v0.y, v1.x + v1.y, v2.x + v2.y, v3.x + v3.y);
            *(float4*)&zb[m1 * NN + colBase + tx * 4] = zp;
            if (m1 >= 1 && m1 <= 65) {
                float4 zm = make_float4(v0.x - v0.y, v1.x - v1.y, v2.x - v2.y, v3.x - v3.y);
                *(float4*)&zb[(NN - m1) * NN + colBase + tx * 4] = zm;
            }
        }
    }
}

// ---------------- final: nearest-up + 3x3 polyphase gather + crop + exact GELU ----------------
__global__ void k_final(const float* __restrict__ x, const float* __restrict__ wt,
                        float* __restrict__ out) {
    int i = blockIdx.x * blockDim.x + threadIdx.x;
    int q = i & 255;
    int p = (i >> 8) & 255;
    int img = i >> 16;
    int c = img & 63;
    int n1 = p + 4, n2 = q + 4;
    int m1 = n1 >> 1, m2 = n2 >> 1;
    int a1 = n1 & 1, a2 = n2 & 1;
    const float* z = g_z + img * NPIX;
    const float* w = wt + c * 9;
    float z00 = z[m1 * NN + m2];
    float acc;
    if (a1 == 0) {
        if (a2 == 0) acc = w[4] * z00;
        else         acc = w[3] * z00 + w[5] * z[m1 * NN + m2 + 1];
    } else {
        if (a2 == 0) acc = w[1] * z00 + w[7] * z[(m1 + 1) * NN + m2];
        else         acc = w[0] * z00 + w[2] * z[m1 * NN + m2 + 1]
                         + w[6] * z[(m1 + 1) * NN + m2] + w[8] * z[(m1 + 1) * NN + m2 + 1];
    }
    float v = x[(img * 128 + ((m1 + 126) & 127)) * 128 + ((m2 + 126) & 127)] + acc;
    out[i] = 0.5f * v * (1.0f + erff(v * 0.70710678118654752f));
}

// ---------------- launch ----------------
extern "C" void kernel_launch(void* const* d_in, const int* in_sizes, int n_in,
                              void* d_out, int out_size) {
    const float* x    = (const float*)d_in[0];   // (4,64,128,128)
    const float* w    = (const float*)d_in[1];   // (1,64,3,3)
    const float* bias = (const float*)d_in[2];   // (1,64,1,1)
    float* out = (float*)d_out;                  // (4,64,256,256)

    k_buildCSd<<<(68 * 68 + 255) / 256, 256>>>();
    k_buildBd3<<<(68 * 132 + 255) / 256, 256>>>();
    k_buildG4<<<(68 * 68 + 255) / 256, 256>>>();
    k_buildTw<<<(MM + 127) / 128, 128>>>();
    k_buildWB<<<dim3((MM + 127) / 128, NCH), 128>>>(w);
    k_buildR<<<dim3(67, NCH), NN>>>(bias);

    kA<<<(NIMG * 68 * 34 + 255) / 256, 256>>>(x);

    dim3 b17(17, 17), b11(11, 17);
    kB<<<dim3(2, NIMG / 2), b17>>>();
    kC<<<dim3(2, NIMG / 2), b17>>>();
    kD<<<dim3(3, NIMG / 2), b11>>>();
    kE<<<dim3(3, NIMG / 2), b11>>>();

    k_final<<<(4 * 64 * 256 * 256) / 256, 256>>>(x, w, out);
}

// round 14
// speedup vs baseline: 2.9905x; 1.0507x over previous
#include <cuda_runtime.h>
#include <math.h>

#define NN 132
#define MM 264
#define NPIX (NN*NN)
#define NIMG 256
#define NCH  64
#define PIF 3.14159265358979323846f

typedef unsigned long long u64;

__device__ __forceinline__ u64 pk(float x, float y) {
    u64 r; asm("mov.b64 %0, {%1,%2};" : "=l"(r) : "f"(x), "f"(y)); return r;
}
__device__ __forceinline__ float2 upk(u64 v) {
    float2 r; asm("mov.b64 {%0,%1}, %2;" : "=f"(r.x), "=f"(r.y) : "l"(v)); return r;
}
#define FMA2(acc, a, b) asm("fma.rn.f32x2 %0, %1, %2, %0;" : "+l"(acc) : "l"(a), "l"(b))

// ---------------- static scratch ----------------
__device__ ulonglong2 g_CSd[68*68];        // {pk(c,c), pk(s,s)}; zero at k==67||n==67
__device__ ulonglong2 g_Bd3[68*132];       // [k2][m2]: {pk(c,c), pk(-s,s)}; zero row k2==67
__device__ u64        g_G4[68*68];         // [m1][k1]: pk(g*c, -g*s); 0 at k1==67
__device__ u64        g_xfP[NIMG*4*68*34]; // folded x, j-pair packed
__device__ ulonglong2 g_P[NIMG*68*68];     // [img][k][j]: {pk(P1,-P3'), pk(-P4',P2)}
__device__ ulonglong2 g_SYDY[NIMG*68*68];  // [img][k1][k2]: {pk(sYr,sYi), pk(dYi,dYr)}
__device__ float      g_z[NIMG*NPIX];
__device__ float2     g_R[NCH*NPIX];
__device__ float2     g_E1[MM*3];
__device__ float2     g_U1[MM];
__device__ float2     g_WB[NCH*MM*3];

// ---------------- fused constant tables ----------------
// [0,4624): CSd | [4624,13600): Bd3 | [13600,18224): G4 | [18224,18488): Tw(E1,U1)
__global__ void k_tables() {
    int idx = blockIdx.x * blockDim.x + threadIdx.x;
    if (idx < 4624) {
        int k = idx / 68, n = idx % 68;
        ulonglong2 v;
        if (k == 67 || n == 67) { v.x = 0ULL; v.y = 0ULL; }
        else {
            int t = (k * n) % NN;
            float ang = (2.0f * PIF / NN) * (float)t;
            float s, c; sincosf(ang, &s, &c);
            v.x = pk(c, c); v.y = pk(s, s);
        }
        g_CSd[idx] = v;
    } else if (idx < 13600) {
        int i = idx - 4624;
        int k2 = i / 132, m2 = i % 132;
        ulonglong2 v;
        if (k2 == 67) { v.x = 0ULL; v.y = 0ULL; }
        else {
            int t = (k2 * m2) % NN;
            float ang = (2.0f * PIF / NN) * (float)t;
            float s, c; sincosf(ang, &s, &c);
            v.x = pk(c, c); v.y = pk(-s, s);
        }
        g_Bd3[i] = v;
    } else if (idx < 18224) {
        int i = idx - 13600;
        int m1 = i / 68, k1 = i % 68;
        if (k1 == 67) { g_G4[i] = 0ULL; return; }
        float g = (k1 == 0 || k1 == 66) ? 1.0f : 2.0f;
        int t = (k1 * m1) % NN;
        float ang = (2.0f * PIF / NN) * (float)t;
        float s, c; sincosf(ang, &s, &c);
        g_G4[i] = pk(g * c, -g * s);
    } else if (idx < 18488) {
        int kk = idx - 18224;
        #pragma unroll
        for (int u = 0; u < 3; u++) {
            int t = kk * (u - 1);
            t %= MM; if (t < 0) t += MM;
            float ang = (2.0f * PIF / MM) * (float)t;
            float s, c; sincosf(ang, &s, &c);
            g_E1[kk * 3 + u] = make_float2(c, -s);
        }
        float ang = (2.0f * PIF / MM) * (float)kk;
        float s, c; sincosf(ang, &s, &c);
        g_U1[kk] = make_float2(1.f + c, -s);
    }
}

__global__ void k_buildWB(const float* __restrict__ w) {
    int kk = blockIdx.x * blockDim.x + threadIdx.x;
    int c = blockIdx.y;
    if (kk >= MM) return;
    float2 e0 = g_E1[kk * 3 + 0], e1 = g_E1[kk * 3 + 1], e2 = g_E1[kk * 3 + 2];
    #pragma unroll
    for (int u = 0; u < 3; u++) {
        float w0 = w[c * 9 + u * 3 + 0];
        float w1 = w[c * 9 + u * 3 + 1];
        float w2 = w[c * 9 + u * 3 + 2];
        g_WB[(c * MM + kk) * 3 + u] =
            make_float2(w0 * e0.x + w1 * e1.x + w2 * e2.x,
                        w0 * e0.y + w1 * e1.y + w2 * e2.y);
    }
}

__global__ void k_buildR(const float* __restrict__ bias) {
    int k2 = threadIdx.x, k1 = blockIdx.x, c = blockIdx.y;
    float alpha = 1.0f / (1.0f + expf(9.0f - bias[c])) + 1e-5f;
    float Vr = 0.f, Vi = 0.f, W2 = 0.f;
    #pragma unroll
    for (int r1 = 0; r1 < 2; r1++)
    #pragma unroll
    for (int r2 = 0; r2 < 2; r2++) {
        int kk1 = k1 + r1 * NN, kk2 = k2 + r2 * NN;
        float fr = 0.f, fi = 0.f;
        #pragma unroll
        for (int u = 0; u < 3; u++) {
            float2 e = g_E1[kk1 * 3 + u];
            float2 b = g_WB[(c * MM + kk2) * 3 + u];
            fr += e.x * b.x - e.y * b.y;
            fi += e.x * b.y + e.y * b.x;
        }
        float2 u1 = g_U1[kk1], u2 = g_U1[kk2];
        float Ur = u1.x * u2.x - u1.y * u2.y;
        float Ui = u1.x * u2.y + u1.y * u2.x;
        Vr += fr * Ur - fi * Ui;
        Vi += fr * Ui + fi * Ur;
        W2 += fr * fr + fi * fi;
    }
    Vr *= 0.25f; Vi *= 0.25f; W2 *= 0.25f;
    float sc = 1.0f / (W2 + alpha) * (1.0f / (float)NPIX);
    g_R[(c * NN + k1) * NN + k2] = make_float2((1.f - Vr) * sc, (-Vi) * sc);
}

// ---------------- kA: quadrant fold of input ----------------
__global__ void kA(const float* __restrict__ x) {
    int idx = blockIdx.x * blockDim.x + threadIdx.x;
    if (idx >= NIMG * 68 * 34) return;
    int img = idx / (68 * 34);
    int rem = idx - img * 68 * 34;
    int n = rem / 34, jp = rem % 34;
    const float* xb = x + img * 16384;
    float vals[4][2];
    #pragma unroll
    for (int h = 0; h < 2; h++) {
        int jt = 2 * jp + h;
        float pp = 0.f, pm = 0.f, mp = 0.f, mm = 0.f;
        if (n < 67 && jt < 67) {
            int n2 = (NN - n) % NN, j2 = (NN - jt) % NN;
            bool nsel = (n != 0 && n != 66);
            bool jsel = (jt != 0 && jt != 66);
            #define XW(R,C) xb[((((R)+126)&127)<<7) + (((C)+126)&127)]
            float a  = XW(n, jt);
            float b  = nsel ? XW(n2, jt) : 0.f;
            float cc = jsel ? XW(n, j2) : 0.f;
            float d  = (nsel && jsel) ? XW(n2, j2) : 0.f;
            #undef XW
            pp = a + b + cc + d;
            pm = jsel ? (a + b - cc - d) : 0.f;
            mp = nsel ? (a - b + cc - d) : 0.f;
            mm = (nsel && jsel) ? (a - b - cc + d) : 0.f;
        }
        vals[0][h] = pp; vals[1][h] = pm; vals[2][h] = mp; vals[3][h] = mm;
    }
    #pragma unroll
    for (int a = 0; a < 4; a++)
        g_xfP[((img * 4 + a) * 68 + n) * 34 + jp] = pk(vals[a][0], vals[a][1]);
}

// ---------------- kB: folded real GEMMs, 2 images per block ----------------
__global__ void kB() {
    __shared__ ulonglong2 As[68][34];
    __shared__ ulonglong2 Bs[4][34][18];
    int img0 = blockIdx.y * 2;
    int jpBase = blockIdx.x * 17;
    int tx = threadIdx.x, ty = threadIdx.y, tid = ty * 17 + tx;
    u64 acc[2][4][4];
    #pragma unroll
    for (int m = 0; m < 2; m++)
        #pragma unroll
        for (int a = 0; a < 4; a++)
            #pragma unroll
            for (int i = 0; i < 4; i++) acc[m][a][i] = 0ULL;

    const int IMGSTR = 4 * 68 * 34;
    for (int k0 = 0; k0 < 68; k0 += 34) {
        for (int i = tid; i < 68 * 34; i += 289) {
            int r = i / 34, n = i - r * 34;
            As[r][n] = g_CSd[r * 68 + k0 + n];
        }
        for (int i = tid; i < 4 * 34 * 17; i += 289) {
            int a = i / 578;
            int rem = i - a * 578;
            int n = rem / 17, jp = rem % 17;
            int base = (a * 68 + k0 + n) * 34 + jpBase + jp;
            ulonglong2 v;
            v.x = g_xfP[img0 * IMGSTR + base];
            v.y = g_xfP[(img0 + 1) * IMGSTR + base];
            Bs[a][n][jp] = v;
        }
        __syncthreads();
        #pragma unroll
        for (int n = 0; n < 34; n++) {
            ulonglong2 cs[4];
            #pragma unroll
            for (int i = 0; i < 4; i++) cs[i] = As[ty + 17 * i][n];
            ulonglong2 b0 = Bs[0][n][tx], b1 = Bs[1][n][tx];
            ulonglong2 b2 = Bs[2][n][tx], b3 = Bs[3][n][tx];
            #pragma unroll
            for (int i = 0; i < 4; i++) {
                FMA2(acc[0][0][i], cs[i].x, b0.x);
                FMA2(acc[0][1][i], cs[i].x, b1.x);
                FMA2(acc[0][2][i], cs[i].y, b2.x);
                FMA2(acc[0][3][i], cs[i].y, b3.x);
                FMA2(acc[1][0][i], cs[i].x, b0.y);
                FMA2(acc[1][1][i], cs[i].x, b1.y);
                FMA2(acc[1][2][i], cs[i].y, b2.y);
                FMA2(acc[1][3][i], cs[i].y, b3.y);
            }
        }
        __syncthreads();
    }
    int j0 = (jpBase + tx) * 2;
    #pragma unroll
    for (int m = 0; m < 2; m++) {
        int img = img0 + m;
        #pragma unroll
        for (int i = 0; i < 4; i++) {
            int k = ty + 17 * i;
            float2 p1 = upk(acc[m][0][i]), p2 = upk(acc[m][1][i]);
            float2 p3 = upk(acc[m][2][i]), p4 = upk(acc[m][3][i]);
            ulonglong2 v0, v1;
            v0.x = pk(p1.x, -p3.x); v0.y = pk(-p4.x, p2.x);
            v1.x = pk(p1.y, -p3.y); v1.y = pk(-p4.y, p2.y);
            g_P[(img * 68 + k) * 68 + j0]     = v0;
            g_P[(img * 68 + k) * 68 + j0 + 1] = v1;
        }
    }
}

// ---------------- kC: U,V,W,Z GEMMs + R + k2-fold, 2 images per block ----------------
__global__ void kC() {
    __shared__ ulonglong2 As[2][68][17];
    __shared__ ulonglong2 Bs[17][35];
    int img0 = blockIdx.y * 2;
    int colBase = blockIdx.x * 34;
    int tx = threadIdx.x, ty = threadIdx.y, tid = ty * 17 + tx;
    u64 UW[2][4][2], VZ[2][4][2];
    #pragma unroll
    for (int m = 0; m < 2; m++)
        #pragma unroll
        for (int i = 0; i < 4; i++)
            #pragma unroll
            for (int j = 0; j < 2; j++) { UW[m][i][j] = 0ULL; VZ[m][i][j] = 0ULL; }

    for (int k0 = 0; k0 < 68; k0 += 17) {
        for (int i = tid; i < 2 * 68 * 17; i += 289) {
            int m = i / 1156;
            int rem = i - m * 1156;
            int r = rem / 17, jj = rem - r * 17;
            As[m][r][jj] = g_P[((img0 + m) * 68 + r) * 68 + k0 + jj];
        }
        for (int i = tid; i < 17 * 34; i += 289) {
            int jj = i / 34, c = i - jj * 34;
            Bs[jj][c] = g_CSd[(colBase + c) * 68 + k0 + jj];
        }
        __syncthreads();
        #pragma unroll
        for (int jj = 0; jj < 17; jj++) {
            ulonglong2 a[2][4], bv[2];
            #pragma unroll
            for (int j = 0; j < 2; j++) bv[j] = Bs[jj][tx * 2 + j];
            #pragma unroll
            for (int m = 0; m < 2; m++)
                #pragma unroll
                for (int i = 0; i < 4; i++) a[m][i] = As[m][ty + 17 * i][jj];
            #pragma unroll
            for (int m = 0; m < 2; m++)
                #pragma unroll
                for (int i = 0; i < 4; i++)
                    #pragma unroll
                    for (int j = 0; j < 2; j++) {
                        FMA2(UW[m][i][j], a[m][i].x, bv[j].x);
                        FMA2(VZ[m][i][j], a[m][i].y, bv[j].y);
                    }
        }
        __syncthreads();
    }
    #pragma unroll
    for (int m = 0; m < 2; m++) {
        int img = img0 + m;
        int ch = img & 63;
        #pragma unroll
        for (int i = 0; i < 4; i++) {
            int k1 = ty + 17 * i;
            #pragma unroll
            for (int j = 0; j < 2; j++) {
                int k2 = colBase + tx * 2 + j;
                float2 uw = upk(UW[m][i][j]), vz = upk(VZ[m][i][j]);
                float U = uw.x, W = uw.y, V = vz.x, Z = vz.y;
                float Xr = U + V, Xi = W - Z;
                float Xr2 = U - V, Xi2 = W + Z;
                int k2m = (NN - k2) % NN;
                float2 R1 = g_R[ch * NPIX + k1 * NN + k2];
                float2 R2 = g_R[ch * NPIX + k1 * NN + k2m];
                float Yr  = Xr * R1.x - Xi * R1.y;
                float Yi  = Xr * R1.y + Xi * R1.x;
                float Yr2 = Xr2 * R2.x - Xi2 * R2.y;
                float Yi2 = Xr2 * R2.y + Xi2 * R2.x;
                bool dbl = (k2 >= 1 && k2 <= 65);
                float sYr = dbl ? Yr + Yr2 : Yr;
                float sYi = dbl ? Yi + Yi2 : Yi;
                float dYi = dbl ? Yi - Yi2 : 0.f;
                float dYr = dbl ? Yr - Yr2 : 0.f;
                ulonglong2 o;
                o.x = pk(sYr, sYi); o.y = pk(dYi, dYr);
                g_SYDY[(img * 68 + k1) * 68 + k2] = o;
            }
        }
    }
}

// ---------------- kDE: fused T2 fold-GEMM (phase1) + G4 GEMM + mirror (phase2) ----------------
// block (11,17); grid (3, NIMG/2). Dynamic smem:
//   [0, 36992)       phase1 As[2][68][17] ulonglong2   | phase2 G4s[68*68] u64
//   [36992, 49232)   phase1 Bs[17][45] ulonglong2
//   [49232, 98192)   Ts[68][45] ulonglong2  (img-packed T2 tile)
extern __shared__ char s_dyn[];
__global__ void kDE() {
    ulonglong2* As = (ulonglong2*)s_dyn;                 // [2][68][17]
    ulonglong2* Bs = (ulonglong2*)(s_dyn + 36992);       // [17][45]
    u64*        G4s = (u64*)s_dyn;                       // [68*68] (phase2)
    ulonglong2* Ts = (ulonglong2*)(s_dyn + 49232);       // [68][45]

    int img0 = blockIdx.y * 2;
    int colBase = blockIdx.x * 44;
    int tx = threadIdx.x, ty = threadIdx.y, tid = ty * 11 + tx;
    u64 acc[2][4][4];
    #pragma unroll
    for (int m = 0; m < 2; m++)
        #pragma unroll
        for (int i = 0; i < 4; i++)
            #pragma unroll
            for (int j = 0; j < 4; j++) acc[m][i][j] = 0ULL;

    // ---- phase 1: T2 tile (kD) ----
    for (int k0 = 0; k0 < 68; k0 += 17) {
        for (int i = tid; i < 2 * 68 * 17; i += 187) {
            int m = i / 1156;
            int rem = i - m * 1156;
            int r = rem / 17, jj = rem - r * 17;
            As[(m * 68 + r) * 17 + jj] = g_SYDY[((img0 + m) * 68 + r) * 68 + k0 + jj];
        }
        for (int i = tid; i < 17 * 44; i += 187) {
            int jj = i / 44, c = i - jj * 44;
            Bs[jj * 45 + c] = g_Bd3[(k0 + jj) * 132 + colBase + c];
        }
        __syncthreads();
        #pragma unroll
        for (int jj = 0; jj < 17; jj++) {
            ulonglong2 a[2][4], bv[4];
            #pragma unroll
            for (int j = 0; j < 4; j++) bv[j] = Bs[jj * 45 + tx * 4 + j];
            #pragma unroll
            for (int m = 0; m < 2; m++)
                #pragma unroll
                for (int i = 0; i < 4; i++) a[m][i] = As[(m * 68 + ty + 17 * i) * 17 + jj];
            #pragma unroll
            for (int m = 0; m < 2; m++)
                #pragma unroll
                for (int i = 0; i < 4; i++)
                    #pragma unroll
                    for (int j = 0; j < 4; j++) {
                        FMA2(acc[m][i][j], a[m][i].x, bv[j].x);
                        FMA2(acc[m][i][j], a[m][i].y, bv[j].y);
                    }
        }
        __syncthreads();
    }

    // ---- handoff: T2 tile -> smem (img-packed), G4 -> smem ----
    #pragma unroll
    for (int i = 0; i < 4; i++) {
        int k1 = ty + 17 * i;
        #pragma unroll
        for (int j = 0; j < 4; j++)
            Ts[k1 * 45 + tx * 4 + j] = make_ulonglong2(acc[0][i][j], acc[1][i][j]);
    }
    for (int i = tid; i < 68 * 68; i += 187) G4s[i] = g_G4[i];
    __syncthreads();

    // ---- phase 2: z = G4 @ T2 (kE) + mirror ----
    #pragma unroll
    for (int m = 0; m < 2; m++)
        #pragma unroll
        for (int i = 0; i < 4; i++)
            #pragma unroll
            for (int j = 0; j < 4; j++) acc[m][i][j] = 0ULL;

    #pragma unroll 4
    for (int jj = 0; jj < 68; jj++) {
        u64 a[4];
        ulonglong2 b[4];
        #pragma unroll
        for (int i = 0; i < 4; i++) a[i] = G4s[(ty + 17 * i) * 68 + jj];
        #pragma unroll
        for (int j = 0; j < 4; j++) b[j] = Ts[jj * 45 + tx * 4 + j];
        #pragma unroll
        for (int i = 0; i < 4; i++)
            #pragma unroll
            for (int j = 0; j < 4; j++) {
                FMA2(acc[0][i][j], a[i], b[j].x);
                FMA2(acc[1][i][j], a[i], b[j].y);
            }
    }

    #pragma unroll
    for (int m = 0; m < 2; m++) {
        float* zb = g_z + (img0 + m) * NPIX;
        #pragma unroll
        for (int i = 0; i < 4; i++) {
            int m1 = ty + 17 * i;
            if (m1 > 66) continue;
            float2 v0 = upk(acc[m][i][0]), v1 = upk(acc[m][i][1]);
            float2 v2 = upk(acc[m][i][2]), v3 = upk(acc[m][i][3]);
            float4 zp = make_float4(v0.x + v0.y, v1.x + v1.y, v2.x + v2.y, v3.x + v3.y);
            *(float4*)&zb[m1 * NN + colBase + tx * 4] = zp;
            if (m1 >= 1 && m1 <= 65) {
                float4 zm = make_float4(v0.x - v0.y, v1.x - v1.y, v2.x - v2.y, v3.x - v3.y);
                *(float4*)&zb[(NN - m1) * NN + colBase + tx * 4] = zm;
            }
        }
    }
}

// ---------------- final: nearest-up + 3x3 polyphase gather + crop + exact GELU ----------------
__global__ void k_final(const float* __restrict__ x, const float* __restrict__ wt,
                        float* __restrict__ out) {
    int i = blockIdx.x * blockDim.x + threadIdx.x;
    int q = i & 255;
    int p = (i >> 8) & 255;
    int img = i >> 16;
    int c = img & 63;
    int n1 = p + 4, n2 = q + 4;
    int m1 = n1 >> 1, m2 = n2 >> 1;
    int a1 = n1 & 1, a2 = n2 & 1;
    const float* z = g_z + img * NPIX;
    const float* w = wt + c * 9;
    float z00 = z[m1 * NN + m2];
    float acc;
    if (a1 == 0) {
        if (a2 == 0) acc = w[4] * z00;
        else         acc = w[3] * z00 + w[5] * z[m1 * NN + m2 + 1];
    } else {
        if (a2 == 0) acc = w[1] * z00 + w[7] * z[(m1 + 1) * NN + m2];
        else         acc = w[0] * z00 + w[2] * z[m1 * NN + m2 + 1]
                         + w[6] * z[(m1 + 1) * NN + m2] + w[8] * z[(m1 + 1) * NN + m2 + 1];
    }
    float v = x[(img * 128 + ((m1 + 126) & 127)) * 128 + ((m2 + 126) & 127)] + acc;
    out[i] = 0.5f * v * (1.0f + erff(v * 0.70710678118654752f));
}

// ---------------- launch ----------------
extern "C" void kernel_launch(void* const* d_in, const int* in_sizes, int n_in,
                              void* d_out, int out_size) {
    const float* x    = (const float*)d_in[0];   // (4,64,128,128)
    const float* w    = (const float*)d_in[1];   // (1,64,3,3)
    const float* bias = (const float*)d_in[2];   // (1,64,1,1)
    float* out = (float*)d_out;                  // (4,64,256,256)

    static bool attr_done = false;
    if (!attr_done) {
        cudaFuncSetAttribute(kDE, cudaFuncAttributeMaxDynamicSharedMemorySize, 98192);
        attr_done = true;
    }

    k_tables<<<(18488 + 255) / 256, 256>>>();
    k_buildWB<<<dim3((MM + 127) / 128, NCH), 128>>>(w);
    k_buildR<<<dim3(67, NCH), NN>>>(bias);

    kA<<<(NIMG * 68 * 34 + 255) / 256, 256>>>(x);

    dim3 b17(17, 17), b11(11, 17);
    kB<<<dim3(2, NIMG / 2), b17>>>();
    kC<<<dim3(2, NIMG / 2), b17>>>();
    kDE<<<dim3(3, NIMG / 2), b11, 98192>>>();

    k_final<<<(4 * 64 * 256 * 256) / 256, 256>>>(x, w, out);
}

// round 15
// speedup vs baseline: 3.1686x; 1.0596x over previous
#include <cuda_runtime.h>
#include <math.h>

#define NN 132
#define MM 264
#define NPIX (NN*NN)
#define NIMG 256
#define NCH  64
#define PIF 3.14159265358979323846f

typedef unsigned long long u64;

__device__ __forceinline__ u64 pk(float x, float y) {
    u64 r; asm("mov.b64 %0, {%1,%2};" : "=l"(r) : "f"(x), "f"(y)); return r;
}
__device__ __forceinline__ float2 upk(u64 v) {
    float2 r; asm("mov.b64 {%0,%1}, %2;" : "=f"(r.x), "=f"(r.y) : "l"(v)); return r;
}
#define FMA2(acc, a, b) asm("fma.rn.f32x2 %0, %1, %2, %0;" : "+l"(acc) : "l"(a), "l"(b))

// ---------------- static scratch ----------------
__device__ ulonglong2 g_CSd[68*68];        // {pk(c,c), pk(s,s)}; zero at k==67||n==67
__device__ ulonglong2 g_Bd3[68*132];       // [k2][m2]: {pk(c,c), pk(-s,s)}; zero row k2==67
__device__ u64        g_G4[68*68];         // [m1][k1]: pk(g*c, -g*s); 0 at k1==67
__device__ u64        g_xfP[NIMG*4*68*34]; // folded x, j-pair packed
__device__ ulonglong2 g_SYDY[NIMG*68*68];  // [img][k1][k2]: {pk(sYr,sYi), pk(dYi,dYr)}
__device__ float      g_z[NIMG*NPIX];
__device__ float2     g_R[NCH*NPIX];
__device__ float2     g_E1[MM*3];
__device__ float2     g_U1[MM];
__device__ float2     g_WB[NCH*MM*3];

extern __shared__ char s_dyn[];

// ---------------- fused constant tables ----------------
__global__ void k_tables() {
    int idx = blockIdx.x * blockDim.x + threadIdx.x;
    if (idx < 4624) {
        int k = idx / 68, n = idx % 68;
        ulonglong2 v;
        if (k == 67 || n == 67) { v.x = 0ULL; v.y = 0ULL; }
        else {
            int t = (k * n) % NN;
            float ang = (2.0f * PIF / NN) * (float)t;
            float s, c; sincosf(ang, &s, &c);
            v.x = pk(c, c); v.y = pk(s, s);
        }
        g_CSd[idx] = v;
    } else if (idx < 13600) {
        int i = idx - 4624;
        int k2 = i / 132, m2 = i % 132;
        ulonglong2 v;
        if (k2 == 67) { v.x = 0ULL; v.y = 0ULL; }
        else {
            int t = (k2 * m2) % NN;
            float ang = (2.0f * PIF / NN) * (float)t;
            float s, c; sincosf(ang, &s, &c);
            v.x = pk(c, c); v.y = pk(-s, s);
        }
        g_Bd3[i] = v;
    } else if (idx < 18224) {
        int i = idx - 13600;
        int m1 = i / 68, k1 = i % 68;
        if (k1 == 67) { g_G4[i] = 0ULL; return; }
        float g = (k1 == 0 || k1 == 66) ? 1.0f : 2.0f;
        int t = (k1 * m1) % NN;
        float ang = (2.0f * PIF / NN) * (float)t;
        float s, c; sincosf(ang, &s, &c);
        g_G4[i] = pk(g * c, -g * s);
    } else if (idx < 18488) {
        int kk = idx - 18224;
        #pragma unroll
        for (int u = 0; u < 3; u++) {
            int t = kk * (u - 1);
            t %= MM; if (t < 0) t += MM;
            float ang = (2.0f * PIF / MM) * (float)t;
            float s, c; sincosf(ang, &s, &c);
            g_E1[kk * 3 + u] = make_float2(c, -s);
        }
        float ang = (2.0f * PIF / MM) * (float)kk;
        float s, c; sincosf(ang, &s, &c);
        g_U1[kk] = make_float2(1.f + c, -s);
    }
}

__global__ void k_buildWB(const float* __restrict__ w) {
    int kk = blockIdx.x * blockDim.x + threadIdx.x;
    int c = blockIdx.y;
    if (kk >= MM) return;
    float2 e0 = g_E1[kk * 3 + 0], e1 = g_E1[kk * 3 + 1], e2 = g_E1[kk * 3 + 2];
    #pragma unroll
    for (int u = 0; u < 3; u++) {
        float w0 = w[c * 9 + u * 3 + 0];
        float w1 = w[c * 9 + u * 3 + 1];
        float w2 = w[c * 9 + u * 3 + 2];
        g_WB[(c * MM + kk) * 3 + u] =
            make_float2(w0 * e0.x + w1 * e1.x + w2 * e2.x,
                        w0 * e0.y + w1 * e1.y + w2 * e2.y);
    }
}

__global__ void k_buildR(const float* __restrict__ bias) {
    int k2 = threadIdx.x, k1 = blockIdx.x, c = blockIdx.y;
    float alpha = 1.0f / (1.0f + expf(9.0f - bias[c])) + 1e-5f;
    float Vr = 0.f, Vi = 0.f, W2 = 0.f;
    #pragma unroll
    for (int r1 = 0; r1 < 2; r1++)
    #pragma unroll
    for (int r2 = 0; r2 < 2; r2++) {
        int kk1 = k1 + r1 * NN, kk2 = k2 + r2 * NN;
        float fr = 0.f, fi = 0.f;
        #pragma unroll
        for (int u = 0; u < 3; u++) {
            float2 e = g_E1[kk1 * 3 + u];
            float2 b = g_WB[(c * MM + kk2) * 3 + u];
            fr += e.x * b.x - e.y * b.y;
            fi += e.x * b.y + e.y * b.x;
        }
        float2 u1 = g_U1[kk1], u2 = g_U1[kk2];
        float Ur = u1.x * u2.x - u1.y * u2.y;
        float Ui = u1.x * u2.y + u1.y * u2.x;
        Vr += fr * Ur - fi * Ui;
        Vi += fr * Ui + fi * Ur;
        W2 += fr * fr + fi * fi;
    }
    Vr *= 0.25f; Vi *= 0.25f; W2 *= 0.25f;
    float sc = 1.0f / (W2 + alpha) * (1.0f / (float)NPIX);
    g_R[(c * NN + k1) * NN + k2] = make_float2((1.f - Vr) * sc, (-Vi) * sc);
}

// ---------------- kA: quadrant fold of input ----------------
__global__ void kA(const float* __restrict__ x) {
    int idx = blockIdx.x * blockDim.x + threadIdx.x;
    if (idx >= NIMG * 68 * 34) return;
    int img = idx / (68 * 34);
    int rem = idx - img * 68 * 34;
    int n = rem / 34, jp = rem % 34;
    const float* xb = x + img * 16384;
    float vals[4][2];
    #pragma unroll
    for (int h = 0; h < 2; h++) {
        int jt = 2 * jp + h;
        float pp = 0.f, pm = 0.f, mp = 0.f, mm = 0.f;
        if (n < 67 && jt < 67) {
            int n2 = (NN - n) % NN, j2 = (NN - jt) % NN;
            bool nsel = (n != 0 && n != 66);
            bool jsel = (jt != 0 && jt != 66);
            #define XW(R,C) xb[((((R)+126)&127)<<7) + (((C)+126)&127)]
            float a  = XW(n, jt);
            float b  = nsel ? XW(n2, jt) : 0.f;
            float cc = jsel ? XW(n, j2) : 0.f;
            float d  = (nsel && jsel) ? XW(n2, j2) : 0.f;
            #undef XW
            pp = a + b + cc + d;
            pm = jsel ? (a + b - cc - d) : 0.f;
            mp = nsel ? (a - b + cc - d) : 0.f;
            mm = (nsel && jsel) ? (a - b - cc + d) : 0.f;
        }
        vals[0][h] = pp; vals[1][h] = pm; vals[2][h] = mp; vals[3][h] = mm;
    }
    #pragma unroll
    for (int a = 0; a < 4; a++)
        g_xfP[((img * 4 + a) * 68 + n) * 34 + jp] = pk(vals[a][0], vals[a][1]);
}

// ---------------- kBC: fused kB (phase1 -> P in smem) + kC (phase2) ----------------
// block (17,34)=578 threads; grid = NIMG/2 (one image pair per block)
// dyn smem layout:
//   [0, 76160)        phase1: As[68][34] ulonglong2 + Bs[4][34][17] ulonglong2
//                     phase2: CSs[68jj][68c] ulonglong2 (transposed CSd)
//   [76160, 224128)   Ps[2][68][68] ulonglong2
__global__ void __launch_bounds__(578) kBC() {
    ulonglong2* As  = (ulonglong2*)(s_dyn);
    ulonglong2* Bs  = (ulonglong2*)(s_dyn + 36992);
    ulonglong2* CSs = (ulonglong2*)(s_dyn);
    ulonglong2* Ps  = (ulonglong2*)(s_dyn + 76160);

    int img0 = blockIdx.x * 2;
    int tx = threadIdx.x, ty = threadIdx.y, tid = ty * 17 + tx;
    const int IMGSTR = 4 * 68 * 34;

    // ---- phase 1: P = CSd-transform over n (two j-halves) ----
    for (int h = 0; h < 2; h++) {
        u64 acc[2][4][2];
        #pragma unroll
        for (int m = 0; m < 2; m++)
            #pragma unroll
            for (int a = 0; a < 4; a++)
                #pragma unroll
                for (int i2 = 0; i2 < 2; i2++) acc[m][a][i2] = 0ULL;

        for (int k0 = 0; k0 < 68; k0 += 34) {
            for (int i = tid; i < 68 * 34; i += 578) {
                int r = i / 34, n = i - r * 34;
                As[r * 34 + n] = g_CSd[r * 68 + k0 + n];
            }
            for (int i = tid; i < 4 * 34 * 17; i += 578) {
                int a = i / 578;
                int rem = i - a * 578;
                int n = rem / 17, jp = rem - n * 17;
                int base = (a * 68 + k0 + n) * 34 + 17 * h + jp;
                ulonglong2 v;
                v.x = g_xfP[img0 * IMGSTR + base];
                v.y = g_xfP[(img0 + 1) * IMGSTR + base];
                Bs[(a * 34 + n) * 17 + jp] = v;
            }
            __syncthreads();
            #pragma unroll 2
            for (int n = 0; n < 34; n++) {
                ulonglong2 cs0 = As[ty * 34 + n];
                ulonglong2 cs1 = As[(ty + 34) * 34 + n];
                ulonglong2 b0 = Bs[(0 * 34 + n) * 17 + tx];
                ulonglong2 b1 = Bs[(1 * 34 + n) * 17 + tx];
                ulonglong2 b2 = Bs[(2 * 34 + n) * 17 + tx];
                ulonglong2 b3 = Bs[(3 * 34 + n) * 17 + tx];
                FMA2(acc[0][0][0], cs0.x, b0.x); FMA2(acc[0][0][1], cs1.x, b0.x);
                FMA2(acc[0][1][0], cs0.x, b1.x); FMA2(acc[0][1][1], cs1.x, b1.x);
                FMA2(acc[0][2][0], cs0.y, b2.x); FMA2(acc[0][2][1], cs1.y, b2.x);
                FMA2(acc[0][3][0], cs0.y, b3.x); FMA2(acc[0][3][1], cs1.y, b3.x);
                FMA2(acc[1][0][0], cs0.x, b0.y); FMA2(acc[1][0][1], cs1.x, b0.y);
                FMA2(acc[1][1][0], cs0.x, b1.y); FMA2(acc[1][1][1], cs1.x, b1.y);
                FMA2(acc[1][2][0], cs0.y, b2.y); FMA2(acc[1][2][1], cs1.y, b2.y);
                FMA2(acc[1][3][0], cs0.y, b3.y); FMA2(acc[1][3][1], cs1.y, b3.y);
            }
            __syncthreads();
        }
        int j0 = 34 * h + 2 * tx;
        #pragma unroll
        for (int m = 0; m < 2; m++)
            #pragma unroll
            for (int i2 = 0; i2 < 2; i2++) {
                int k = ty + 34 * i2;
                float2 p1 = upk(acc[m][0][i2]), p2 = upk(acc[m][1][i2]);
                float2 p3 = upk(acc[m][2][i2]), p4 = upk(acc[m][3][i2]);
                ulonglong2 v0, v1;
                v0.x = pk(p1.x, -p3.x); v0.y = pk(-p4.x, p2.x);
                v1.x = pk(p1.y, -p3.y); v1.y = pk(-p4.y, p2.y);
                Ps[m * 4624 + k * 68 + j0]     = v0;
                Ps[m * 4624 + k * 68 + j0 + 1] = v1;
            }
        __syncthreads();
    }

    // ---- phase 2: X = P-transform over j, fused R + k2-fold (kC) ----
    for (int i = tid; i < 68 * 68; i += 578) {
        int jj = i / 68, c = i - jj * 68;
        CSs[jj * 68 + c] = g_CSd[c * 68 + jj];   // transposed for conflict-free col reads
    }
    __syncthreads();

    #pragma unroll
    for (int hc = 0; hc < 2; hc++) {
        u64 UW[2][2][2], VZ[2][2][2];
        #pragma unroll
        for (int m = 0; m < 2; m++)
            #pragma unroll
            for (int i2 = 0; i2 < 2; i2++)
                #pragma unroll
                for (int j = 0; j < 2; j++) { UW[m][i2][j] = 0ULL; VZ[m][i2][j] = 0ULL; }

        #pragma unroll 4
        for (int jj = 0; jj < 68; jj++) {
            ulonglong2 a00 = Ps[0 * 4624 + ty * 68 + jj];
            ulonglong2 a01 = Ps[0 * 4624 + (ty + 34) * 68 + jj];
            ulonglong2 a10 = Ps[1 * 4624 + ty * 68 + jj];
            ulonglong2 a11 = Ps[1 * 4624 + (ty + 34) * 68 + jj];
            ulonglong2 bv0 = CSs[jj * 68 + 34 * hc + 2 * tx];
            ulonglong2 bv1 = CSs[jj * 68 + 34 * hc + 2 * tx + 1];
            FMA2(UW[0][0][0], a00.x, bv0.x); FMA2(VZ[0][0][0], a00.y, bv0.y);
            FMA2(UW[0][0][1], a00.x, bv1.x); FMA2(VZ[0][0][1], a00.y, bv1.y);
            FMA2(UW[0][1][0], a01.x, bv0.x); FMA2(VZ[0][1][0], a01.y, bv0.y);
            FMA2(UW[0][1][1], a01.x, bv1.x); FMA2(VZ[0][1][1], a01.y, bv1.y);
            FMA2(UW[1][0][0], a10.x, bv0.x); FMA2(VZ[1][0][0], a10.y, bv0.y);
            FMA2(UW[1][0][1], a10.x, bv1.x); FMA2(VZ[1][0][1], a10.y, bv1.y);
            FMA2(UW[1][1][0], a11.x, bv0.x); FMA2(VZ[1][1][0], a11.y, bv0.y);
            FMA2(UW[1][1][1], a11.x, bv1.x); FMA2(VZ[1][1][1], a11.y, bv1.y);
        }

        #pragma unroll
        for (int m = 0; m < 2; m++) {
            int img = img0 + m;
            int ch = img & 63;
            #pragma unroll
            for (int i2 = 0; i2 < 2; i2++) {
                int k1 = ty + 34 * i2;
                #pragma unroll
                for (int j = 0; j < 2; j++) {
                    int k2 = 34 * hc + 2 * tx + j;
                    float2 uw = upk(UW[m][i2][j]), vz = upk(VZ[m][i2][j]);
                    float U = uw.x, W = uw.y, V = vz.x, Z = vz.y;
                    float Xr = U + V, Xi = W - Z;
                    float Xr2 = U - V, Xi2 = W + Z;
                    int k2m = (NN - k2) % NN;
                    float2 R1 = g_R[ch * NPIX + k1 * NN + k2];
                    float2 R2 = g_R[ch * NPIX + k1 * NN + k2m];
                    float Yr  = Xr * R1.x - Xi * R1.y;
                    float Yi  = Xr * R1.y + Xi * R1.x;
                    float Yr2 = Xr2 * R2.x - Xi2 * R2.y;
                    float Yi2 = Xr2 * R2.y + Xi2 * R2.x;
                    bool dbl = (k2 >= 1 && k2 <= 65);
                    float sYr = dbl ? Yr + Yr2 : Yr;
                    float sYi = dbl ? Yi + Yi2 : Yi;
                    float dYi = dbl ? Yi - Yi2 : 0.f;
                    float dYr = dbl ? Yr - Yr2 : 0.f;
                    ulonglong2 o;
                    o.x = pk(sYr, sYi); o.y = pk(dYi, dYr);
                    g_SYDY[(img * 68 + k1) * 68 + k2] = o;
                }
            }
        }
    }
}

// ---------------- kDE: fused T2 fold-GEMM (phase1) + G4 GEMM + mirror (phase2) ----------------
__global__ void kDE() {
    ulonglong2* As = (ulonglong2*)s_dyn;                 // [2][68][17]
    ulonglong2* Bs = (ulonglong2*)(s_dyn + 36992);       // [17][45]
    u64*        G4s = (u64*)s_dyn;                       // [68*68] (phase2)
    ulonglong2* Ts = (ulonglong2*)(s_dyn + 49232);       // [68][45]

    int img0 = blockIdx.y * 2;
    int colBase = blockIdx.x * 44;
    int tx = threadIdx.x, ty = threadIdx.y, tid = ty * 11 + tx;
    u64 acc[2][4][4];
    #pragma unroll
    for (int m = 0; m < 2; m++)
        #pragma unroll
        for (int i = 0; i < 4; i++)
            #pragma unroll
            for (int j = 0; j < 4; j++) acc[m][i][j] = 0ULL;

    for (int k0 = 0; k0 < 68; k0 += 17) {
        for (int i = tid; i < 2 * 68 * 17; i += 187) {
            int m = i / 1156;
            int rem = i - m * 1156;
            int r = rem / 17, jj = rem - r * 17;
            As[(m * 68 + r) * 17 + jj] = g_SYDY[((img0 + m) * 68 + r) * 68 + k0 + jj];
        }
        for (int i = tid; i < 17 * 44; i += 187) {
            int jj = i / 44, c = i - jj * 44;
            Bs[jj * 45 + c] = g_Bd3[(k0 + jj) * 132 + colBase + c];
        }
        __syncthreads();
        #pragma unroll
        for (int jj = 0; jj < 17; jj++) {
            ulonglong2 a[2][4], bv[4];
            #pragma unroll
            for (int j = 0; j < 4; j++) bv[j] = Bs[jj * 45 + tx * 4 + j];
            #pragma unroll
            for (int m = 0; m < 2; m++)
                #pragma unroll
                for (int i = 0; i < 4; i++) a[m][i] = As[(m * 68 + ty + 17 * i) * 17 + jj];
            #pragma unroll
            for (int m = 0; m < 2; m++)
                #pragma unroll
                for (int i = 0; i < 4; i++)
                    #pragma unroll
                    for (int j = 0; j < 4; j++) {
                        FMA2(acc[m][i][j], a[m][i].x, bv[j].x);
                        FMA2(acc[m][i][j], a[m][i].y, bv[j].y);
                    }
        }
        __syncthreads();
    }

    #pragma unroll
    for (int i = 0; i < 4; i++) {
        int k1 = ty + 17 * i;
        #pragma unroll
        for (int j = 0; j < 4; j++)
            Ts[k1 * 45 + tx * 4 + j] = make_ulonglong2(acc[0][i][j], acc[1][i][j]);
    }
    for (int i = tid; i < 68 * 68; i += 187) G4s[i] = g_G4[i];
    __syncthreads();

    #pragma unroll
    for (int m = 0; m < 2; m++)
        #pragma unroll
        for (int i = 0; i < 4; i++)
            #pragma unroll
            for (int j = 0; j < 4; j++) acc[m][i][j] = 0ULL;

    #pragma unroll 4
    for (int jj = 0; jj < 68; jj++) {
        u64 a[4];
        ulonglong2 b[4];
        #pragma unroll
        for (int i = 0; i < 4; i++) a[i] = G4s[(ty + 17 * i) * 68 + jj];
        #pragma unroll
        for (int j = 0; j < 4; j++) b[j] = Ts[jj * 45 + tx * 4 + j];
        #pragma unroll
        for (int i = 0; i < 4; i++)
            #pragma unroll
            for (int j = 0; j < 4; j++) {
                FMA2(acc[0][i][j], a[i], b[j].x);
                FMA2(acc[1][i][j], a[i], b[j].y);
            }
    }

    #pragma unroll
    for (int m = 0; m < 2; m++) {
        float* zb = g_z + (img0 + m) * NPIX;
        #pragma unroll
        for (int i = 0; i < 4; i++) {
            int m1 = ty + 17 * i;
            if (m1 > 66) continue;
            float2 v0 = upk(acc[m][i][0]), v1 = upk(acc[m][i][1]);
            float2 v2 = upk(acc[m][i][2]), v3 = upk(acc[m][i][3]);
            float4 zp = make_float4(v0.x + v0.y, v1.x + v1.y, v2.x + v2.y, v3.x + v3.y);
            *(float4*)&zb[m1 * NN + colBase + tx * 4] = zp;
            if (m1 >= 1 && m1 <= 65) {
                float4 zm = make_float4(v0.x - v0.y, v1.x - v1.y, v2.x - v2.y, v3.x - v3.y);
                *(float4*)&zb[(NN - m1) * NN + colBase + tx * 4] = zm;
            }
        }
    }
}

// ---------------- final: 2x2 quad per thread, shared m1/m2, exact GELU ----------------
__global__ void k_final(const float* __restrict__ x, const float* __restrict__ wt,
                        float* __restrict__ out) {
    int i = blockIdx.x * blockDim.x + threadIdx.x;   // 256*128*128
    int Q = i & 127, P = (i >> 7) & 127, img = i >> 14;
    int c = img & 63;
    __shared__ float sw[9];
    if (threadIdx.x < 9) sw[threadIdx.x] = wt[c * 9 + threadIdx.x];
    __syncthreads();
    int m1 = P + 2, m2 = Q + 2;
    const float* z = g_z + img * NPIX;
    float z00 = z[m1 * NN + m2],       z01 = z[m1 * NN + m2 + 1];
    float z10 = z[(m1 + 1) * NN + m2], z11 = z[(m1 + 1) * NN + m2 + 1];
    float xv = x[(img * 128 + ((m1 + 126) & 127)) * 128 + ((m2 + 126) & 127)];
    float v00 = xv + sw[4] * z00;
    float v01 = xv + sw[3] * z00 + sw[5] * z01;
    float v10 = xv + sw[1] * z00 + sw[7] * z10;
    float v11 = xv + sw[0] * z00 + sw[2] * z01 + sw[6] * z10 + sw[8] * z11;
    #define GELU(v) (0.5f * (v) * (1.0f + erff((v) * 0.70710678118654752f)))
    float* ob = out + img * 65536;
    *(float2*)&ob[(2 * P) * 256 + 2 * Q]     = make_float2(GELU(v00), GELU(v01));
    *(float2*)&ob[(2 * P + 1) * 256 + 2 * Q] = make_float2(GELU(v10), GELU(v11));
    #undef GELU
}

// ---------------- launch ----------------
extern "C" void kernel_launch(void* const* d_in, const int* in_sizes, int n_in,
                              void* d_out, int out_size) {
    const float* x    = (const float*)d_in[0];   // (4,64,128,128)
    const float* w    = (const float*)d_in[1];   // (1,64,3,3)
    const float* bias = (const float*)d_in[2];   // (1,64,1,1)
    float* out = (float*)d_out;                  // (4,64,256,256)

    static bool attr_done = false;
    if (!attr_done) {
        cudaFuncSetAttribute(kBC, cudaFuncAttributeMaxDynamicSharedMemorySize, 224128);
        cudaFuncSetAttribute(kDE, cudaFuncAttributeMaxDynamicSharedMemorySize, 98192);
        attr_done = true;
    }

    k_tables<<<(18488 + 255) / 256, 256>>>();
    k_buildWB<<<dim3((MM + 127) / 128, NCH), 128>>>(w);
    k_buildR<<<dim3(67, NCH), NN>>>(bias);

    kA<<<(NIMG * 68 * 34 + 255) / 256, 256>>>(x);

    kBC<<<NIMG / 2, dim3(17, 34), 224128>>>();
    kDE<<<dim3(3, NIMG / 2), dim3(11, 17), 98192>>>();

    k_final<<<(NIMG * 128 * 128) / 256, 256>>>(x, w, out);
}

// round 16
// speedup vs baseline: 3.4084x; 1.0757x over previous
#include <cuda_runtime.h>
#include <math.h>

#define NN 132
#define MM 264
#define NPIX (NN*NN)
#define NIMG 256
#define NCH  64
#define PIF 3.14159265358979323846f

typedef unsigned long long u64;

__device__ __forceinline__ u64 pk(float x, float y) {
    u64 r; asm("mov.b64 %0, {%1,%2};" : "=l"(r) : "f"(x), "f"(y)); return r;
}
__device__ __forceinline__ float2 upk(u64 v) {
    float2 r; asm("mov.b64 {%0,%1}, %2;" : "=f"(r.x), "=f"(r.y) : "l"(v)); return r;
}
#define FMA2(acc, a, b) asm("fma.rn.f32x2 %0, %1, %2, %0;" : "+l"(acc) : "l"(a), "l"(b))

// ---------------- static scratch ----------------
__device__ ulonglong2 g_CSd[68*68];        // {pk(c,c), pk(s,s)}; zero at k==67||n==67
__device__ ulonglong2 g_Bd3[68*132];       // [k2][m2]: {pk(c,c), pk(-s,s)}; zero row k2==67
__device__ u64        g_G4[68*68];         // [m1][k1]: pk(g*c, -g*s); 0 at k1==67
__device__ u64        g_xfP[NIMG*4*68*34]; // folded x, j-pair packed
__device__ ulonglong2 g_SYDY[NIMG*68*68];  // [img][k1][k2]: {pk(sYr,sYi), pk(dYi,dYr)}
__device__ float      g_z[NIMG*NPIX];
__device__ float2     g_R[NCH*NPIX];
__device__ float2     g_E1[MM*3];
__device__ float2     g_U1[MM];
__device__ float2     g_WB[NCH*MM*3];

extern __shared__ char s_dyn[];

// ---------------- fused constant tables ----------------
__global__ void k_tables() {
    int idx = blockIdx.x * blockDim.x + threadIdx.x;
    if (idx < 4624) {
        int k = idx / 68, n = idx % 68;
        ulonglong2 v;
        if (k == 67 || n == 67) { v.x = 0ULL; v.y = 0ULL; }
        else {
            int t = (k * n) % NN;
            float ang = (2.0f * PIF / NN) * (float)t;
            float s, c; sincosf(ang, &s, &c);
            v.x = pk(c, c); v.y = pk(s, s);
        }
        g_CSd[idx] = v;
    } else if (idx < 13600) {
        int i = idx - 4624;
        int k2 = i / 132, m2 = i % 132;
        ulonglong2 v;
        if (k2 == 67) { v.x = 0ULL; v.y = 0ULL; }
        else {
            int t = (k2 * m2) % NN;
            float ang = (2.0f * PIF / NN) * (float)t;
            float s, c; sincosf(ang, &s, &c);
            v.x = pk(c, c); v.y = pk(-s, s);
        }
        g_Bd3[i] = v;
    } else if (idx < 18224) {
        int i = idx - 13600;
        int m1 = i / 68, k1 = i % 68;
        if (k1 == 67) { g_G4[i] = 0ULL; return; }
        float g = (k1 == 0 || k1 == 66) ? 1.0f : 2.0f;
        int t = (k1 * m1) % NN;
        float ang = (2.0f * PIF / NN) * (float)t;
        float s, c; sincosf(ang, &s, &c);
        g_G4[i] = pk(g * c, -g * s);
    } else if (idx < 18488) {
        int kk = idx - 18224;
        #pragma unroll
        for (int u = 0; u < 3; u++) {
            int t = kk * (u - 1);
            t %= MM; if (t < 0) t += MM;
            float ang = (2.0f * PIF / MM) * (float)t;
            float s, c; sincosf(ang, &s, &c);
            g_E1[kk * 3 + u] = make_float2(c, -s);
        }
        float ang = (2.0f * PIF / MM) * (float)kk;
        float s, c; sincosf(ang, &s, &c);
        g_U1[kk] = make_float2(1.f + c, -s);
    }
}

__global__ void k_buildWB(const float* __restrict__ w) {
    int kk = blockIdx.x * blockDim.x + threadIdx.x;
    int c = blockIdx.y;
    if (kk >= MM) return;
    float2 e0 = g_E1[kk * 3 + 0], e1 = g_E1[kk * 3 + 1], e2 = g_E1[kk * 3 + 2];
    #pragma unroll
    for (int u = 0; u < 3; u++) {
        float w0 = w[c * 9 + u * 3 + 0];
        float w1 = w[c * 9 + u * 3 + 1];
        float w2 = w[c * 9 + u * 3 + 2];
        g_WB[(c * MM + kk) * 3 + u] =
            make_float2(w0 * e0.x + w1 * e1.x + w2 * e2.x,
                        w0 * e0.y + w1 * e1.y + w2 * e2.y);
    }
}

__global__ void k_buildR(const float* __restrict__ bias) {
    int k2 = threadIdx.x, k1 = blockIdx.x, c = blockIdx.y;
    float alpha = 1.0f / (1.0f + expf(9.0f - bias[c])) + 1e-5f;
    float Vr = 0.f, Vi = 0.f, W2 = 0.f;
    #pragma unroll
    for (int r1 = 0; r1 < 2; r1++)
    #pragma unroll
    for (int r2 = 0; r2 < 2; r2++) {
        int kk1 = k1 + r1 * NN, kk2 = k2 + r2 * NN;
        float fr = 0.f, fi = 0.f;
        #pragma unroll
        for (int u = 0; u < 3; u++) {
            float2 e = g_E1[kk1 * 3 + u];
            float2 b = g_WB[(c * MM + kk2) * 3 + u];
            fr += e.x * b.x - e.y * b.y;
            fi += e.x * b.y + e.y * b.x;
        }
        float2 u1 = g_U1[kk1], u2 = g_U1[kk2];
        float Ur = u1.x * u2.x - u1.y * u2.y;
        float Ui = u1.x * u2.y + u1.y * u2.x;
        Vr += fr * Ur - fi * Ui;
        Vi += fr * Ui + fi * Ur;
        W2 += fr * fr + fi * fi;
    }
    Vr *= 0.25f; Vi *= 0.25f; W2 *= 0.25f;
    float sc = 1.0f / (W2 + alpha) * (1.0f / (float)NPIX);
    g_R[(c * NN + k1) * NN + k2] = make_float2((1.f - Vr) * sc, (-Vi) * sc);
}

// ---------------- kA: quadrant fold of input ----------------
__global__ void kA(const float* __restrict__ x) {
    int idx = blockIdx.x * blockDim.x + threadIdx.x;
    if (idx >= NIMG * 68 * 34) return;
    int img = idx / (68 * 34);
    int rem = idx - img * 68 * 34;
    int n = rem / 34, jp = rem % 34;
    const float* xb = x + img * 16384;
    float vals[4][2];
    #pragma unroll
    for (int h = 0; h < 2; h++) {
        int jt = 2 * jp + h;
        float pp = 0.f, pm = 0.f, mp = 0.f, mm = 0.f;
        if (n < 67 && jt < 67) {
            int n2 = (NN - n) % NN, j2 = (NN - jt) % NN;
            bool nsel = (n != 0 && n != 66);
            bool jsel = (jt != 0 && jt != 66);
            #define XW(R,C) xb[((((R)+126)&127)<<7) + (((C)+126)&127)]
            float a  = XW(n, jt);
            float b  = nsel ? XW(n2, jt) : 0.f;
            float cc = jsel ? XW(n, j2) : 0.f;
            float d  = (nsel && jsel) ? XW(n2, j2) : 0.f;
            #undef XW
            pp = a + b + cc + d;
            pm = jsel ? (a + b - cc - d) : 0.f;
            mp = nsel ? (a - b + cc - d) : 0.f;
            mm = (nsel && jsel) ? (a - b - cc + d) : 0.f;
        }
        vals[0][h] = pp; vals[1][h] = pm; vals[2][h] = mp; vals[3][h] = mm;
    }
    #pragma unroll
    for (int a = 0; a < 4; a++)
        g_xfP[((img * 4 + a) * 68 + n) * 34 + jp] = pk(vals[a][0], vals[a][1]);
}

// ---------------- kBC: fused kB+kC, widened microtiles, single-pass phases ----------------
// block (17,34)=578 threads; grid = NIMG/2
// dyn smem:
//   phase1: As[68][18] ulonglong2 @0 (19584B); Bs[4][17][35] ulonglong2 @19584 (38080B)
//   phase2: CSs[68][69] ulonglong2 @0 (75072B)
//   Ps[2][68][68] ulonglong2 @76160 (148 KB)
__global__ void __launch_bounds__(578) kBC() {
    ulonglong2* As  = (ulonglong2*)(s_dyn);
    ulonglong2* Bs  = (ulonglong2*)(s_dyn + 19584);
    ulonglong2* CSs = (ulonglong2*)(s_dyn);
    ulonglong2* Ps  = (ulonglong2*)(s_dyn + 76160);

    int img0 = blockIdx.x * 2;
    int tx = threadIdx.x, ty = threadIdx.y, tid = ty * 17 + tx;
    int h2 = (ty >= 17) ? 1 : 0;
    int tyr = ty - 17 * h2;
    const int IMGSTR = 4 * 68 * 34;

    // ---- phase 1: P = CSd-transform over n; rows 4x, all 34 jp in one pass ----
    {
        u64 acc[2][4][4];   // [img][arr][rowi]
        #pragma unroll
        for (int m = 0; m < 2; m++)
            #pragma unroll
            for (int a = 0; a < 4; a++)
                #pragma unroll
                for (int i = 0; i < 4; i++) acc[m][a][i] = 0ULL;

        int jp = tx + 17 * h2;   // 0..33
        for (int k0 = 0; k0 < 68; k0 += 17) {
            for (int i = tid; i < 68 * 17; i += 578) {
                int r = i / 17, n = i - r * 17;
                As[r * 18 + n] = g_CSd[r * 68 + k0 + n];
            }
            for (int i = tid; i < 4 * 17 * 34; i += 578) {
                int a = i / 578;
                int rem = i - a * 578;
                int n = rem / 34, jpx = rem - n * 34;
                int base = (a * 68 + k0 + n) * 34 + jpx;
                ulonglong2 v;
                v.x = g_xfP[img0 * IMGSTR + base];
                v.y = g_xfP[(img0 + 1) * IMGSTR + base];
                Bs[(a * 17 + n) * 35 + jpx] = v;
            }
            __syncthreads();
            #pragma unroll
            for (int n = 0; n < 17; n++) {
                ulonglong2 cs[4], b[4];
                #pragma unroll
                for (int i = 0; i < 4; i++) cs[i] = As[(tyr + 17 * i) * 18 + n];
                #pragma unroll
                for (int a = 0; a < 4; a++) b[a] = Bs[(a * 17 + n) * 35 + jp];
                #pragma unroll
                for (int i = 0; i < 4; i++) {
                    FMA2(acc[0][0][i], cs[i].x, b[0].x); FMA2(acc[1][0][i], cs[i].x, b[0].y);
                    FMA2(acc[0][1][i], cs[i].x, b[1].x); FMA2(acc[1][1][i], cs[i].x, b[1].y);
                    FMA2(acc[0][2][i], cs[i].y, b[2].x); FMA2(acc[1][2][i], cs[i].y, b[2].y);
                    FMA2(acc[0][3][i], cs[i].y, b[3].x); FMA2(acc[1][3][i], cs[i].y, b[3].y);
                }
            }
            __syncthreads();
        }
        int j0 = 2 * jp;
        #pragma unroll
        for (int m = 0; m < 2; m++)
            #pragma unroll
            for (int i = 0; i < 4; i++) {
                int k = tyr + 17 * i;
                float2 p1 = upk(acc[m][0][i]), p2 = upk(acc[m][1][i]);
                float2 p3 = upk(acc[m][2][i]), p4 = upk(acc[m][3][i]);
                ulonglong2 v0, v1;
                v0.x = pk(p1.x, -p3.x); v0.y = pk(-p4.x, p2.x);
                v1.x = pk(p1.y, -p3.y); v1.y = pk(-p4.y, p2.y);
                Ps[m * 4624 + k * 68 + j0]     = v0;
                Ps[m * 4624 + k * 68 + j0 + 1] = v1;
            }
        __syncthreads();
    }

    // ---- phase 2: X over j; img split across ty-halves; 4 rows x 4 k2-cols ----
    for (int i = tid; i < 68 * 68; i += 578) {
        int jj = i / 68, c = i - jj * 68;
        CSs[jj * 69 + c] = g_CSd[c * 68 + jj];
    }
    __syncthreads();

    {
        int m = h2;                       // image index within pair
        u64 UW[4][4], VZ[4][4];           // [rowi][colj]
        #pragma unroll
        for (int i = 0; i < 4; i++)
            #pragma unroll
            for (int j = 0; j < 4; j++) { UW[i][j] = 0ULL; VZ[i][j] = 0ULL; }

        #pragma unroll 4
        for (int jj = 0; jj < 68; jj++) {
            ulonglong2 a[4], bv[4];
            #pragma unroll
            for (int i = 0; i < 4; i++) a[i] = Ps[m * 4624 + (tyr + 17 * i) * 68 + jj];
            #pragma unroll
            for (int j = 0; j < 4; j++) bv[j] = CSs[jj * 69 + 4 * tx + j];
            #pragma unroll
            for (int i = 0; i < 4; i++)
                #pragma unroll
                for (int j = 0; j < 4; j++) {
                    FMA2(UW[i][j], a[i].x, bv[j].x);
                    FMA2(VZ[i][j], a[i].y, bv[j].y);
                }
        }

        int img = img0 + m;
        int ch = img & 63;
        #pragma unroll
        for (int i = 0; i < 4; i++) {
            int k1 = tyr + 17 * i;
            #pragma unroll
            for (int j = 0; j < 4; j++) {
                int k2 = 4 * tx + j;
                float2 uw = upk(UW[i][j]), vz = upk(VZ[i][j]);
                float U = uw.x, W = uw.y, V = vz.x, Z = vz.y;
                float Xr = U + V, Xi = W - Z;
                float Xr2 = U - V, Xi2 = W + Z;
                int k2m = (NN - k2) % NN;
                float2 R1 = g_R[ch * NPIX + k1 * NN + k2];
                float2 R2 = g_R[ch * NPIX + k1 * NN + k2m];
                float Yr  = Xr * R1.x - Xi * R1.y;
                float Yi  = Xr * R1.y + Xi * R1.x;
                float Yr2 = Xr2 * R2.x - Xi2 * R2.y;
                float Yi2 = Xr2 * R2.y + Xi2 * R2.x;
                bool dbl = (k2 >= 1 && k2 <= 65);
                float sYr = dbl ? Yr + Yr2 : Yr;
                float sYi = dbl ? Yi + Yi2 : Yi;
                float dYi = dbl ? Yi - Yi2 : 0.f;
                float dYr = dbl ? Yr - Yr2 : 0.f;
                ulonglong2 o;
                o.x = pk(sYr, sYi); o.y = pk(dYi, dYr);
                g_SYDY[(img * 68 + k1) * 68 + k2] = o;
            }
        }
    }
}

// ---------------- kDE: fused T2 fold-GEMM (phase1) + G4 GEMM + mirror (phase2) ----------------
__global__ void kDE() {
    ulonglong2* As = (ulonglong2*)s_dyn;                 // [2][68][17]
    ulonglong2* Bs = (ulonglong2*)(s_dyn + 36992);       // [17][45]
    u64*        G4s = (u64*)s_dyn;                       // [68*68] (phase2)
    ulonglong2* Ts = (ulonglong2*)(s_dyn + 49232);       // [68][45]

    int img0 = blockIdx.y * 2;
    int colBase = blockIdx.x * 44;
    int tx = threadIdx.x, ty = threadIdx.y, tid = ty * 11 + tx;
    u64 acc[2][4][4];
    #pragma unroll
    for (int m = 0; m < 2; m++)
        #pragma unroll
        for (int i = 0; i < 4; i++)
            #pragma unroll
            for (int j = 0; j < 4; j++) acc[m][i][j] = 0ULL;

    for (int k0 = 0; k0 < 68; k0 += 17) {
        for (int i = tid; i < 2 * 68 * 17; i += 187) {
            int m = i / 1156;
            int rem = i - m * 1156;
            int r = rem / 17, jj = rem - r * 17;
            As[(m * 68 + r) * 17 + jj] = g_SYDY[((img0 + m) * 68 + r) * 68 + k0 + jj];
        }
        for (int i = tid; i < 17 * 44; i += 187) {
            int jj = i / 44, c = i - jj * 44;
            Bs[jj * 45 + c] = g_Bd3[(k0 + jj) * 132 + colBase + c];
        }
        __syncthreads();
        #pragma unroll
        for (int jj = 0; jj < 17; jj++) {
            ulonglong2 a[2][4], bv[4];
            #pragma unroll
            for (int j = 0; j < 4; j++) bv[j] = Bs[jj * 45 + tx * 4 + j];
            #pragma unroll
            for (int m = 0; m < 2; m++)
                #pragma unroll
                for (int i = 0; i < 4; i++) a[m][i] = As[(m * 68 + ty + 17 * i) * 17 + jj];
            #pragma unroll
            for (int m = 0; m < 2; m++)
                #pragma unroll
                for (int i = 0; i < 4; i++)
                    #pragma unroll
                    for (int j = 0; j < 4; j++) {
                        FMA2(acc[m][i][j], a[m][i].x, bv[j].x);
                        FMA2(acc[m][i][j], a[m][i].y, bv[j].y);
                    }
        }
        __syncthreads();
    }

    #pragma unroll
    for (int i = 0; i < 4; i++) {
        int k1 = ty + 17 * i;
        #pragma unroll
        for (int j = 0; j < 4; j++)
            Ts[k1 * 45 + tx * 4 + j] = make_ulonglong2(acc[0][i][j], acc[1][i][j]);
    }
    for (int i = tid; i < 68 * 68; i += 187) G4s[i] = g_G4[i];
    __syncthreads();

    #pragma unroll
    for (int m = 0; m < 2; m++)
        #pragma unroll
        for (int i = 0; i < 4; i++)
            #pragma unroll
            for (int j = 0; j < 4; j++) acc[m][i][j] = 0ULL;

    #pragma unroll 4
    for (int jj = 0; jj < 68; jj++) {
        u64 a[4];
        ulonglong2 b[4];
        #pragma unroll
        for (int i = 0; i < 4; i++) a[i] = G4s[(ty + 17 * i) * 68 + jj];
        #pragma unroll
        for (int j = 0; j < 4; j++) b[j] = Ts[jj * 45 + tx * 4 + j];
        #pragma unroll
        for (int i = 0; i < 4; i++)
            #pragma unroll
            for (int j = 0; j < 4; j++) {
                FMA2(acc[0][i][j], a[i], b[j].x);
                FMA2(acc[1][i][j], a[i], b[j].y);
            }
    }

    #pragma unroll
    for (int m = 0; m < 2; m++) {
        float* zb = g_z + (img0 + m) * NPIX;
        #pragma unroll
        for (int i = 0; i < 4; i++) {
            int m1 = ty + 17 * i;
            if (m1 > 66) continue;
            float2 v0 = upk(acc[m][i][0]), v1 = upk(acc[m][i][1]);
            float2 v2 = upk(acc[m][i][2]), v3 = upk(acc[m][i][3]);
            float4 zp = make_float4(v0.x + v0.y, v1.x + v1.y, v2.x + v2.y, v3.x + v3.y);
            *(float4*)&zb[m1 * NN + colBase + tx * 4] = zp;
            if (m1 >= 1 && m1 <= 65) {
                float4 zm = make_float4(v0.x - v0.y, v1.x - v1.y, v2.x - v2.y, v3.x - v3.y);
                *(float4*)&zb[(NN - m1) * NN + colBase + tx * 4] = zm;
            }
        }
    }
}

// ---------------- final: 2x2 quad per thread, shared m1/m2, exact GELU ----------------
__global__ void k_final(const float* __restrict__ x, const float* __restrict__ wt,
                        float* __restrict__ out) {
    int i = blockIdx.x * blockDim.x + threadIdx.x;   // 256*128*128
    int Q = i & 127, P = (i >> 7) & 127, img = i >> 14;
    int c = img & 63;
    __shared__ float sw[9];
    if (threadIdx.x < 9) sw[threadIdx.x] = wt[c * 9 + threadIdx.x];
    __syncthreads();
    int m1 = P + 2, m2 = Q + 2;
    const float* z = g_z + img * NPIX;
    float z00 = z[m1 * NN + m2],       z01 = z[m1 * NN + m2 + 1];
    float z10 = z[(m1 + 1) * NN + m2], z11 = z[(m1 + 1) * NN + m2 + 1];
    float xv = x[(img * 128 + ((m1 + 126) & 127)) * 128 + ((m2 + 126) & 127)];
    float v00 = xv + sw[4] * z00;
    float v01 = xv + sw[3] * z00 + sw[5] * z01;
    float v10 = xv + sw[1] * z00 + sw[7] * z10;
    float v11 = xv + sw[0] * z00 + sw[2] * z01 + sw[6] * z10 + sw[8] * z11;
    #define GELU(v) (0.5f * (v) * (1.0f + erff((v) * 0.70710678118654752f)))
    float* ob = out + img * 65536;
    *(float2*)&ob[(2 * P) * 256 + 2 * Q]     = make_float2(GELU(v00), GELU(v01));
    *(float2*)&ob[(2 * P + 1) * 256 + 2 * Q] = make_float2(GELU(v10), GELU(v11));
    #undef GELU
}

// ---------------- launch ----------------
extern "C" void kernel_launch(void* const* d_in, const int* in_sizes, int n_in,
                              void* d_out, int out_size) {
    const float* x    = (const float*)d_in[0];   // (4,64,128,128)
    const float* w    = (const float*)d_in[1];   // (1,64,3,3)
    const float* bias = (const float*)d_in[2];   // (1,64,1,1)
    float* out = (float*)d_out;                  // (4,64,256,256)

    static bool attr_done = false;
    if (!attr_done) {
        cudaFuncSetAttribute(kBC, cudaFuncAttributeMaxDynamicSharedMemorySize, 224128);
        cudaFuncSetAttribute(kDE, cudaFuncAttributeMaxDynamicSharedMemorySize, 98192);
        attr_done = true;
    }

    k_tables<<<(18488 + 255) / 256, 256>>>();
    k_buildWB<<<dim3((MM + 127) / 128, NCH), 128>>>(w);
    k_buildR<<<dim3(67, NCH), NN>>>(bias);

    kA<<<(NIMG * 68 * 34 + 255) / 256, 256>>>(x);

    kBC<<<NIMG / 2, dim3(17, 34), 224128>>>();
    kDE<<<dim3(3, NIMG / 2), dim3(11, 17), 98192>>>();

    k_final<<<(NIMG * 128 * 128) / 256, 256>>>(x, w, out);
}